// round 4
// baseline (speedup 1.0000x reference)
#include <cuda_runtime.h>
#include <math.h>

#define SEQ_L 64
#define NSTOCK 8000
#define NNEWS 1600
#define C_IN 128
#define HID 256
#define NEDGE 32000
#define G3 768            // 3*HID
#define CM 384            // C_IN + HID
#define NT 256            // threads per block
#define NBLK 296          // 2 blocks per SM on 148+ SMs (GB300 has 152)

// ---------------- scratch (static device memory; no allocs allowed) ----------
__device__ float g_acc_news[NNEWS * C_IN];
__device__ float g_cnt_news[NNEWS];
__device__ float g_center[NNEWS * C_IN];
__device__ float g_mc[NNEWS * HID];
__device__ float g_acc_stock[NSTOCK * CM];
__device__ float g_cnt_stock[NSTOCK];
__device__ float g_gi_n[NNEWS * G3];
__device__ float g_gh_n[NNEWS * G3];
__device__ float g_gi_s[NSTOCK * G3];
__device__ float g_gh_s[NSTOCK * G3];
__device__ unsigned g_bar_count = 0;

// ---------------- software grid barrier (monotonic, no reset race) -----------
// All writes before the barrier are made visible via __threadfence (gpu scope),
// which also emits CCTL.IVALL on sm_103a -> L1 invalidated -> plain loads after
// the barrier observe other blocks' writes.
__device__ __forceinline__ void grid_sync() {
    __syncthreads();
    __threadfence();
    if (threadIdx.x == 0) {
        unsigned G = gridDim.x;
        unsigned arrival = atomicAdd(&g_bar_count, 1u) + 1u;
        unsigned target = ((arrival + G - 1u) / G) * G;
        volatile unsigned* vc = &g_bar_count;
        while (*vc < target) { __nanosleep(64); }
    }
    __syncthreads();
    __threadfence();
}

// ---------------- 64x64 fp32 GEMM tile: C[m0:+64, n0:+64] += A @ W^T + bias --
// A[M,K], W[768,K] row-major; C row stride = 768. 256 threads, 4x4 microtile.
__device__ __forceinline__ void gemm_tile(
    const float* __restrict__ A, const float* __restrict__ W,
    const float* __restrict__ bias, float* __restrict__ Cc,
    int K, int m0, int n0, float (*As)[65], float (*Bs)[65]) {
    int tid = threadIdx.x;
    int tx = tid & 15;          // 16 col groups of 4
    int ty = tid >> 4;          // 16 row groups of 4
    int lk = tid & 15;
    int lm = tid >> 4;
    float acc[4][4] = {};
    for (int kt = 0; kt < K; kt += 16) {
#pragma unroll
        for (int i = 0; i < 4; i++) {
            As[lk][lm + i * 16] = A[(size_t)(m0 + lm + i * 16) * K + kt + lk];
            Bs[lk][lm + i * 16] = W[(size_t)(n0 + lm + i * 16) * K + kt + lk];
        }
        __syncthreads();
#pragma unroll
        for (int k = 0; k < 16; k++) {
            float a[4], b[4];
#pragma unroll
            for (int i = 0; i < 4; i++) a[i] = As[k][ty * 4 + i];
#pragma unroll
            for (int j = 0; j < 4; j++) b[j] = Bs[k][tx * 4 + j];
#pragma unroll
            for (int i = 0; i < 4; i++)
#pragma unroll
                for (int j = 0; j < 4; j++) acc[i][j] += a[i] * b[j];
        }
        __syncthreads();
    }
#pragma unroll
    for (int i = 0; i < 4; i++) {
        int m = m0 + ty * 4 + i;
#pragma unroll
        for (int j = 0; j < 4; j++) {
            int n = n0 + tx * 4 + j;
            Cc[(size_t)m * G3 + n] = acc[i][j] + bias[n];
        }
    }
}

// ---------------- GRU gate fusion --------------------------------------------
__device__ __forceinline__ void gate_apply(const float* __restrict__ gi,
                                           const float* __restrict__ gh,
                                           float* __restrict__ h, int M,
                                           int gtid, int nthr) {
    int total = M * HID;
    for (int idx = gtid; idx < total; idx += nthr) {
        int m = idx >> 8;          // HID == 256
        int j = idx & 255;
        const float* gim = gi + (size_t)m * G3;
        const float* ghm = gh + (size_t)m * G3;
        float r = 1.0f / (1.0f + __expf(-(gim[j] + ghm[j])));
        float z = 1.0f / (1.0f + __expf(-(gim[HID + j] + ghm[HID + j])));
        float n = tanhf(gim[2 * HID + j] + r * ghm[2 * HID + j]);
        h[idx] = (1.0f - z) * n + z * h[idx];
    }
}

// ---------------- the persistent mega-kernel ---------------------------------
__global__ __launch_bounds__(NT, 2)
void mega_kernel(const float* __restrict__ inputs, const int* __restrict__ ei,
                 const float* __restrict__ h_start, const float* __restrict__ hi_start,
                 const float* __restrict__ mc_start,
                 const float* __restrict__ Wih_c,  const float* __restrict__ Whh_c,
                 const float* __restrict__ bih_c,  const float* __restrict__ bhh_c,
                 const float* __restrict__ Wih_lh, const float* __restrict__ Whh_lh,
                 const float* __restrict__ bih_lh, const float* __restrict__ bhh_lh,
                 const float* __restrict__ Wih_li, const float* __restrict__ Whh_li,
                 const float* __restrict__ bih_li, const float* __restrict__ bhh_li,
                 float* __restrict__ m_out, float* __restrict__ h_out,
                 float* __restrict__ hi_out) {
    __shared__ float As[16][65];
    __shared__ float Bs[16][65];

    const int gtid = blockIdx.x * NT + threadIdx.x;
    const int nthr = gridDim.x * NT;
    const int gwarp = gtid >> 5;
    const int lane = threadIdx.x & 31;
    const int nwarp = nthr >> 5;

    // ---- init recurrent state ----
    for (int i = gtid; i < NSTOCK * HID; i += nthr) {
        h_out[i] = h_start[i & 255];
        hi_out[i] = hi_start[i & 255];
    }
    for (int i = gtid; i < NNEWS * HID; i += nthr) g_mc[i] = mc_start[i & 255];
    grid_sync();

    for (int t = 0; t < SEQ_L; t++) {
        const float* xt = inputs + (size_t)t * NSTOCK * C_IN;
        const int* news = ei + (size_t)t * 2 * NEDGE;
        const int* stck = news + NEDGE;

        // ---- P0: zero accumulators ----
        for (int i = gtid; i < NNEWS * C_IN; i += nthr) g_acc_news[i] = 0.0f;
        for (int i = gtid; i < NNEWS; i += nthr) g_cnt_news[i] = 0.0f;
        for (int i = gtid; i < NSTOCK * CM; i += nthr) g_acc_stock[i] = 0.0f;
        for (int i = gtid; i < NSTOCK; i += nthr) g_cnt_stock[i] = 0.0f;
        grid_sync();

        // ---- P1: scatter stocks -> news (sum x[stck] at news) ----
        for (int e = gwarp; e < NEDGE; e += nwarp) {
            int n = news[e];
            int s = stck[e];
            float4 v = ((const float4*)(xt + (size_t)s * C_IN))[lane];
            float* dst = g_acc_news + (size_t)n * C_IN + lane * 4;
            atomicAdd(dst + 0, v.x);
            atomicAdd(dst + 1, v.y);
            atomicAdd(dst + 2, v.z);
            atomicAdd(dst + 3, v.w);
            if (lane == 0) atomicAdd(&g_cnt_news[n], 1.0f);
        }
        grid_sync();

        // ---- P2: normalize -> center_m ----
        for (int i = gtid; i < NNEWS * C_IN; i += nthr) {
            float c = g_cnt_news[i >> 7];           // C_IN == 128
            g_center[i] = g_acc_news[i] / fmaxf(c, 1.0f);
        }
        grid_sync();

        // ---- P3: GEMMs gi_c, gh_c (news) + gi_li, gh_li (stocks) ----
        // tile counts: 25*12=300 (news), 125*12=1500 (stocks)
        for (int tile = blockIdx.x; tile < 3600; tile += gridDim.x) {
            const float *A, *W, *B; float* Cc; int K, idx;
            if (tile < 1500)      { A = xt;       W = Wih_li; B = bih_li; Cc = g_gi_s; K = C_IN; idx = tile; }
            else if (tile < 3000) { A = hi_out;   W = Whh_li; B = bhh_li; Cc = g_gh_s; K = HID;  idx = tile - 1500; }
            else if (tile < 3300) { A = g_center; W = Wih_c;  B = bih_c;  Cc = g_gi_n; K = C_IN; idx = tile - 3000; }
            else                  { A = g_mc;     W = Whh_c;  B = bhh_c;  Cc = g_gh_n; K = HID;  idx = tile - 3300; }
            int mt = idx / 12, nt = idx % 12;
            gemm_tile(A, W, B, Cc, K, mt * 64, nt * 64, As, Bs);
        }
        grid_sync();

        // ---- P4: gates: m_c update (news) + h_input update (stocks) ----
        gate_apply(g_gi_n, g_gh_n, g_mc, NNEWS, gtid, nthr);
        gate_apply(g_gi_s, g_gh_s, hi_out, NSTOCK, gtid, nthr);
        grid_sync();

        // ---- P5: scatter news -> stocks (sum [center_m, m_c][news] at stck) ----
        for (int e = gwarp; e < NEDGE; e += nwarp) {
            int n = news[e];
            int s = stck[e];
#pragma unroll
            for (int j = 0; j < 3; j++) {
                int c = (lane + j * 32) * 4;        // 0..380
                float4 v;
                if (c < C_IN) v = *(const float4*)(g_center + (size_t)n * C_IN + c);
                else          v = *(const float4*)(g_mc + (size_t)n * HID + (c - C_IN));
                float* dst = g_acc_stock + (size_t)s * CM + c;
                atomicAdd(dst + 0, v.x);
                atomicAdd(dst + 1, v.y);
                atomicAdd(dst + 2, v.z);
                atomicAdd(dst + 3, v.w);
            }
            if (lane == 0) atomicAdd(&g_cnt_stock[s], 1.0f);
        }
        grid_sync();

        // ---- P6: normalize -> m_out ----
        for (int i = gtid; i < NSTOCK * CM; i += nthr) {
            float c = g_cnt_stock[i / CM];
            m_out[i] = g_acc_stock[i] / fmaxf(c, 1.0f);
        }
        grid_sync();

        // ---- P7: GEMMs gi_lh (K=384), gh_lh (K=256) ----
        for (int tile = blockIdx.x; tile < 3000; tile += gridDim.x) {
            const float *A, *W, *B; float* Cc; int K, idx;
            if (tile < 1500) { A = m_out; W = Wih_lh; B = bih_lh; Cc = g_gi_s; K = CM;  idx = tile; }
            else             { A = h_out; W = Whh_lh; B = bhh_lh; Cc = g_gh_s; K = HID; idx = tile - 1500; }
            int mt = idx / 12, nt = idx % 12;
            gemm_tile(A, W, B, Cc, K, mt * 64, nt * 64, As, Bs);
        }
        grid_sync();

        // ---- P8: gate: h update ----
        gate_apply(g_gi_s, g_gh_s, h_out, NSTOCK, gtid, nthr);
        grid_sync();
    }
}

// ---------------- launch -----------------------------------------------------
extern "C" void kernel_launch(void* const* d_in, const int* in_sizes, int n_in,
                              void* d_out, int out_size) {
    const float* inputs   = (const float*)d_in[0];   // [64, 8000, 128]
    const int*   ei       = (const int*)d_in[1];     // [64, 2, 32000]
    const float* h_start  = (const float*)d_in[2];
    const float* hi_start = (const float*)d_in[3];
    const float* mc_start = (const float*)d_in[4];
    const float* Wih_c  = (const float*)d_in[5];
    const float* Whh_c  = (const float*)d_in[6];
    const float* bih_c  = (const float*)d_in[7];
    const float* bhh_c  = (const float*)d_in[8];
    const float* Wih_lh = (const float*)d_in[9];
    const float* Whh_lh = (const float*)d_in[10];
    const float* bih_lh = (const float*)d_in[11];
    const float* bhh_lh = (const float*)d_in[12];
    const float* Wih_li = (const float*)d_in[13];
    const float* Whh_li = (const float*)d_in[14];
    const float* bih_li = (const float*)d_in[15];
    const float* bhh_li = (const float*)d_in[16];

    float* out    = (float*)d_out;
    float* m_out  = out;                                // [8000, 384]
    float* h_out  = out + (size_t)NSTOCK * CM;          // [8000, 256]
    float* hi_out = h_out + (size_t)NSTOCK * HID;       // [8000, 256]

    unsigned* bar = nullptr;
    cudaGetSymbolAddress((void**)&bar, g_bar_count);
    cudaMemsetAsync(bar, 0, sizeof(unsigned));

    mega_kernel<<<NBLK, NT>>>(inputs, ei, h_start, hi_start, mc_start,
                              Wih_c, Whh_c, bih_c, bhh_c,
                              Wih_lh, Whh_lh, bih_lh, bhh_lh,
                              Wih_li, Whh_li, bih_li, bhh_li,
                              m_out, h_out, hi_out);
}

// round 5
// speedup vs baseline: 1.5857x; 1.5857x over previous
#include <cuda_runtime.h>
#include <math.h>

#define SEQ_L 64
#define NSTOCK 8000
#define NNEWS 1600
#define C_IN 128
#define HID 256
#define NEDGE 32000
#define G3 768            // 3*HID
#define CM 384            // C_IN + HID
#define NT 256            // threads per block
#define SPAD 132          // smem row stride (floats): 16B-aligned rows, 2-way store conflict

// ---------------- scratch (static device memory; no allocs allowed) ----------
__device__ float g_acc_news[NNEWS * C_IN];
__device__ float g_cnt_news[NNEWS];
__device__ float g_center[NNEWS * C_IN];
__device__ float g_mc[NNEWS * HID];
__device__ float g_acc_stock[NSTOCK * CM];
__device__ float g_cnt_stock[NSTOCK];
__device__ float g_gi_n[NNEWS * G3];
__device__ float g_gh_n[NNEWS * G3];
__device__ float g_gi_s[NSTOCK * G3];
__device__ float g_gh_s[NSTOCK * G3];
__device__ unsigned g_bar_count = 0;

// ---------------- software grid barrier (monotonic, no reset race) -----------
__device__ __forceinline__ void grid_sync() {
    __syncthreads();
    __threadfence();
    if (threadIdx.x == 0) {
        unsigned G = gridDim.x;
        unsigned arrival = atomicAdd(&g_bar_count, 1u) + 1u;
        unsigned target = ((arrival + G - 1u) / G) * G;
        volatile unsigned* vc = &g_bar_count;
        while (*vc < target) { __nanosleep(64); }
    }
    __syncthreads();
    __threadfence();
}

// ---------------- 128x128 fp32 GEMM tile: C[m0:+128, n0:+128] = A@W^T + bias -
// A[M,K] (rows clamped to Mlim on load), W[768,K] row-major, C row stride G3.
// 256 threads, 8x8 microtile, float4 smem loads -> 4 FMA per loaded float.
__device__ __forceinline__ void gemm_tile128(
    const float* __restrict__ A, const float* __restrict__ W,
    const float* __restrict__ bias, float* __restrict__ Cc,
    int K, int M, int m0, int n0,
    float (*As)[SPAD], float (*Bs)[SPAD]) {
    const int tid = threadIdx.x;
    const int lk = tid & 15;        // k within BK=16
    const int r  = tid >> 4;        // 0..15 row group for loads
    const int tx = tid & 15;        // col group (8 cols)
    const int ty = tid >> 4;        // row group (8 rows)
    const int tx8 = tx * 8, ty8 = ty * 8;
    const int Mlim = M - 1;

    float acc[8][8] = {};
    for (int kt = 0; kt < K; kt += 16) {
#pragma unroll
        for (int i = 0; i < 8; i++) {
            int mm = m0 + r + i * 16;
            if (mm > Mlim) mm = Mlim;
            As[lk][r + i * 16] = A[(size_t)mm * K + kt + lk];
            Bs[lk][r + i * 16] = W[(size_t)(n0 + r + i * 16) * K + kt + lk];
        }
        __syncthreads();
#pragma unroll
        for (int k = 0; k < 16; k++) {
            float4 a0 = *(const float4*)&As[k][ty8];
            float4 a1 = *(const float4*)&As[k][ty8 + 4];
            float4 b0 = *(const float4*)&Bs[k][tx8];
            float4 b1 = *(const float4*)&Bs[k][tx8 + 4];
            float a[8] = {a0.x, a0.y, a0.z, a0.w, a1.x, a1.y, a1.z, a1.w};
            float b[8] = {b0.x, b0.y, b0.z, b0.w, b1.x, b1.y, b1.z, b1.w};
#pragma unroll
            for (int i = 0; i < 8; i++)
#pragma unroll
                for (int j = 0; j < 8; j++) acc[i][j] += a[i] * b[j];
        }
        __syncthreads();
    }
    float4 bl = *(const float4*)&bias[n0 + tx8];
    float4 bh = *(const float4*)&bias[n0 + tx8 + 4];
#pragma unroll
    for (int i = 0; i < 8; i++) {
        int m = m0 + ty8 + i;
        if (m < M) {
            float4 v0 = make_float4(acc[i][0] + bl.x, acc[i][1] + bl.y,
                                    acc[i][2] + bl.z, acc[i][3] + bl.w);
            float4 v1 = make_float4(acc[i][4] + bh.x, acc[i][5] + bh.y,
                                    acc[i][6] + bh.z, acc[i][7] + bh.w);
            float* cp = Cc + (size_t)m * G3 + n0 + tx8;
            *(float4*)cp = v0;
            *(float4*)(cp + 4) = v1;
        }
    }
}

// ---------------- GRU gate fusion --------------------------------------------
__device__ __forceinline__ void gate_apply(const float* __restrict__ gi,
                                           const float* __restrict__ gh,
                                           float* __restrict__ h, int M,
                                           int gtid, int nthr) {
    int total = M * HID;
    for (int idx = gtid; idx < total; idx += nthr) {
        int m = idx >> 8;          // HID == 256
        int j = idx & 255;
        const float* gim = gi + (size_t)m * G3;
        const float* ghm = gh + (size_t)m * G3;
        float r = 1.0f / (1.0f + __expf(-(gim[j] + ghm[j])));
        float z = 1.0f / (1.0f + __expf(-(gim[HID + j] + ghm[HID + j])));
        float n = tanhf(gim[2 * HID + j] + r * ghm[2 * HID + j]);
        h[idx] = (1.0f - z) * n + z * h[idx];
    }
}

// tile counts (BM=BN=128): stocks 63 x 6, news 13 x 6
#define ST_T (63 * 6)      // 378
#define NW_T (13 * 6)      // 78
#define P3_TOT (ST_T * 2 + NW_T * 2)   // 912
#define P7_TOT (ST_T * 2)              // 756

// ---------------- the persistent mega-kernel ---------------------------------
__global__ __launch_bounds__(NT, 2)
void mega_kernel(const float* __restrict__ inputs, const int* __restrict__ ei,
                 const float* __restrict__ h_start, const float* __restrict__ hi_start,
                 const float* __restrict__ mc_start,
                 const float* __restrict__ Wih_c,  const float* __restrict__ Whh_c,
                 const float* __restrict__ bih_c,  const float* __restrict__ bhh_c,
                 const float* __restrict__ Wih_lh, const float* __restrict__ Whh_lh,
                 const float* __restrict__ bih_lh, const float* __restrict__ bhh_lh,
                 const float* __restrict__ Wih_li, const float* __restrict__ Whh_li,
                 const float* __restrict__ bih_li, const float* __restrict__ bhh_li,
                 float* __restrict__ m_out, float* __restrict__ h_out,
                 float* __restrict__ hi_out) {
    __shared__ float As[16][SPAD];
    __shared__ float Bs[16][SPAD];

    const int gtid = blockIdx.x * NT + threadIdx.x;
    const int nthr = gridDim.x * NT;
    const int gwarp = gtid >> 5;
    const int lane = threadIdx.x & 31;
    const int nwarp = nthr >> 5;

    // ---- init recurrent state ----
    for (int i = gtid; i < NSTOCK * HID; i += nthr) {
        h_out[i] = h_start[i & 255];
        hi_out[i] = hi_start[i & 255];
    }
    for (int i = gtid; i < NNEWS * HID; i += nthr) g_mc[i] = mc_start[i & 255];
    grid_sync();

    for (int t = 0; t < SEQ_L; t++) {
        const float* xt = inputs + (size_t)t * NSTOCK * C_IN;
        const int* news = ei + (size_t)t * 2 * NEDGE;
        const int* stck = news + NEDGE;

        // ---- P0: zero accumulators ----
        for (int i = gtid; i < NNEWS * C_IN; i += nthr) g_acc_news[i] = 0.0f;
        for (int i = gtid; i < NNEWS; i += nthr) g_cnt_news[i] = 0.0f;
        for (int i = gtid; i < NSTOCK * CM; i += nthr) g_acc_stock[i] = 0.0f;
        for (int i = gtid; i < NSTOCK; i += nthr) g_cnt_stock[i] = 0.0f;
        grid_sync();

        // ---- P1: scatter stocks -> news (sum x[stck] at news) ----
        for (int e = gwarp; e < NEDGE; e += nwarp) {
            int n = news[e];
            int s = stck[e];
            float4 v = ((const float4*)(xt + (size_t)s * C_IN))[lane];
            float* dst = g_acc_news + (size_t)n * C_IN + lane * 4;
            atomicAdd(dst + 0, v.x);
            atomicAdd(dst + 1, v.y);
            atomicAdd(dst + 2, v.z);
            atomicAdd(dst + 3, v.w);
            if (lane == 0) atomicAdd(&g_cnt_news[n], 1.0f);
        }
        grid_sync();

        // ---- P2: normalize -> center_m ----
        for (int i = gtid; i < NNEWS * C_IN; i += nthr) {
            float c = g_cnt_news[i >> 7];           // C_IN == 128
            g_center[i] = g_acc_news[i] / fmaxf(c, 1.0f);
        }
        grid_sync();

        // ---- P3: GEMMs gi_li, gh_li (stocks) + gi_c, gh_c (news) ----
        for (int tile = blockIdx.x; tile < P3_TOT; tile += gridDim.x) {
            const float *A, *W, *B; float* Cc; int K, M, idx;
            if (tile < ST_T)            { A = xt;       W = Wih_li; B = bih_li; Cc = g_gi_s; K = C_IN; M = NSTOCK; idx = tile; }
            else if (tile < 2 * ST_T)   { A = hi_out;   W = Whh_li; B = bhh_li; Cc = g_gh_s; K = HID;  M = NSTOCK; idx = tile - ST_T; }
            else if (tile < 2 * ST_T + NW_T) { A = g_center; W = Wih_c; B = bih_c; Cc = g_gi_n; K = C_IN; M = NNEWS; idx = tile - 2 * ST_T; }
            else                        { A = g_mc;     W = Whh_c;  B = bhh_c;  Cc = g_gh_n; K = HID;  M = NNEWS;  idx = tile - 2 * ST_T - NW_T; }
            int mt = idx / 6, nt = idx % 6;
            gemm_tile128(A, W, B, Cc, K, M, mt * 128, nt * 128, As, Bs);
        }
        grid_sync();

        // ---- P4: gates: m_c update (news) + h_input update (stocks) ----
        gate_apply(g_gi_n, g_gh_n, g_mc, NNEWS, gtid, nthr);
        gate_apply(g_gi_s, g_gh_s, hi_out, NSTOCK, gtid, nthr);
        grid_sync();

        // ---- P5: scatter news -> stocks (sum [center_m, m_c][news] at stck) ----
        for (int e = gwarp; e < NEDGE; e += nwarp) {
            int n = news[e];
            int s = stck[e];
#pragma unroll
            for (int j = 0; j < 3; j++) {
                int c = (lane + j * 32) * 4;        // 0..380
                float4 v;
                if (c < C_IN) v = *(const float4*)(g_center + (size_t)n * C_IN + c);
                else          v = *(const float4*)(g_mc + (size_t)n * HID + (c - C_IN));
                float* dst = g_acc_stock + (size_t)s * CM + c;
                atomicAdd(dst + 0, v.x);
                atomicAdd(dst + 1, v.y);
                atomicAdd(dst + 2, v.z);
                atomicAdd(dst + 3, v.w);
            }
            if (lane == 0) atomicAdd(&g_cnt_stock[s], 1.0f);
        }
        grid_sync();

        // ---- P6: normalize -> m_out ----
        for (int i = gtid; i < NSTOCK * CM; i += nthr) {
            float c = g_cnt_stock[i / CM];
            m_out[i] = g_acc_stock[i] / fmaxf(c, 1.0f);
        }
        grid_sync();

        // ---- P7: GEMMs gi_lh (K=384), gh_lh (K=256) ----
        for (int tile = blockIdx.x; tile < P7_TOT; tile += gridDim.x) {
            const float *A, *W, *B; float* Cc; int K, idx;
            if (tile < ST_T) { A = m_out; W = Wih_lh; B = bih_lh; Cc = g_gi_s; K = CM;  idx = tile; }
            else             { A = h_out; W = Whh_lh; B = bhh_lh; Cc = g_gh_s; K = HID; idx = tile - ST_T; }
            int mt = idx / 6, nt = idx % 6;
            gemm_tile128(A, W, B, Cc, K, NSTOCK, mt * 128, nt * 128, As, Bs);
        }
        grid_sync();

        // ---- P8: gate: h update ----
        gate_apply(g_gi_s, g_gh_s, h_out, NSTOCK, gtid, nthr);
        grid_sync();
    }
}

// ---------------- launch -----------------------------------------------------
extern "C" void kernel_launch(void* const* d_in, const int* in_sizes, int n_in,
                              void* d_out, int out_size) {
    const float* inputs   = (const float*)d_in[0];   // [64, 8000, 128]
    const int*   ei       = (const int*)d_in[1];     // [64, 2, 32000]
    const float* h_start  = (const float*)d_in[2];
    const float* hi_start = (const float*)d_in[3];
    const float* mc_start = (const float*)d_in[4];
    const float* Wih_c  = (const float*)d_in[5];
    const float* Whh_c  = (const float*)d_in[6];
    const float* bih_c  = (const float*)d_in[7];
    const float* bhh_c  = (const float*)d_in[8];
    const float* Wih_lh = (const float*)d_in[9];
    const float* Whh_lh = (const float*)d_in[10];
    const float* bih_lh = (const float*)d_in[11];
    const float* bhh_lh = (const float*)d_in[12];
    const float* Wih_li = (const float*)d_in[13];
    const float* Whh_li = (const float*)d_in[14];
    const float* bih_li = (const float*)d_in[15];
    const float* bhh_li = (const float*)d_in[16];

    float* out    = (float*)d_out;
    float* m_out  = out;                                // [8000, 384]
    float* h_out  = out + (size_t)NSTOCK * CM;          // [8000, 256]
    float* hi_out = h_out + (size_t)NSTOCK * HID;       // [8000, 256]

    // persistent grid sized to exactly fill the device (barrier-safe)
    int dev = 0, nsm = 0, occ = 0;
    cudaGetDevice(&dev);
    cudaDeviceGetAttribute(&nsm, cudaDevAttrMultiProcessorCount, dev);
    cudaOccupancyMaxActiveBlocksPerMultiprocessor(&occ, mega_kernel, NT, 0);
    int nblk = nsm * (occ > 0 ? occ : 1);

    unsigned* bar = nullptr;
    cudaGetSymbolAddress((void**)&bar, g_bar_count);
    cudaMemsetAsync(bar, 0, sizeof(unsigned));

    mega_kernel<<<nblk, NT>>>(inputs, ei, h_start, hi_start, mc_start,
                              Wih_c, Whh_c, bih_c, bhh_c,
                              Wih_lh, Whh_lh, bih_lh, bhh_lh,
                              Wih_li, Whh_li, bih_li, bhh_li,
                              m_out, h_out, hi_out);
}

// round 7
// speedup vs baseline: 2.4352x; 1.5357x over previous
#include <cuda_runtime.h>
#include <cuda_bf16.h>
#include <math.h>
#include <stdint.h>

#define SEQ_L 64
#define NSTOCK 8000
#define NNEWS 1600
#define C_IN 128
#define HID 256
#define NEDGE 32000
#define G3 768            // 3*HID
#define CM 384            // C_IN + HID
#define NT 256            // threads per block
#define BKP 40            // padded smem K stride (elems): 80B rows, conflict-free frags

// ---- weight bf16 hi/lo offsets (elements) ------------------------------------
#define OW_IH_LI 0
#define OW_HH_LI 98304
#define OW_IH_C  294912
#define OW_HH_C  393216
#define OW_IH_LH 589824
#define OW_HH_LH 884736
#define W_TOTAL  1081344

// ---------------- scratch (static device memory; no allocs allowed) ----------
__device__ float g_acc_news[NNEWS * C_IN];
__device__ float g_cnt_news[NNEWS];
__device__ float g_center[NNEWS * C_IN];
__device__ float g_mc[NNEWS * HID];
__device__ float g_acc_stock[NSTOCK * CM];
__device__ float g_cnt_stock[NSTOCK];
__device__ float g_gi_n[NNEWS * G3];
__device__ float g_gh_n[NNEWS * G3];
__device__ float g_gi_s[NSTOCK * G3];
__device__ float g_gh_s[NSTOCK * G3];
__device__ __nv_bfloat16 g_Whi[W_TOTAL];
__device__ __nv_bfloat16 g_Wlo[W_TOTAL];
__device__ unsigned g_bar_count = 0;

// ---------------- software grid barrier (monotonic) --------------------------
__device__ __forceinline__ void grid_sync() {
    __syncthreads();
    __threadfence();
    if (threadIdx.x == 0) {
        unsigned G = gridDim.x;
        unsigned arrival = atomicAdd(&g_bar_count, 1u) + 1u;
        unsigned target = ((arrival + G - 1u) / G) * G;
        volatile unsigned* vc = &g_bar_count;
        while (*vc < target) { __nanosleep(64); }
    }
    __syncthreads();
    __threadfence();
}

// ---------------- bf16 HMMA m16n8k16 -----------------------------------------
__device__ __forceinline__ void mma_bf16(float* c, const uint32_t* a, const uint32_t* b) {
    asm volatile("mma.sync.aligned.m16n8k16.row.col.f32.bf16.bf16.f32 "
                 "{%0,%1,%2,%3}, {%4,%5,%6,%7}, {%8,%9}, {%0,%1,%2,%3};"
                 : "+f"(c[0]), "+f"(c[1]), "+f"(c[2]), "+f"(c[3])
                 : "r"(a[0]), "r"(a[1]), "r"(a[2]), "r"(a[3]), "r"(b[0]), "r"(b[1]));
}

// ---------------- MMA GEMM tile: C[m0:+128, n0:+128] = A@W^T + bias ----------
// A fp32 [M,K] (rows clamped), W preconverted bf16 hi/lo [768,K] row-major.
// 3-term bf16 split: Ah*Wh + Ah*Wl + Al*Wh, fp32 accumulate in registers.
__device__ void gemm_tile_mma(const float* __restrict__ A,
                              const __nv_bfloat16* __restrict__ Wh,
                              const __nv_bfloat16* __restrict__ Wl,
                              const float* __restrict__ bias, float* __restrict__ Cc,
                              int K, int M, int m0, int n0,
                              uint16_t* sAh, uint16_t* sAl,
                              uint16_t* sBh, uint16_t* sBl) {
    const int tid = threadIdx.x;
    const int w = tid >> 5, lane = tid & 31;
    const int g = lane >> 2, t4 = lane & 3;
    const int mbase = (w >> 2) * 64;     // warp m offset within tile
    const int nbase = (w & 3) * 32;      // warp n offset within tile

    float acc[4][4][4];
#pragma unroll
    for (int i = 0; i < 4; i++)
#pragma unroll
        for (int j = 0; j < 4; j++)
#pragma unroll
            for (int q = 0; q < 4; q++) acc[i][j][q] = 0.0f;

    for (int kt = 0; kt < K; kt += 32) {
        // ---- stage A (fp32 -> bf16 hi/lo) and B (bf16 copy) chunks ----------
        for (int it = tid; it < 128 * 8; it += NT) {
            int row = it >> 3;
            int c4 = (it & 7) << 2;                  // 0..28
            int mm = m0 + row; if (mm >= M) mm = M - 1;
            float4 v = *(const float4*)(A + (size_t)mm * K + kt + c4);
            __nv_bfloat16 h0 = __float2bfloat16(v.x), h1 = __float2bfloat16(v.y);
            __nv_bfloat16 h2 = __float2bfloat16(v.z), h3 = __float2bfloat16(v.w);
            __nv_bfloat16 l0 = __float2bfloat16(v.x - __bfloat162float(h0));
            __nv_bfloat16 l1 = __float2bfloat16(v.y - __bfloat162float(h1));
            __nv_bfloat16 l2 = __float2bfloat16(v.z - __bfloat162float(h2));
            __nv_bfloat16 l3 = __float2bfloat16(v.w - __bfloat162float(h3));
            uint32_t ph0 = (uint32_t)__bfloat16_as_ushort(h0) | ((uint32_t)__bfloat16_as_ushort(h1) << 16);
            uint32_t ph1 = (uint32_t)__bfloat16_as_ushort(h2) | ((uint32_t)__bfloat16_as_ushort(h3) << 16);
            uint32_t pl0 = (uint32_t)__bfloat16_as_ushort(l0) | ((uint32_t)__bfloat16_as_ushort(l1) << 16);
            uint32_t pl1 = (uint32_t)__bfloat16_as_ushort(l2) | ((uint32_t)__bfloat16_as_ushort(l3) << 16);
            int o = row * BKP + c4;
            *(uint2*)(sAh + o) = make_uint2(ph0, ph1);
            *(uint2*)(sAl + o) = make_uint2(pl0, pl1);
            size_t go = (size_t)(n0 + row) * K + kt + c4;
            *(uint2*)(sBh + o) = *(const uint2*)(Wh + go);
            *(uint2*)(sBl + o) = *(const uint2*)(Wl + go);
        }
        __syncthreads();
        // ---- compute: two k16 steps ----------------------------------------
#pragma unroll
        for (int kk = 0; kk < 32; kk += 16) {
            uint32_t ah[4][4], al[4][4];
#pragma unroll
            for (int mf = 0; mf < 4; mf++) {
                int base = (mbase + mf * 16 + g) * BKP + kk + 2 * t4;
                ah[mf][0] = *(const uint32_t*)(sAh + base);
                ah[mf][1] = *(const uint32_t*)(sAh + base + 8 * BKP);
                ah[mf][2] = *(const uint32_t*)(sAh + base + 8);
                ah[mf][3] = *(const uint32_t*)(sAh + base + 8 * BKP + 8);
                al[mf][0] = *(const uint32_t*)(sAl + base);
                al[mf][1] = *(const uint32_t*)(sAl + base + 8 * BKP);
                al[mf][2] = *(const uint32_t*)(sAl + base + 8);
                al[mf][3] = *(const uint32_t*)(sAl + base + 8 * BKP + 8);
            }
#pragma unroll
            for (int nf = 0; nf < 4; nf++) {
                int bb = (nbase + nf * 8 + g) * BKP + kk + 2 * t4;
                uint32_t bh[2], bl[2];
                bh[0] = *(const uint32_t*)(sBh + bb);
                bh[1] = *(const uint32_t*)(sBh + bb + 8);
                bl[0] = *(const uint32_t*)(sBl + bb);
                bl[1] = *(const uint32_t*)(sBl + bb + 8);
#pragma unroll
                for (int mf = 0; mf < 4; mf++) {
                    mma_bf16(acc[mf][nf], ah[mf], bh);
                    mma_bf16(acc[mf][nf], ah[mf], bl);
                    mma_bf16(acc[mf][nf], al[mf], bh);
                }
            }
        }
        __syncthreads();
    }
    // ---- epilogue: bias + store --------------------------------------------
#pragma unroll
    for (int mf = 0; mf < 4; mf++) {
#pragma unroll
        for (int nf = 0; nf < 4; nf++) {
            int m = m0 + mbase + mf * 16 + g;
            int n = n0 + nbase + nf * 8 + 2 * t4;
            float b0 = bias[n], b1 = bias[n + 1];
            if (m < M) {
                float2 v = make_float2(acc[mf][nf][0] + b0, acc[mf][nf][1] + b1);
                *(float2*)(Cc + (size_t)m * G3 + n) = v;
            }
            if (m + 8 < M) {
                float2 v = make_float2(acc[mf][nf][2] + b0, acc[mf][nf][3] + b1);
                *(float2*)(Cc + (size_t)(m + 8) * G3 + n) = v;
            }
        }
    }
    __syncthreads();
}

// ---------------- GRU gate fusion --------------------------------------------
__device__ __forceinline__ void gate_apply(const float* __restrict__ gi,
                                           const float* __restrict__ gh,
                                           float* __restrict__ h, int M,
                                           int gtid, int nthr) {
    int total = M * HID;
    for (int idx = gtid; idx < total; idx += nthr) {
        int m = idx >> 8;
        int j = idx & 255;
        const float* gim = gi + (size_t)m * G3;
        const float* ghm = gh + (size_t)m * G3;
        float r = 1.0f / (1.0f + __expf(-(gim[j] + ghm[j])));
        float z = 1.0f / (1.0f + __expf(-(gim[HID + j] + ghm[HID + j])));
        float n = tanhf(gim[2 * HID + j] + r * ghm[2 * HID + j]);
        h[idx] = (1.0f - z) * n + z * h[idx];
    }
}

__device__ __forceinline__ void convW(const float* __restrict__ W, int off, int n,
                                      int gtid, int nthr) {
    for (int i = gtid; i < n; i += nthr) {
        float w = W[i];
        __nv_bfloat16 h = __float2bfloat16(w);
        g_Whi[off + i] = h;
        g_Wlo[off + i] = __float2bfloat16(w - __bfloat162float(h));
    }
}

// tile counts (BM=BN=128): stocks 63 x 6, news 13 x 6
#define ST_T (63 * 6)      // 378
#define NW_T (13 * 6)      // 78
#define P3_TOT (ST_T * 2 + NW_T * 2)   // 912
#define P7_TOT (ST_T * 2)              // 756

// ---------------- the persistent mega-kernel ---------------------------------
__global__ __launch_bounds__(NT, 2)
void mega_kernel(const float* __restrict__ inputs, const int* __restrict__ ei,
                 const float* __restrict__ h_start, const float* __restrict__ hi_start,
                 const float* __restrict__ mc_start,
                 const float* __restrict__ Wih_c,  const float* __restrict__ Whh_c,
                 const float* __restrict__ bih_c,  const float* __restrict__ bhh_c,
                 const float* __restrict__ Wih_lh, const float* __restrict__ Whh_lh,
                 const float* __restrict__ bih_lh, const float* __restrict__ bhh_lh,
                 const float* __restrict__ Wih_li, const float* __restrict__ Whh_li,
                 const float* __restrict__ bih_li, const float* __restrict__ bhh_li,
                 float* __restrict__ m_out, float* __restrict__ h_out,
                 float* __restrict__ hi_out) {
    __shared__ __align__(16) uint16_t sAh[128 * BKP];
    __shared__ __align__(16) uint16_t sAl[128 * BKP];
    __shared__ __align__(16) uint16_t sBh[128 * BKP];
    __shared__ __align__(16) uint16_t sBl[128 * BKP];

    const int gtid = blockIdx.x * NT + threadIdx.x;
    const int nthr = gridDim.x * NT;
    const int gwarp = gtid >> 5;
    const int lane = threadIdx.x & 31;
    const int nwarp = nthr >> 5;

    // ---- init recurrent state + preconvert weights to bf16 hi/lo ----
    for (int i = gtid; i < NSTOCK * HID; i += nthr) {
        h_out[i] = h_start[i & 255];
        hi_out[i] = hi_start[i & 255];
    }
    for (int i = gtid; i < NNEWS * HID; i += nthr) g_mc[i] = mc_start[i & 255];
    convW(Wih_li, OW_IH_LI, G3 * C_IN, gtid, nthr);
    convW(Whh_li, OW_HH_LI, G3 * HID,  gtid, nthr);
    convW(Wih_c,  OW_IH_C,  G3 * C_IN, gtid, nthr);
    convW(Whh_c,  OW_HH_C,  G3 * HID,  gtid, nthr);
    convW(Wih_lh, OW_IH_LH, G3 * CM,   gtid, nthr);
    convW(Whh_lh, OW_HH_LH, G3 * HID,  gtid, nthr);
    grid_sync();

    for (int t = 0; t < SEQ_L; t++) {
        const float* xt = inputs + (size_t)t * NSTOCK * C_IN;
        const int* news = ei + (size_t)t * 2 * NEDGE;
        const int* stck = news + NEDGE;

        // ---- P0: zero accumulators ----
        for (int i = gtid; i < NNEWS * C_IN; i += nthr) g_acc_news[i] = 0.0f;
        for (int i = gtid; i < NNEWS; i += nthr) g_cnt_news[i] = 0.0f;
        for (int i = gtid; i < NSTOCK * CM; i += nthr) g_acc_stock[i] = 0.0f;
        for (int i = gtid; i < NSTOCK; i += nthr) g_cnt_stock[i] = 0.0f;
        grid_sync();

        // ---- P1: scatter stocks -> news ----
        for (int e = gwarp; e < NEDGE; e += nwarp) {
            int n = news[e];
            int s = stck[e];
            float4 v = ((const float4*)(xt + (size_t)s * C_IN))[lane];
            float* dst = g_acc_news + (size_t)n * C_IN + lane * 4;
            atomicAdd(dst + 0, v.x);
            atomicAdd(dst + 1, v.y);
            atomicAdd(dst + 2, v.z);
            atomicAdd(dst + 3, v.w);
            if (lane == 0) atomicAdd(&g_cnt_news[n], 1.0f);
        }
        grid_sync();

        // ---- P2: normalize -> center_m ----
        for (int i = gtid; i < NNEWS * C_IN; i += nthr) {
            float c = g_cnt_news[i >> 7];
            g_center[i] = g_acc_news[i] / fmaxf(c, 1.0f);
        }
        grid_sync();

        // ---- P3: GEMMs gi_li, gh_li (stocks) + gi_c, gh_c (news) ----
        for (int tile = blockIdx.x; tile < P3_TOT; tile += gridDim.x) {
            const float* A; const __nv_bfloat16 *Wh, *Wl;
            const float* B; float* Cc; int K, M, idx;
            if (tile < ST_T)                { A = xt;       Wh = g_Whi + OW_IH_LI; Wl = g_Wlo + OW_IH_LI; B = bih_li; Cc = g_gi_s; K = C_IN; M = NSTOCK; idx = tile; }
            else if (tile < 2 * ST_T)       { A = hi_out;   Wh = g_Whi + OW_HH_LI; Wl = g_Wlo + OW_HH_LI; B = bhh_li; Cc = g_gh_s; K = HID;  M = NSTOCK; idx = tile - ST_T; }
            else if (tile < 2 * ST_T + NW_T){ A = g_center; Wh = g_Whi + OW_IH_C;  Wl = g_Wlo + OW_IH_C;  B = bih_c;  Cc = g_gi_n; K = C_IN; M = NNEWS;  idx = tile - 2 * ST_T; }
            else                            { A = g_mc;     Wh = g_Whi + OW_HH_C;  Wl = g_Wlo + OW_HH_C;  B = bhh_c;  Cc = g_gh_n; K = HID;  M = NNEWS;  idx = tile - 2 * ST_T - NW_T; }
            int mt = idx / 6, nt = idx % 6;
            gemm_tile_mma(A, Wh, Wl, B, Cc, K, M, mt * 128, nt * 128, sAh, sAl, sBh, sBl);
        }
        grid_sync();

        // ---- P4: gates: m_c update (news) + h_input update (stocks) ----
        gate_apply(g_gi_n, g_gh_n, g_mc, NNEWS, gtid, nthr);
        gate_apply(g_gi_s, g_gh_s, hi_out, NSTOCK, gtid, nthr);
        grid_sync();

        // ---- P5: scatter news -> stocks ----
        for (int e = gwarp; e < NEDGE; e += nwarp) {
            int n = news[e];
            int s = stck[e];
#pragma unroll
            for (int j = 0; j < 3; j++) {
                int c = (lane + j * 32) * 4;
                float4 v;
                if (c < C_IN) v = *(const float4*)(g_center + (size_t)n * C_IN + c);
                else          v = *(const float4*)(g_mc + (size_t)n * HID + (c - C_IN));
                float* dst = g_acc_stock + (size_t)s * CM + c;
                atomicAdd(dst + 0, v.x);
                atomicAdd(dst + 1, v.y);
                atomicAdd(dst + 2, v.z);
                atomicAdd(dst + 3, v.w);
            }
            if (lane == 0) atomicAdd(&g_cnt_stock[s], 1.0f);
        }
        grid_sync();

        // ---- P6: normalize -> m_out ----
        for (int i = gtid; i < NSTOCK * CM; i += nthr) {
            float c = g_cnt_stock[i / CM];
            m_out[i] = g_acc_stock[i] / fmaxf(c, 1.0f);
        }
        grid_sync();

        // ---- P7: GEMMs gi_lh (K=384), gh_lh (K=256) ----
        for (int tile = blockIdx.x; tile < P7_TOT; tile += gridDim.x) {
            const float* A; const __nv_bfloat16 *Wh, *Wl;
            const float* B; float* Cc; int K, idx;
            if (tile < ST_T) { A = m_out; Wh = g_Whi + OW_IH_LH; Wl = g_Wlo + OW_IH_LH; B = bih_lh; Cc = g_gi_s; K = CM;  idx = tile; }
            else             { A = h_out; Wh = g_Whi + OW_HH_LH; Wl = g_Wlo + OW_HH_LH; B = bhh_lh; Cc = g_gh_s; K = HID; idx = tile - ST_T; }
            int mt = idx / 6, nt = idx % 6;
            gemm_tile_mma(A, Wh, Wl, B, Cc, K, NSTOCK, mt * 128, nt * 128, sAh, sAl, sBh, sBl);
        }
        grid_sync();

        // ---- P8: gate: h update ----
        gate_apply(g_gi_s, g_gh_s, h_out, NSTOCK, gtid, nthr);
        grid_sync();
    }
}

// ---------------- launch -----------------------------------------------------
extern "C" void kernel_launch(void* const* d_in, const int* in_sizes, int n_in,
                              void* d_out, int out_size) {
    const float* inputs   = (const float*)d_in[0];   // [64, 8000, 128]
    const int*   ei       = (const int*)d_in[1];     // [64, 2, 32000]
    const float* h_start  = (const float*)d_in[2];
    const float* hi_start = (const float*)d_in[3];
    const float* mc_start = (const float*)d_in[4];
    const float* Wih_c  = (const float*)d_in[5];
    const float* Whh_c  = (const float*)d_in[6];
    const float* bih_c  = (const float*)d_in[7];
    const float* bhh_c  = (const float*)d_in[8];
    const float* Wih_lh = (const float*)d_in[9];
    const float* Whh_lh = (const float*)d_in[10];
    const float* bih_lh = (const float*)d_in[11];
    const float* bhh_lh = (const float*)d_in[12];
    const float* Wih_li = (const float*)d_in[13];
    const float* Whh_li = (const float*)d_in[14];
    const float* bih_li = (const float*)d_in[15];
    const float* bhh_li = (const float*)d_in[16];

    float* out    = (float*)d_out;
    float* m_out  = out;                                // [8000, 384]
    float* h_out  = out + (size_t)NSTOCK * CM;          // [8000, 256]
    float* hi_out = h_out + (size_t)NSTOCK * HID;       // [8000, 256]

    int dev = 0, nsm = 0, occ = 0;
    cudaGetDevice(&dev);
    cudaDeviceGetAttribute(&nsm, cudaDevAttrMultiProcessorCount, dev);
    cudaOccupancyMaxActiveBlocksPerMultiprocessor(&occ, mega_kernel, NT, 0);
    if (occ < 1) occ = 1;
    int nblk = nsm * occ;

    unsigned* bar = nullptr;
    cudaGetSymbolAddress((void**)&bar, g_bar_count);
    cudaMemsetAsync(bar, 0, sizeof(unsigned));

    mega_kernel<<<nblk, NT>>>(inputs, ei, h_start, hi_start, mc_start,
                              Wih_c, Whh_c, bih_c, bhh_c,
                              Wih_lh, Whh_lh, bih_lh, bhh_lh,
                              Wih_li, Whh_li, bih_li, bhh_li,
                              m_out, h_out, hi_out);
}

// round 9
// speedup vs baseline: 2.4444x; 1.0038x over previous
#include <cuda_runtime.h>
#include <cuda_bf16.h>
#include <cuda_fp16.h>
#include <math.h>
#include <stdint.h>

#define SEQ_L 64
#define NSTOCK 8000
#define NNEWS 1600
#define C_IN 128
#define HID 256
#define NEDGE 32000
#define G3 768
#define CM 384
#define NT 256
#define BKP 72            // smem row stride (bf16 elems): 144B, 16B-aligned
#define NSTE 512000       // NSTOCK*SEQ_L
#define NNE  102400       // NNEWS*SEQ_L
#define SMEM_BYTES (4 * 128 * BKP * 2)   // 73728

// ---- weight bf16 hi/lo offsets (elements) -----------------------------------
#define OW_IH_LI 0
#define OW_HH_LI 98304
#define OW_IH_C  294912
#define OW_HH_C  393216
#define OW_IH_LH 589824
#define OW_HH_LH 884736
#define W_TOTAL  1081344

// ---------------- static device scratch (total ~2.2GB, linker-safe) ----------
__device__ float g_acc_news_all[(size_t)NNE * C_IN];    // 52MB; normalized in place
__device__ float g_accmc_all[(size_t)NSTE * C_IN];      // 262MB; normalized in place
__device__ __half g_gi_li_all[(size_t)NSTE * G3];       // 786MB
__device__ __half g_gi_c_all[(size_t)NNE * G3];         // 157MB
__device__ __half g_gi_lh1_all[(size_t)NSTE * G3];      // 786MB
__device__ float g_inv_news_all[NNE];
__device__ float g_inv_stock_all[NSTE];
// per-step state
__device__ float g_mc[NNEWS * HID];
__device__ __nv_bfloat16 g_mc_hi[NNEWS * HID];
__device__ __nv_bfloat16 g_mc_lo[NNEWS * HID];
__device__ __nv_bfloat16 g_h_hi[NSTOCK * HID];
__device__ __nv_bfloat16 g_h_lo[NSTOCK * HID];
__device__ __nv_bfloat16 g_p_hi[NSTOCK * HID];
__device__ __nv_bfloat16 g_p_lo[NSTOCK * HID];
__device__ float g_accmc[NSTOCK * HID];
__device__ __nv_bfloat16 g_amc_hi[NSTOCK * HID];
__device__ __nv_bfloat16 g_amc_lo[NSTOCK * HID];
__device__ float g_gh_li[NSTOCK * G3];
__device__ float g_gh_lh[NSTOCK * G3];
__device__ float g_gh_n[NNEWS * G3];
__device__ float g_gis[NSTOCK * G3];
__device__ __nv_bfloat16 g_Whi[W_TOTAL];
__device__ __nv_bfloat16 g_Wlo[W_TOTAL];
__device__ unsigned g_bar_count = 0;

// ---------------- software grid barrier (monotonic) --------------------------
__device__ __forceinline__ void grid_sync() {
    __syncthreads();
    __threadfence();
    if (threadIdx.x == 0) {
        unsigned G = gridDim.x;
        unsigned arrival = atomicAdd(&g_bar_count, 1u) + 1u;
        unsigned target = ((arrival + G - 1u) / G) * G;
        volatile unsigned* vc = &g_bar_count;
        while (*vc < target) { __nanosleep(64); }
    }
    __syncthreads();
    __threadfence();
}

__device__ __forceinline__ void bsplit(float v, __nv_bfloat16* hp, __nv_bfloat16* lp) {
    __nv_bfloat16 h = __float2bfloat16(v);
    *hp = h;
    *lp = __float2bfloat16(v - __bfloat162float(h));
}

__device__ __forceinline__ void mma_bf16(float* c, const uint32_t* a, const uint32_t* b) {
    asm volatile("mma.sync.aligned.m16n8k16.row.col.f32.bf16.bf16.f32 "
                 "{%0,%1,%2,%3}, {%4,%5,%6,%7}, {%8,%9}, {%0,%1,%2,%3};"
                 : "+f"(c[0]), "+f"(c[1]), "+f"(c[2]), "+f"(c[3])
                 : "r"(a[0]), "r"(a[1]), "r"(a[2]), "r"(a[3]), "r"(b[0]), "r"(b[1]));
}

// ---------------- shared compute core (operands staged in smem) --------------
struct Acc { float v[4][4][4]; };

__device__ __forceinline__ void mma_chunk(uint16_t* sAh, uint16_t* sAl,
                                          uint16_t* sBh, uint16_t* sBl,
                                          int mbase, int nbase, int g, int t4, Acc& A) {
#pragma unroll
    for (int kk = 0; kk < 64; kk += 16) {
        uint32_t ah[4][4], al[4][4];
#pragma unroll
        for (int mf = 0; mf < 4; mf++) {
            int base = (mbase + mf * 16 + g) * BKP + kk + 2 * t4;
            ah[mf][0] = *(const uint32_t*)(sAh + base);
            ah[mf][1] = *(const uint32_t*)(sAh + base + 8 * BKP);
            ah[mf][2] = *(const uint32_t*)(sAh + base + 8);
            ah[mf][3] = *(const uint32_t*)(sAh + base + 8 * BKP + 8);
            al[mf][0] = *(const uint32_t*)(sAl + base);
            al[mf][1] = *(const uint32_t*)(sAl + base + 8 * BKP);
            al[mf][2] = *(const uint32_t*)(sAl + base + 8);
            al[mf][3] = *(const uint32_t*)(sAl + base + 8 * BKP + 8);
        }
#pragma unroll
        for (int nf = 0; nf < 4; nf++) {
            int bb = (nbase + nf * 8 + g) * BKP + kk + 2 * t4;
            uint32_t bh[2], bl[2];
            bh[0] = *(const uint32_t*)(sBh + bb);
            bh[1] = *(const uint32_t*)(sBh + bb + 8);
            bl[0] = *(const uint32_t*)(sBl + bb);
            bl[1] = *(const uint32_t*)(sBl + bb + 8);
#pragma unroll
            for (int mf = 0; mf < 4; mf++) {
                mma_bf16(A.v[mf][nf], ah[mf], bh);
                mma_bf16(A.v[mf][nf], ah[mf], bl);
                mma_bf16(A.v[mf][nf], al[mf], bh);
            }
        }
    }
}

// ---- bulk GEMM: A fp32 (split on the fly), output fp16 with bias ------------
__device__ void gemm_f32A_h16(const float* __restrict__ A, int lda,
                              const __nv_bfloat16* __restrict__ Wh,
                              const __nv_bfloat16* __restrict__ Wl, int ldw,
                              const float* __restrict__ bias,
                              __half* __restrict__ Cc, int K, int M, int m0, int n0,
                              uint16_t* sm) {
    uint16_t* sAh = sm;
    uint16_t* sAl = sm + 128 * BKP;
    uint16_t* sBh = sm + 2 * 128 * BKP;
    uint16_t* sBl = sm + 3 * 128 * BKP;
    const int tid = threadIdx.x;
    const int w = tid >> 5, lane = tid & 31;
    const int g = lane >> 2, t4 = lane & 3;
    const int mbase = (w >> 2) * 64, nbase = (w & 3) * 32;
    Acc acc;
#pragma unroll
    for (int i = 0; i < 4; i++)
#pragma unroll
        for (int j = 0; j < 4; j++)
#pragma unroll
            for (int q = 0; q < 4; q++) acc.v[i][j][q] = 0.0f;

    for (int kt = 0; kt < K; kt += 64) {
        for (int it = tid; it < 1024; it += NT) {
            int row = it >> 3;
            int c8 = (it & 7) << 3;
            int mm = m0 + row; if (mm >= M) mm = M - 1;
            const float* ap = A + (size_t)mm * lda + kt + c8;
            float4 v0 = *(const float4*)ap;
            float4 v1 = *(const float4*)(ap + 4);
            ushort4 h4a, h4b, l4a, l4b;
            __nv_bfloat16 hh, ll;
            float f[8] = {v0.x, v0.y, v0.z, v0.w, v1.x, v1.y, v1.z, v1.w};
            uint16_t hs[8], ls[8];
#pragma unroll
            for (int q = 0; q < 8; q++) {
                hh = __float2bfloat16(f[q]);
                ll = __float2bfloat16(f[q] - __bfloat162float(hh));
                hs[q] = __bfloat16_as_ushort(hh);
                ls[q] = __bfloat16_as_ushort(ll);
            }
            int so = row * BKP + c8;
#pragma unroll
            for (int q = 0; q < 8; q++) { sAh[so + q] = hs[q]; sAl[so + q] = ls[q]; }
            size_t bo = (size_t)(n0 + row) * ldw + kt + c8;
            *(uint4*)(sBh + so) = *(const uint4*)(Wh + bo);
            *(uint4*)(sBl + so) = *(const uint4*)(Wl + bo);
        }
        __syncthreads();
        mma_chunk(sAh, sAl, sBh, sBl, mbase, nbase, g, t4, acc);
        __syncthreads();
    }
#pragma unroll
    for (int mf = 0; mf < 4; mf++) {
#pragma unroll
        for (int nf = 0; nf < 4; nf++) {
            int m = m0 + mbase + mf * 16 + g;
            int n = n0 + nbase + nf * 8 + 2 * t4;
            float b0 = bias[n], b1 = bias[n + 1];
            if (m < M)
                *(__half2*)(Cc + (size_t)m * G3 + n) =
                    __floats2half2_rn(acc.v[mf][nf][0] + b0, acc.v[mf][nf][1] + b1);
            if (m + 8 < M)
                *(__half2*)(Cc + (size_t)(m + 8) * G3 + n) =
                    __floats2half2_rn(acc.v[mf][nf][2] + b0, acc.v[mf][nf][3] + b1);
        }
    }
    __syncthreads();
}

// ---- per-step GEMM: A pre-split bf16, output fp32; bias or fp16-pre add -----
__device__ void gemm_bf16A(const __nv_bfloat16* __restrict__ Ah,
                           const __nv_bfloat16* __restrict__ Al, int lda,
                           const __nv_bfloat16* __restrict__ Wh,
                           const __nv_bfloat16* __restrict__ Wl, int ldw,
                           const float* __restrict__ bias,
                           const __half* __restrict__ pre,
                           float* __restrict__ Cc, int K, int M, int m0, int n0,
                           uint16_t* sm) {
    uint16_t* sAh = sm;
    uint16_t* sAl = sm + 128 * BKP;
    uint16_t* sBh = sm + 2 * 128 * BKP;
    uint16_t* sBl = sm + 3 * 128 * BKP;
    const int tid = threadIdx.x;
    const int w = tid >> 5, lane = tid & 31;
    const int g = lane >> 2, t4 = lane & 3;
    const int mbase = (w >> 2) * 64, nbase = (w & 3) * 32;
    Acc acc;
#pragma unroll
    for (int i = 0; i < 4; i++)
#pragma unroll
        for (int j = 0; j < 4; j++)
#pragma unroll
            for (int q = 0; q < 4; q++) acc.v[i][j][q] = 0.0f;

    for (int kt = 0; kt < K; kt += 64) {
        for (int it = tid; it < 1024; it += NT) {
            int row = it >> 3;
            int c8 = (it & 7) << 3;
            int mm = m0 + row; if (mm >= M) mm = M - 1;
            size_t ao = (size_t)mm * lda + kt + c8;
            int so = row * BKP + c8;
            *(uint4*)(sAh + so) = *(const uint4*)(Ah + ao);
            *(uint4*)(sAl + so) = *(const uint4*)(Al + ao);
            size_t bo = (size_t)(n0 + row) * ldw + kt + c8;
            *(uint4*)(sBh + so) = *(const uint4*)(Wh + bo);
            *(uint4*)(sBl + so) = *(const uint4*)(Wl + bo);
        }
        __syncthreads();
        mma_chunk(sAh, sAl, sBh, sBl, mbase, nbase, g, t4, acc);
        __syncthreads();
    }
#pragma unroll
    for (int mf = 0; mf < 4; mf++) {
#pragma unroll
        for (int nf = 0; nf < 4; nf++) {
            int m = m0 + mbase + mf * 16 + g;
            int n = n0 + nbase + nf * 8 + 2 * t4;
            if (pre == nullptr) {
                float b0 = bias[n], b1 = bias[n + 1];
                if (m < M)
                    *(float2*)(Cc + (size_t)m * G3 + n) =
                        make_float2(acc.v[mf][nf][0] + b0, acc.v[mf][nf][1] + b1);
                if (m + 8 < M)
                    *(float2*)(Cc + (size_t)(m + 8) * G3 + n) =
                        make_float2(acc.v[mf][nf][2] + b0, acc.v[mf][nf][3] + b1);
            } else {
                if (m < M) {
                    float2 p = __half22float2(*(const __half2*)(pre + (size_t)m * G3 + n));
                    *(float2*)(Cc + (size_t)m * G3 + n) =
                        make_float2(acc.v[mf][nf][0] + p.x, acc.v[mf][nf][1] + p.y);
                }
                if (m + 8 < M) {
                    float2 p = __half22float2(*(const __half2*)(pre + (size_t)(m + 8) * G3 + n));
                    *(float2*)(Cc + (size_t)(m + 8) * G3 + n) =
                        make_float2(acc.v[mf][nf][2] + p.x, acc.v[mf][nf][3] + p.y);
                }
            }
        }
    }
    __syncthreads();
}

// ---------------- GRU gates ---------------------------------------------------
__device__ __forceinline__ void gate_h16(const __half* __restrict__ gi,
                                         const float* __restrict__ gh,
                                         float* __restrict__ h,
                                         __nv_bfloat16* __restrict__ hhi,
                                         __nv_bfloat16* __restrict__ hlo,
                                         int M, int gtid, int nthr) {
    int total = M * HID;
    for (int idx = gtid; idx < total; idx += nthr) {
        int m = idx >> 8;
        int j = idx & 255;
        const __half* gim = gi + (size_t)m * G3;
        const float* ghm = gh + (size_t)m * G3;
        float r = 1.0f / (1.0f + __expf(-(__half2float(gim[j]) + ghm[j])));
        float z = 1.0f / (1.0f + __expf(-(__half2float(gim[HID + j]) + ghm[HID + j])));
        float n = tanhf(__half2float(gim[2 * HID + j]) + r * ghm[2 * HID + j]);
        float v = (1.0f - z) * n + z * h[idx];
        h[idx] = v;
        bsplit(v, hhi + idx, hlo + idx);
    }
}

__device__ __forceinline__ void gate_f32(const float* __restrict__ gi,
                                         const float* __restrict__ gh,
                                         float* __restrict__ h,
                                         __nv_bfloat16* __restrict__ hhi,
                                         __nv_bfloat16* __restrict__ hlo,
                                         int M, int gtid, int nthr) {
    int total = M * HID;
    for (int idx = gtid; idx < total; idx += nthr) {
        int m = idx >> 8;
        int j = idx & 255;
        const float* gim = gi + (size_t)m * G3;
        const float* ghm = gh + (size_t)m * G3;
        float r = 1.0f / (1.0f + __expf(-(gim[j] + ghm[j])));
        float z = 1.0f / (1.0f + __expf(-(gim[HID + j] + ghm[HID + j])));
        float n = tanhf(gim[2 * HID + j] + r * ghm[2 * HID + j]);
        float v = (1.0f - z) * n + z * h[idx];
        h[idx] = v;
        bsplit(v, hhi + idx, hlo + idx);
    }
}

__device__ __forceinline__ void convW(const float* __restrict__ W, int off, int n,
                                      int gtid, int nthr) {
    for (int i = gtid; i < n; i += nthr) {
        float w = W[i];
        __nv_bfloat16 h = __float2bfloat16(w);
        g_Whi[off + i] = h;
        g_Wlo[off + i] = __float2bfloat16(w - __bfloat162float(h));
    }
}

#define ST_T 378                   // 63 x 6 tiles (stocks)
#define NW_T 78                    // 13 x 6 tiles (news)
#define PA_TOT (ST_T * 2 + NW_T)   // 834
#define BI3_TOT (24000 + 4800)     // bulk gi_li + gi_c

// ---------------- the persistent mega-kernel ---------------------------------
__global__ __launch_bounds__(NT, 2)
void mega_kernel(const float* __restrict__ inputs, const int* __restrict__ ei,
                 const float* __restrict__ h_start, const float* __restrict__ hi_start,
                 const float* __restrict__ mc_start,
                 const float* __restrict__ Wih_c,  const float* __restrict__ Whh_c,
                 const float* __restrict__ bih_c,  const float* __restrict__ bhh_c,
                 const float* __restrict__ Wih_lh, const float* __restrict__ Whh_lh,
                 const float* __restrict__ bih_lh, const float* __restrict__ bhh_lh,
                 const float* __restrict__ Wih_li, const float* __restrict__ Whh_li,
                 const float* __restrict__ bih_li, const float* __restrict__ bhh_li,
                 float* __restrict__ m_out, float* __restrict__ h_out,
                 float* __restrict__ hi_out) {
    extern __shared__ uint16_t sm16[];

    const int gtid = blockIdx.x * NT + threadIdx.x;
    const int nthr = gridDim.x * NT;
    const int gwarp = gtid >> 5;
    const int lane = threadIdx.x & 31;
    const int nwarp = nthr >> 5;

    // ==== I0: init states, weights, zero counts + accumulators ====
    for (int i = gtid; i < NSTOCK * HID; i += nthr) {
        float hv = h_start[i & 255], pv = hi_start[i & 255];
        h_out[i] = hv; hi_out[i] = pv;
        bsplit(hv, g_h_hi + i, g_h_lo + i);
        bsplit(pv, g_p_hi + i, g_p_lo + i);
    }
    for (int i = gtid; i < NNEWS * HID; i += nthr) {
        float v = mc_start[i & 255];
        g_mc[i] = v;
        bsplit(v, g_mc_hi + i, g_mc_lo + i);
    }
    convW(Wih_li, OW_IH_LI, G3 * C_IN, gtid, nthr);
    convW(Whh_li, OW_HH_LI, G3 * HID,  gtid, nthr);
    convW(Wih_c,  OW_IH_C,  G3 * C_IN, gtid, nthr);
    convW(Whh_c,  OW_HH_C,  G3 * HID,  gtid, nthr);
    convW(Wih_lh, OW_IH_LH, G3 * CM,   gtid, nthr);
    convW(Whh_lh, OW_HH_LH, G3 * HID,  gtid, nthr);
    for (int i = gtid; i < NNE; i += nthr) g_inv_news_all[i] = 0.0f;
    for (int i = gtid; i < NSTE; i += nthr) g_inv_stock_all[i] = 0.0f;
    for (size_t i = gtid; i < (size_t)NNE * C_IN; i += nthr) g_acc_news_all[i] = 0.0f;
    for (size_t i = gtid; i < (size_t)NSTE * C_IN; i += nthr) g_accmc_all[i] = 0.0f;
    grid_sync();
    // ==== I0b: degree counts ====
    for (int task = gtid; task < SEQ_L * NEDGE; task += nthr) {
        int t = task / NEDGE, e = task - t * NEDGE;
        const int* news = ei + (size_t)t * 2 * NEDGE;
        atomicAdd(&g_inv_news_all[t * NNEWS + news[e]], 1.0f);
        atomicAdd(&g_inv_stock_all[t * NSTOCK + news[NEDGE + e]], 1.0f);
    }
    grid_sync();
    // ==== I1: invert counts; bulk scatter x -> news ====
    for (int i = gtid; i < NNE; i += nthr)
        g_inv_news_all[i] = 1.0f / fmaxf(g_inv_news_all[i], 1.0f);
    for (int i = gtid; i < NSTE; i += nthr)
        g_inv_stock_all[i] = 1.0f / fmaxf(g_inv_stock_all[i], 1.0f);
    for (int task = gwarp; task < SEQ_L * NEDGE; task += nwarp) {
        int t = task / NEDGE, e = task - t * NEDGE;
        const int* news = ei + (size_t)t * 2 * NEDGE;
        int n = news[e], s = news[NEDGE + e];
        float4 v = ((const float4*)(inputs + ((size_t)t * NSTOCK + s) * C_IN))[lane];
        float* dst = g_acc_news_all + ((size_t)t * NNEWS + n) * C_IN + lane * 4;
        atomicAdd(dst + 0, v.x); atomicAdd(dst + 1, v.y);
        atomicAdd(dst + 2, v.z); atomicAdd(dst + 3, v.w);
    }
    grid_sync();
    // ==== I2: normalize center in place ====
    for (size_t i = gtid; i < (size_t)NNE * C_IN; i += nthr)
        g_acc_news_all[i] *= g_inv_news_all[i >> 7];
    grid_sync();
    // ==== I3: bulk GEMMs gi_li (M=512000) + gi_c (M=102400), K=128 ====
    for (int tile = blockIdx.x; tile < BI3_TOT; tile += gridDim.x) {
        if (tile < 24000) {
            int mt = tile / 6, nt = tile % 6;
            gemm_f32A_h16(inputs, C_IN, g_Whi + OW_IH_LI, g_Wlo + OW_IH_LI, C_IN,
                          bih_li, g_gi_li_all, C_IN, NSTE, mt * 128, nt * 128, sm16);
        } else {
            int idx = tile - 24000, mt = idx / 6, nt = idx % 6;
            gemm_f32A_h16(g_acc_news_all, C_IN, g_Whi + OW_IH_C, g_Wlo + OW_IH_C, C_IN,
                          bih_c, g_gi_c_all, C_IN, NNE, mt * 128, nt * 128, sm16);
        }
    }
    grid_sync();
    // ==== I4: bulk scatter center -> stocks ====
    for (int task = gwarp; task < SEQ_L * NEDGE; task += nwarp) {
        int t = task / NEDGE, e = task - t * NEDGE;
        const int* news = ei + (size_t)t * 2 * NEDGE;
        int n = news[e], s = news[NEDGE + e];
        float4 v = ((const float4*)(g_acc_news_all + ((size_t)t * NNEWS + n) * C_IN))[lane];
        float* dst = g_accmc_all + ((size_t)t * NSTOCK + s) * C_IN + lane * 4;
        atomicAdd(dst + 0, v.x); atomicAdd(dst + 1, v.y);
        atomicAdd(dst + 2, v.z); atomicAdd(dst + 3, v.w);
    }
    grid_sync();
    // ==== I5: normalize mcenter in place; write m_out center cols (t=63) ====
    for (size_t i = gtid; i < (size_t)NSTE * C_IN; i += nthr) {
        float v = g_accmc_all[i] * g_inv_stock_all[i >> 7];
        g_accmc_all[i] = v;
        if (i >= (size_t)63 * NSTOCK * C_IN) {
            size_t r = i - (size_t)63 * NSTOCK * C_IN;
            m_out[(r >> 7) * CM + (r & 127)] = v;
        }
    }
    grid_sync();
    // ==== I6: bulk GEMM gi_lh1 = mcenter @ Wih_lh[:, :128]^T + bih_lh ====
    for (int tile = blockIdx.x; tile < 24000; tile += gridDim.x) {
        int mt = tile / 6, nt = tile % 6;
        gemm_f32A_h16(g_accmc_all, C_IN, g_Whi + OW_IH_LH, g_Wlo + OW_IH_LH, CM,
                      bih_lh, g_gi_lh1_all, C_IN, NSTE, mt * 128, nt * 128, sm16);
    }
    grid_sync();

    // ==== sequential recurrence: all GEMMs K=256, pure-copy staging ====
    for (int t = 0; t < SEQ_L; t++) {
        const int* news = ei + (size_t)t * 2 * NEDGE;
        const int* stck = news + NEDGE;

        // ---- A: gh_li, gh_lh, gh_n ----
        for (int tile = blockIdx.x; tile < PA_TOT; tile += gridDim.x) {
            if (tile < ST_T) {
                int mt = tile / 6, nt = tile % 6;
                gemm_bf16A(g_p_hi, g_p_lo, HID, g_Whi + OW_HH_LI, g_Wlo + OW_HH_LI, HID,
                           bhh_li, nullptr, g_gh_li, HID, NSTOCK, mt * 128, nt * 128, sm16);
            } else if (tile < 2 * ST_T) {
                int idx = tile - ST_T, mt = idx / 6, nt = idx % 6;
                gemm_bf16A(g_h_hi, g_h_lo, HID, g_Whi + OW_HH_LH, g_Wlo + OW_HH_LH, HID,
                           bhh_lh, nullptr, g_gh_lh, HID, NSTOCK, mt * 128, nt * 128, sm16);
            } else {
                int idx = tile - 2 * ST_T, mt = idx / 6, nt = idx % 6;
                gemm_bf16A(g_mc_hi, g_mc_lo, HID, g_Whi + OW_HH_C, g_Wlo + OW_HH_C, HID,
                           bhh_c, nullptr, g_gh_n, HID, NNEWS, mt * 128, nt * 128, sm16);
            }
        }
        grid_sync();

        // ---- B: gates m_c + h_input; zero acc_mc ----
        gate_h16(g_gi_c_all + (size_t)t * NNEWS * G3, g_gh_n,
                 g_mc, g_mc_hi, g_mc_lo, NNEWS, gtid, nthr);
        gate_h16(g_gi_li_all + (size_t)t * NSTOCK * G3, g_gh_li,
                 hi_out, g_p_hi, g_p_lo, NSTOCK, gtid, nthr);
        for (int i = gtid; i < NSTOCK * HID; i += nthr) g_accmc[i] = 0.0f;
        grid_sync();

        // ---- C: scatter m_c (news -> stocks, 256 ch) ----
        for (int e = gwarp; e < NEDGE; e += nwarp) {
            int n = news[e];
            int s = stck[e];
#pragma unroll
            for (int j = 0; j < 2; j++) {
                int c = (lane + j * 32) * 4;
                float4 v = *(const float4*)(g_mc + (size_t)n * HID + c);
                float* dst = g_accmc + (size_t)s * HID + c;
                atomicAdd(dst + 0, v.x); atomicAdd(dst + 1, v.y);
                atomicAdd(dst + 2, v.z); atomicAdd(dst + 3, v.w);
            }
        }
        grid_sync();

        // ---- D: normalize acc_mc + split (m_out mc cols at t=63) ----
        {
            const float* inv = g_inv_stock_all + t * NSTOCK;
            for (int i = gtid; i < NSTOCK * HID; i += nthr) {
                float v = g_accmc[i] * inv[i >> 8];
                bsplit(v, g_amc_hi + i, g_amc_lo + i);
                if (t == SEQ_L - 1) m_out[(i >> 8) * CM + C_IN + (i & 255)] = v;
            }
        }
        grid_sync();

        // ---- E: gis = gi_lh1[t] + m_mc @ Wih_lh[:, 128:]^T ----
        for (int tile = blockIdx.x; tile < ST_T; tile += gridDim.x) {
            int mt = tile / 6, nt = tile % 6;
            gemm_bf16A(g_amc_hi, g_amc_lo, HID,
                       g_Whi + OW_IH_LH + C_IN, g_Wlo + OW_IH_LH + C_IN, CM,
                       nullptr, g_gi_lh1_all + (size_t)t * NSTOCK * G3,
                       g_gis, HID, NSTOCK, mt * 128, nt * 128, sm16);
        }
        grid_sync();

        // ---- F: gate h ----
        gate_f32(g_gis, g_gh_lh, h_out, g_h_hi, g_h_lo, NSTOCK, gtid, nthr);
        grid_sync();
    }
}

// ---------------- launch -----------------------------------------------------
extern "C" void kernel_launch(void* const* d_in, const int* in_sizes, int n_in,
                              void* d_out, int out_size) {
    const float* inputs   = (const float*)d_in[0];
    const int*   ei       = (const int*)d_in[1];
    const float* h_start  = (const float*)d_in[2];
    const float* hi_start = (const float*)d_in[3];
    const float* mc_start = (const float*)d_in[4];
    const float* Wih_c  = (const float*)d_in[5];
    const float* Whh_c  = (const float*)d_in[6];
    const float* bih_c  = (const float*)d_in[7];
    const float* bhh_c  = (const float*)d_in[8];
    const float* Wih_lh = (const float*)d_in[9];
    const float* Whh_lh = (const float*)d_in[10];
    const float* bih_lh = (const float*)d_in[11];
    const float* bhh_lh = (const float*)d_in[12];
    const float* Wih_li = (const float*)d_in[13];
    const float* Whh_li = (const float*)d_in[14];
    const float* bih_li = (const float*)d_in[15];
    const float* bhh_li = (const float*)d_in[16];

    float* out    = (float*)d_out;
    float* m_out  = out;                                // [8000, 384]
    float* h_out  = out + (size_t)NSTOCK * CM;          // [8000, 256]
    float* hi_out = h_out + (size_t)NSTOCK * HID;       // [8000, 256]

    cudaFuncSetAttribute(mega_kernel, cudaFuncAttributeMaxDynamicSharedMemorySize, SMEM_BYTES);

    int dev = 0, nsm = 0, occ = 0;
    cudaGetDevice(&dev);
    cudaDeviceGetAttribute(&nsm, cudaDevAttrMultiProcessorCount, dev);
    cudaOccupancyMaxActiveBlocksPerMultiprocessor(&occ, mega_kernel, NT, SMEM_BYTES);
    if (occ < 1) occ = 1;
    int nblk = nsm * occ;

    unsigned* bar = nullptr;
    cudaGetSymbolAddress((void**)&bar, g_bar_count);
    cudaMemsetAsync(bar, 0, sizeof(unsigned));

    mega_kernel<<<nblk, NT, SMEM_BYTES>>>(inputs, ei, h_start, hi_start, mc_start,
                                          Wih_c, Whh_c, bih_c, bhh_c,
                                          Wih_lh, Whh_lh, bih_lh, bhh_lh,
                                          Wih_li, Whh_li, bih_li, bhh_li,
                                          m_out, h_out, hi_out);
}

// round 10
// speedup vs baseline: 2.6901x; 1.1005x over previous
#include <cuda_runtime.h>
#include <cuda_bf16.h>
#include <cuda_fp16.h>
#include <math.h>
#include <stdint.h>

#define SEQ_L 64
#define NSTOCK 8000
#define NNEWS 1600
#define C_IN 128
#define HID 256
#define NEDGE 32000
#define G3 768
#define CM 384
#define NT 256
#define NSTE 512000
#define NNE  102400

// per-step cp.async GEMM: BK=32 double-buffered
#define BKP32 40
#define SA_ELEM (128 * BKP32)          // 5120 elems
#define SA_SZ (SA_ELEM * 2)            // 10240 B
#define STAGE_SZ (4 * SA_SZ)           // 40960 B
#define SMEM_BYTES (2 * STAGE_SZ)      // 81920 B (bulk BK=64 core needs 73728 <= this)
// bulk single-buffer GEMM: BK=64
#define BKP 72

// ---- weight bf16 hi/lo offsets (elements) -----------------------------------
#define OW_IH_LI 0
#define OW_HH_LI 98304
#define OW_IH_C  294912
#define OW_HH_C  393216
#define OW_IH_LH 589824
#define OW_HH_LH 884736
#define W_TOTAL  1081344

// ---------------- static device scratch (~2.1GB, linker-safe) ----------------
__device__ __align__(16) float g_acc_news_all[(size_t)NNE * C_IN];
__device__ __align__(16) float g_accmc_all[(size_t)NSTE * C_IN];
__device__ __align__(16) __half g_gi_li_all[(size_t)NSTE * G3];
__device__ __align__(16) __half g_gi_c_all[(size_t)NNE * G3];
__device__ __align__(16) __half g_gi_lh1_all[(size_t)NSTE * G3];
__device__ float g_inv_news_all[NNE];
__device__ float g_inv_stock_all[NSTE];
// CSR (stock-destination sorted edges, per t)
__device__ int g_deg[NSTE];
__device__ int g_csr_off[NSTE];
__device__ int g_cur[NSTE];
__device__ int g_csr_n[SEQ_L * NEDGE];
__device__ int g_tot[SEQ_L];
// per-step state
__device__ __align__(16) float g_mc[NNEWS * HID];
__device__ __align__(16) __nv_bfloat16 g_mc_hi[NNEWS * HID];
__device__ __align__(16) __nv_bfloat16 g_mc_lo[NNEWS * HID];
__device__ __align__(16) __nv_bfloat16 g_h_hi[NSTOCK * HID];
__device__ __align__(16) __nv_bfloat16 g_h_lo[NSTOCK * HID];
__device__ __align__(16) __nv_bfloat16 g_p_hi[NSTOCK * HID];
__device__ __align__(16) __nv_bfloat16 g_p_lo[NSTOCK * HID];
__device__ __align__(16) __nv_bfloat16 g_amc_hi[NSTOCK * HID];
__device__ __align__(16) __nv_bfloat16 g_amc_lo[NSTOCK * HID];
__device__ __align__(16) __half g_gh_li[NSTOCK * G3];
__device__ __align__(16) __half g_gh_lh[NSTOCK * G3];
__device__ __align__(16) __half g_gh_n[NNEWS * G3];
__device__ __align__(16) __half g_gis[NSTOCK * G3];
__device__ __align__(16) __nv_bfloat16 g_Whi[W_TOTAL];
__device__ __align__(16) __nv_bfloat16 g_Wlo[W_TOTAL];
__device__ unsigned g_bar_count = 0;

// ---------------- software grid barrier (monotonic) --------------------------
__device__ __forceinline__ void grid_sync() {
    __syncthreads();
    __threadfence();
    if (threadIdx.x == 0) {
        unsigned G = gridDim.x;
        unsigned arrival = atomicAdd(&g_bar_count, 1u) + 1u;
        unsigned target = ((arrival + G - 1u) / G) * G;
        volatile unsigned* vc = &g_bar_count;
        while (*vc < target) { __nanosleep(64); }
    }
    __syncthreads();
    __threadfence();
}

__device__ __forceinline__ void bsplit(float v, __nv_bfloat16* hp, __nv_bfloat16* lp) {
    __nv_bfloat16 h = __float2bfloat16(v);
    *hp = h;
    *lp = __float2bfloat16(v - __bfloat162float(h));
}

__device__ __forceinline__ void mma_bf16(float* c, const uint32_t* a, const uint32_t* b) {
    asm volatile("mma.sync.aligned.m16n8k16.row.col.f32.bf16.bf16.f32 "
                 "{%0,%1,%2,%3}, {%4,%5,%6,%7}, {%8,%9}, {%0,%1,%2,%3};"
                 : "+f"(c[0]), "+f"(c[1]), "+f"(c[2]), "+f"(c[3])
                 : "r"(a[0]), "r"(a[1]), "r"(a[2]), "r"(a[3]), "r"(b[0]), "r"(b[1]));
}

struct Acc { float v[4][4][4]; };

// ---------------- fragment compute over one staged chunk ---------------------
template <int BK, int KP>
__device__ __forceinline__ void mma_chunk(const uint16_t* sAh, const uint16_t* sAl,
                                          const uint16_t* sBh, const uint16_t* sBl,
                                          int mbase, int nbase, int g, int t4, Acc& A) {
#pragma unroll
    for (int kk = 0; kk < BK; kk += 16) {
        uint32_t ah[4][4], al[4][4];
#pragma unroll
        for (int mf = 0; mf < 4; mf++) {
            int base = (mbase + mf * 16 + g) * KP + kk + 2 * t4;
            ah[mf][0] = *(const uint32_t*)(sAh + base);
            ah[mf][1] = *(const uint32_t*)(sAh + base + 8 * KP);
            ah[mf][2] = *(const uint32_t*)(sAh + base + 8);
            ah[mf][3] = *(const uint32_t*)(sAh + base + 8 * KP + 8);
            al[mf][0] = *(const uint32_t*)(sAl + base);
            al[mf][1] = *(const uint32_t*)(sAl + base + 8 * KP);
            al[mf][2] = *(const uint32_t*)(sAl + base + 8);
            al[mf][3] = *(const uint32_t*)(sAl + base + 8 * KP + 8);
        }
#pragma unroll
        for (int nf = 0; nf < 4; nf++) {
            int bb = (nbase + nf * 8 + g) * KP + kk + 2 * t4;
            uint32_t bh[2], bl[2];
            bh[0] = *(const uint32_t*)(sBh + bb);
            bh[1] = *(const uint32_t*)(sBh + bb + 8);
            bl[0] = *(const uint32_t*)(sBl + bb);
            bl[1] = *(const uint32_t*)(sBl + bb + 8);
#pragma unroll
            for (int mf = 0; mf < 4; mf++) {
                mma_bf16(A.v[mf][nf], ah[mf], bh);
                mma_bf16(A.v[mf][nf], ah[mf], bl);
                mma_bf16(A.v[mf][nf], al[mf], bh);
            }
        }
    }
}

// ---------------- per-step GEMM: cp.async 2-stage, output fp16 ---------------
__device__ void gemm_step(const __nv_bfloat16* __restrict__ Ah,
                          const __nv_bfloat16* __restrict__ Al, int lda,
                          const __nv_bfloat16* __restrict__ Wh,
                          const __nv_bfloat16* __restrict__ Wl, int ldw,
                          const float* __restrict__ bias,
                          const __half* __restrict__ pre,
                          __half* __restrict__ Cc, int K, int M, int m0, int n0,
                          char* dsm) {
    const int tid = threadIdx.x;
    const int w = tid >> 5, lane = tid & 31;
    const int g = lane >> 2, t4 = lane & 3;
    const int mbase = (w >> 2) * 64, nbase = (w & 3) * 32;
    const uint32_t sb0 = (uint32_t)__cvta_generic_to_shared(dsm);
    Acc acc;
#pragma unroll
    for (int i = 0; i < 4; i++)
#pragma unroll
        for (int j = 0; j < 4; j++)
#pragma unroll
            for (int q = 0; q < 4; q++) acc.v[i][j][q] = 0.0f;

    const int NC = K >> 5;
    // stage a chunk via cp.async (512 16B items per operand array)
    auto stage = [&](int c) {
        uint32_t sb = sb0 + (c & 1) * STAGE_SZ;
        int kt = c << 5;
        for (int it = tid; it < 512; it += NT) {
            int row = it >> 2;
            int c8 = (it & 3) << 3;
            int mm = m0 + row; if (mm >= M) mm = M - 1;
            const void* gah = Ah + (size_t)mm * lda + kt + c8;
            const void* gal = Al + (size_t)mm * lda + kt + c8;
            const void* gbh = Wh + (size_t)(n0 + row) * ldw + kt + c8;
            const void* gbl = Wl + (size_t)(n0 + row) * ldw + kt + c8;
            uint32_t so = sb + (row * BKP32 + c8) * 2;
            asm volatile("cp.async.ca.shared.global [%0], [%1], 16;" :: "r"(so), "l"(gah));
            asm volatile("cp.async.ca.shared.global [%0], [%1], 16;" :: "r"(so + SA_SZ), "l"(gal));
            asm volatile("cp.async.ca.shared.global [%0], [%1], 16;" :: "r"(so + 2 * SA_SZ), "l"(gbh));
            asm volatile("cp.async.ca.shared.global [%0], [%1], 16;" :: "r"(so + 3 * SA_SZ), "l"(gbl));
        }
        asm volatile("cp.async.commit_group;");
    };

    stage(0);
    for (int c = 0; c < NC; c++) {
        if (c + 1 < NC) {
            stage(c + 1);
            asm volatile("cp.async.wait_group 1;");
        } else {
            asm volatile("cp.async.wait_group 0;");
        }
        __syncthreads();
        const uint16_t* st = (const uint16_t*)(dsm + (c & 1) * STAGE_SZ);
        mma_chunk<32, BKP32>(st, st + SA_ELEM, st + 2 * SA_ELEM, st + 3 * SA_ELEM,
                             mbase, nbase, g, t4, acc);
        __syncthreads();
    }
#pragma unroll
    for (int mf = 0; mf < 4; mf++) {
#pragma unroll
        for (int nf = 0; nf < 4; nf++) {
            int m = m0 + mbase + mf * 16 + g;
            int n = n0 + nbase + nf * 8 + 2 * t4;
            if (pre == nullptr) {
                float b0 = bias[n], b1 = bias[n + 1];
                if (m < M)
                    *(__half2*)(Cc + (size_t)m * G3 + n) =
                        __floats2half2_rn(acc.v[mf][nf][0] + b0, acc.v[mf][nf][1] + b1);
                if (m + 8 < M)
                    *(__half2*)(Cc + (size_t)(m + 8) * G3 + n) =
                        __floats2half2_rn(acc.v[mf][nf][2] + b0, acc.v[mf][nf][3] + b1);
            } else {
                if (m < M) {
                    float2 p = __half22float2(*(const __half2*)(pre + (size_t)m * G3 + n));
                    *(__half2*)(Cc + (size_t)m * G3 + n) =
                        __floats2half2_rn(acc.v[mf][nf][0] + p.x, acc.v[mf][nf][1] + p.y);
                }
                if (m + 8 < M) {
                    float2 p = __half22float2(*(const __half2*)(pre + (size_t)(m + 8) * G3 + n));
                    *(__half2*)(Cc + (size_t)(m + 8) * G3 + n) =
                        __floats2half2_rn(acc.v[mf][nf][2] + p.x, acc.v[mf][nf][3] + p.y);
                }
            }
        }
    }
    __syncthreads();
}

// ---------------- bulk GEMM: fp32 A split on the fly, output fp16 ------------
__device__ void gemm_f32A_h16(const float* __restrict__ A, int lda,
                              const __nv_bfloat16* __restrict__ Wh,
                              const __nv_bfloat16* __restrict__ Wl, int ldw,
                              const float* __restrict__ bias,
                              __half* __restrict__ Cc, int K, int M, int m0, int n0,
                              uint16_t* sm) {
    uint16_t* sAh = sm;
    uint16_t* sAl = sm + 128 * BKP;
    uint16_t* sBh = sm + 2 * 128 * BKP;
    uint16_t* sBl = sm + 3 * 128 * BKP;
    const int tid = threadIdx.x;
    const int w = tid >> 5, lane = tid & 31;
    const int g = lane >> 2, t4 = lane & 3;
    const int mbase = (w >> 2) * 64, nbase = (w & 3) * 32;
    Acc acc;
#pragma unroll
    for (int i = 0; i < 4; i++)
#pragma unroll
        for (int j = 0; j < 4; j++)
#pragma unroll
            for (int q = 0; q < 4; q++) acc.v[i][j][q] = 0.0f;

    for (int kt = 0; kt < K; kt += 64) {
        for (int it = tid; it < 1024; it += NT) {
            int row = it >> 3;
            int c8 = (it & 7) << 3;
            int mm = m0 + row; if (mm >= M) mm = M - 1;
            const float* ap = A + (size_t)mm * lda + kt + c8;
            float4 v0 = *(const float4*)ap;
            float4 v1 = *(const float4*)(ap + 4);
            float f[8] = {v0.x, v0.y, v0.z, v0.w, v1.x, v1.y, v1.z, v1.w};
            int so = row * BKP + c8;
#pragma unroll
            for (int q = 0; q < 8; q++) {
                __nv_bfloat16 hh = __float2bfloat16(f[q]);
                sAh[so + q] = __bfloat16_as_ushort(hh);
                sAl[so + q] = __bfloat16_as_ushort(
                    __float2bfloat16(f[q] - __bfloat162float(hh)));
            }
            size_t bo = (size_t)(n0 + row) * ldw + kt + c8;
            *(uint4*)(sBh + so) = *(const uint4*)(Wh + bo);
            *(uint4*)(sBl + so) = *(const uint4*)(Wl + bo);
        }
        __syncthreads();
        mma_chunk<64, BKP>(sAh, sAl, sBh, sBl, mbase, nbase, g, t4, acc);
        __syncthreads();
    }
#pragma unroll
    for (int mf = 0; mf < 4; mf++) {
#pragma unroll
        for (int nf = 0; nf < 4; nf++) {
            int m = m0 + mbase + mf * 16 + g;
            int n = n0 + nbase + nf * 8 + 2 * t4;
            float b0 = bias[n], b1 = bias[n + 1];
            if (m < M)
                *(__half2*)(Cc + (size_t)m * G3 + n) =
                    __floats2half2_rn(acc.v[mf][nf][0] + b0, acc.v[mf][nf][1] + b1);
            if (m + 8 < M)
                *(__half2*)(Cc + (size_t)(m + 8) * G3 + n) =
                    __floats2half2_rn(acc.v[mf][nf][2] + b0, acc.v[mf][nf][3] + b1);
        }
    }
    __syncthreads();
}

// ---------------- GRU gate (fp16 gi + fp16 gh) -------------------------------
__device__ __forceinline__ void gate_hh(const __half* __restrict__ gi,
                                        const __half* __restrict__ gh,
                                        float* __restrict__ h,
                                        __nv_bfloat16* __restrict__ hhi,
                                        __nv_bfloat16* __restrict__ hlo,
                                        int M, int gtid, int nthr) {
    int total = M * HID;
    for (int idx = gtid; idx < total; idx += nthr) {
        int m = idx >> 8;
        int j = idx & 255;
        const __half* gim = gi + (size_t)m * G3;
        const __half* ghm = gh + (size_t)m * G3;
        float r = 1.0f / (1.0f + __expf(-(__half2float(gim[j]) + __half2float(ghm[j]))));
        float z = 1.0f / (1.0f + __expf(-(__half2float(gim[HID + j]) + __half2float(ghm[HID + j]))));
        float n = tanhf(__half2float(gim[2 * HID + j]) + r * __half2float(ghm[2 * HID + j]));
        float v = (1.0f - z) * n + z * h[idx];
        h[idx] = v;
        bsplit(v, hhi + idx, hlo + idx);
    }
}

__device__ __forceinline__ void convW(const float* __restrict__ W, int off, int n,
                                      int gtid, int nthr) {
    for (int i = gtid; i < n; i += nthr) {
        float w = W[i];
        __nv_bfloat16 h = __float2bfloat16(w);
        g_Whi[off + i] = h;
        g_Wlo[off + i] = __float2bfloat16(w - __bfloat162float(h));
    }
}

#define ST_T 378
#define NW_T 78
#define PA_TOT (ST_T * 2 + NW_T)
#define BI3_TOT (24000 + 4800)

// ---------------- the persistent mega-kernel ---------------------------------
__global__ __launch_bounds__(NT, 2)
void mega_kernel(const float* __restrict__ inputs, const int* __restrict__ ei,
                 const float* __restrict__ h_start, const float* __restrict__ hi_start,
                 const float* __restrict__ mc_start,
                 const float* __restrict__ Wih_c,  const float* __restrict__ Whh_c,
                 const float* __restrict__ bih_c,  const float* __restrict__ bhh_c,
                 const float* __restrict__ Wih_lh, const float* __restrict__ Whh_lh,
                 const float* __restrict__ bih_lh, const float* __restrict__ bhh_lh,
                 const float* __restrict__ Wih_li, const float* __restrict__ Whh_li,
                 const float* __restrict__ bih_li, const float* __restrict__ bhh_li,
                 float* __restrict__ m_out, float* __restrict__ h_out,
                 float* __restrict__ hi_out) {
    extern __shared__ char dsm[];

    const int gtid = blockIdx.x * NT + threadIdx.x;
    const int nthr = gridDim.x * NT;
    const int gwarp = gtid >> 5;
    const int lane = threadIdx.x & 31;
    const int nwarp = nthr >> 5;

    // ==== I0: init states, weights, zero counters ====
    for (int i = gtid; i < NSTOCK * HID; i += nthr) {
        float hv = h_start[i & 255], pv = hi_start[i & 255];
        h_out[i] = hv; hi_out[i] = pv;
        bsplit(hv, g_h_hi + i, g_h_lo + i);
        bsplit(pv, g_p_hi + i, g_p_lo + i);
    }
    for (int i = gtid; i < NNEWS * HID; i += nthr) {
        float v = mc_start[i & 255];
        g_mc[i] = v;
        bsplit(v, g_mc_hi + i, g_mc_lo + i);
    }
    convW(Wih_li, OW_IH_LI, G3 * C_IN, gtid, nthr);
    convW(Whh_li, OW_HH_LI, G3 * HID,  gtid, nthr);
    convW(Wih_c,  OW_IH_C,  G3 * C_IN, gtid, nthr);
    convW(Whh_c,  OW_HH_C,  G3 * HID,  gtid, nthr);
    convW(Wih_lh, OW_IH_LH, G3 * CM,   gtid, nthr);
    convW(Whh_lh, OW_HH_LH, G3 * HID,  gtid, nthr);
    for (int i = gtid; i < NNE; i += nthr) g_inv_news_all[i] = 0.0f;
    for (int i = gtid; i < NSTE; i += nthr) { g_deg[i] = 0; }
    for (int i = gtid; i < SEQ_L; i += nthr) g_tot[i] = 0;
    for (size_t i = gtid; i < (size_t)NNE * C_IN; i += nthr) g_acc_news_all[i] = 0.0f;
    for (size_t i = gtid; i < (size_t)NSTE * C_IN; i += nthr) g_accmc_all[i] = 0.0f;
    grid_sync();
    // ==== I0b: degree counts ====
    for (int task = gtid; task < SEQ_L * NEDGE; task += nthr) {
        int t = task / NEDGE, e = task - t * NEDGE;
        const int* news = ei + (size_t)t * 2 * NEDGE;
        atomicAdd(&g_inv_news_all[t * NNEWS + news[e]], 1.0f);
        atomicAdd(&g_deg[t * NSTOCK + news[NEDGE + e]], 1);
    }
    grid_sync();
    // ==== I1: invert counts; CSR offsets; bulk scatter x -> news ====
    for (int i = gtid; i < NNE; i += nthr)
        g_inv_news_all[i] = 1.0f / fmaxf(g_inv_news_all[i], 1.0f);
    for (int i = gtid; i < NSTE; i += nthr) {
        int d = g_deg[i];
        g_inv_stock_all[i] = 1.0f / fmaxf((float)d, 1.0f);
        int off = atomicAdd(&g_tot[i / NSTOCK], d);
        g_csr_off[i] = off;
        g_cur[i] = off;
    }
    for (int task = gwarp; task < SEQ_L * NEDGE; task += nwarp) {
        int t = task / NEDGE, e = task - t * NEDGE;
        const int* news = ei + (size_t)t * 2 * NEDGE;
        int n = news[e], s = news[NEDGE + e];
        float4 v = ((const float4*)(inputs + ((size_t)t * NSTOCK + s) * C_IN))[lane];
        float* dst = g_acc_news_all + ((size_t)t * NNEWS + n) * C_IN + lane * 4;
        atomicAdd(dst + 0, v.x); atomicAdd(dst + 1, v.y);
        atomicAdd(dst + 2, v.z); atomicAdd(dst + 3, v.w);
    }
    grid_sync();
    // ==== I2: fill CSR edge lists; normalize center in place ====
    for (int task = gtid; task < SEQ_L * NEDGE; task += nthr) {
        int t = task / NEDGE, e = task - t * NEDGE;
        const int* news = ei + (size_t)t * 2 * NEDGE;
        int n = news[e], s = news[NEDGE + e];
        int slot = atomicAdd(&g_cur[t * NSTOCK + s], 1);
        g_csr_n[(size_t)t * NEDGE + slot] = n;
    }
    for (size_t i = gtid; i < (size_t)NNE * C_IN; i += nthr)
        g_acc_news_all[i] *= g_inv_news_all[i >> 7];
    grid_sync();
    // ==== I3: bulk GEMMs gi_li + gi_c (K=128) ====
    for (int tile = blockIdx.x; tile < BI3_TOT; tile += gridDim.x) {
        if (tile < 24000) {
            int mt = tile / 6, nt = tile % 6;
            gemm_f32A_h16(inputs, C_IN, g_Whi + OW_IH_LI, g_Wlo + OW_IH_LI, C_IN,
                          bih_li, g_gi_li_all, C_IN, NSTE, mt * 128, nt * 128, (uint16_t*)dsm);
        } else {
            int idx = tile - 24000, mt = idx / 6, nt = idx % 6;
            gemm_f32A_h16(g_acc_news_all, C_IN, g_Whi + OW_IH_C, g_Wlo + OW_IH_C, C_IN,
                          bih_c, g_gi_c_all, C_IN, NNE, mt * 128, nt * 128, (uint16_t*)dsm);
        }
    }
    grid_sync();
    // ==== I4: bulk scatter center -> stocks ====
    for (int task = gwarp; task < SEQ_L * NEDGE; task += nwarp) {
        int t = task / NEDGE, e = task - t * NEDGE;
        const int* news = ei + (size_t)t * 2 * NEDGE;
        int n = news[e], s = news[NEDGE + e];
        float4 v = ((const float4*)(g_acc_news_all + ((size_t)t * NNEWS + n) * C_IN))[lane];
        float* dst = g_accmc_all + ((size_t)t * NSTOCK + s) * C_IN + lane * 4;
        atomicAdd(dst + 0, v.x); atomicAdd(dst + 1, v.y);
        atomicAdd(dst + 2, v.z); atomicAdd(dst + 3, v.w);
    }
    grid_sync();
    // ==== I5: normalize mcenter in place; m_out center cols (t=63) ====
    for (size_t i = gtid; i < (size_t)NSTE * C_IN; i += nthr) {
        float v = g_accmc_all[i] * g_inv_stock_all[i >> 7];
        g_accmc_all[i] = v;
        if (i >= (size_t)63 * NSTOCK * C_IN) {
            size_t r = i - (size_t)63 * NSTOCK * C_IN;
            m_out[(r >> 7) * CM + (r & 127)] = v;
        }
    }
    grid_sync();
    // ==== I6: bulk GEMM gi_lh1 (K=128) ====
    for (int tile = blockIdx.x; tile < 24000; tile += gridDim.x) {
        int mt = tile / 6, nt = tile % 6;
        gemm_f32A_h16(g_accmc_all, C_IN, g_Whi + OW_IH_LH, g_Wlo + OW_IH_LH, CM,
                      bih_lh, g_gi_lh1_all, C_IN, NSTE, mt * 128, nt * 128, (uint16_t*)dsm);
    }
    grid_sync();

    // ==== sequential recurrence: K=256 cp.async GEMMs, CSR gather ====
    for (int t = 0; t < SEQ_L; t++) {
        // ---- A: gh_li, gh_lh, gh_n ----
        for (int tile = blockIdx.x; tile < PA_TOT; tile += gridDim.x) {
            if (tile < ST_T) {
                int mt = tile / 6, nt = tile % 6;
                gemm_step(g_p_hi, g_p_lo, HID, g_Whi + OW_HH_LI, g_Wlo + OW_HH_LI, HID,
                          bhh_li, nullptr, g_gh_li, HID, NSTOCK, mt * 128, nt * 128, dsm);
            } else if (tile < 2 * ST_T) {
                int idx = tile - ST_T, mt = idx / 6, nt = idx % 6;
                gemm_step(g_h_hi, g_h_lo, HID, g_Whi + OW_HH_LH, g_Wlo + OW_HH_LH, HID,
                          bhh_lh, nullptr, g_gh_lh, HID, NSTOCK, mt * 128, nt * 128, dsm);
            } else {
                int idx = tile - 2 * ST_T, mt = idx / 6, nt = idx % 6;
                gemm_step(g_mc_hi, g_mc_lo, HID, g_Whi + OW_HH_C, g_Wlo + OW_HH_C, HID,
                          bhh_c, nullptr, g_gh_n, HID, NNEWS, mt * 128, nt * 128, dsm);
            }
        }
        grid_sync();

        // ---- B: gates m_c + h_input ----
        gate_hh(g_gi_c_all + (size_t)t * NNEWS * G3, g_gh_n,
                g_mc, g_mc_hi, g_mc_lo, NNEWS, gtid, nthr);
        gate_hh(g_gi_li_all + (size_t)t * NSTOCK * G3, g_gh_li,
                hi_out, g_p_hi, g_p_lo, NSTOCK, gtid, nthr);
        grid_sync();

        // ---- C': CSR gather m_c (news -> stocks) + normalize + split ----
        for (int s = gwarp; s < NSTOCK; s += nwarp) {
            int base = t * NSTOCK + s;
            int off = g_csr_off[base], deg = g_deg[base];
            const int* en = g_csr_n + (size_t)t * NEDGE;
            float4 a0 = make_float4(0.f, 0.f, 0.f, 0.f);
            float4 a1 = make_float4(0.f, 0.f, 0.f, 0.f);
            for (int e = off; e < off + deg; e++) {
                int n = en[e];
                const float4* mp = (const float4*)(g_mc + (size_t)n * HID);
                float4 v0 = mp[lane], v1 = mp[lane + 32];
                a0.x += v0.x; a0.y += v0.y; a0.z += v0.z; a0.w += v0.w;
                a1.x += v1.x; a1.y += v1.y; a1.z += v1.z; a1.w += v1.w;
            }
            float inv = g_inv_stock_all[base];
            float vs[8] = {a0.x * inv, a0.y * inv, a0.z * inv, a0.w * inv,
                           a1.x * inv, a1.y * inv, a1.z * inv, a1.w * inv};
            int c0 = s * HID + lane * 4;
#pragma unroll
            for (int q = 0; q < 4; q++) {
                bsplit(vs[q], g_amc_hi + c0 + q, g_amc_lo + c0 + q);
                bsplit(vs[4 + q], g_amc_hi + c0 + 128 + q, g_amc_lo + c0 + 128 + q);
            }
            if (t == SEQ_L - 1) {
                float* mo = m_out + (size_t)s * CM + C_IN + lane * 4;
#pragma unroll
                for (int q = 0; q < 4; q++) { mo[q] = vs[q]; mo[128 + q] = vs[4 + q]; }
            }
        }
        grid_sync();

        // ---- E: gis = gi_lh1[t] + amc @ Wih_lh[:, 128:]^T ----
        for (int tile = blockIdx.x; tile < ST_T; tile += gridDim.x) {
            int mt = tile / 6, nt = tile % 6;
            gemm_step(g_amc_hi, g_amc_lo, HID,
                      g_Whi + OW_IH_LH + C_IN, g_Wlo + OW_IH_LH + C_IN, CM,
                      nullptr, g_gi_lh1_all + (size_t)t * NSTOCK * G3,
                      g_gis, HID, NSTOCK, mt * 128, nt * 128, dsm);
        }
        grid_sync();

        // ---- F: gate h ----
        gate_hh(g_gis, g_gh_lh, h_out, g_h_hi, g_h_lo, NSTOCK, gtid, nthr);
        grid_sync();
    }
}

// ---------------- launch -----------------------------------------------------
extern "C" void kernel_launch(void* const* d_in, const int* in_sizes, int n_in,
                              void* d_out, int out_size) {
    const float* inputs   = (const float*)d_in[0];
    const int*   ei       = (const int*)d_in[1];
    const float* h_start  = (const float*)d_in[2];
    const float* hi_start = (const float*)d_in[3];
    const float* mc_start = (const float*)d_in[4];
    const float* Wih_c  = (const float*)d_in[5];
    const float* Whh_c  = (const float*)d_in[6];
    const float* bih_c  = (const float*)d_in[7];
    const float* bhh_c  = (const float*)d_in[8];
    const float* Wih_lh = (const float*)d_in[9];
    const float* Whh_lh = (const float*)d_in[10];
    const float* bih_lh = (const float*)d_in[11];
    const float* bhh_lh = (const float*)d_in[12];
    const float* Wih_li = (const float*)d_in[13];
    const float* Whh_li = (const float*)d_in[14];
    const float* bih_li = (const float*)d_in[15];
    const float* bhh_li = (const float*)d_in[16];

    float* out    = (float*)d_out;
    float* m_out  = out;
    float* h_out  = out + (size_t)NSTOCK * CM;
    float* hi_out = h_out + (size_t)NSTOCK * HID;

    cudaFuncSetAttribute(mega_kernel, cudaFuncAttributeMaxDynamicSharedMemorySize, SMEM_BYTES);

    int dev = 0, nsm = 0, occ = 0;
    cudaGetDevice(&dev);
    cudaDeviceGetAttribute(&nsm, cudaDevAttrMultiProcessorCount, dev);
    cudaOccupancyMaxActiveBlocksPerMultiprocessor(&occ, mega_kernel, NT, SMEM_BYTES);
    if (occ < 1) occ = 1;
    int nblk = nsm * occ;

    unsigned* bar = nullptr;
    cudaGetSymbolAddress((void**)&bar, g_bar_count);
    cudaMemsetAsync(bar, 0, sizeof(unsigned));

    mega_kernel<<<nblk, NT, SMEM_BYTES>>>(inputs, ei, h_start, hi_start, mc_start,
                                          Wih_c, Whh_c, bih_c, bhh_c,
                                          Wih_lh, Whh_lh, bih_lh, bhh_lh,
                                          Wih_li, Whh_li, bih_li, bhh_li,
                                          m_out, h_out, hi_out);
}

// round 11
// speedup vs baseline: 2.7049x; 1.0055x over previous
#include <cuda_runtime.h>
#include <cuda_bf16.h>
#include <cuda_fp16.h>
#include <math.h>
#include <stdint.h>

#define SEQ_L 64
#define NSTOCK 8000
#define NNEWS 1600
#define C_IN 128
#define HID 256
#define NEDGE 32000
#define G3 768
#define CM 384
#define NT 256
#define NSTE 512000
#define NNE  102400

// per-step cp.async GEMM: BK=32 double-buffered
#define BKP32 40
#define SA_ELEM (128 * BKP32)
#define SA_SZ (SA_ELEM * 2)            // 10240 B
#define STAGE_SZ (4 * SA_SZ)           // 40960 B
#define SMEM_BYTES (2 * STAGE_SZ)      // 81920 B
// bulk single-buffer GEMM: BK=64
#define BKP 72

// ---- weight bf16 hi/lo offsets (elements) -----------------------------------
#define OW_IH_LI 0
#define OW_HH_LI 98304
#define OW_IH_C  294912
#define OW_HH_C  393216
#define OW_IH_LH 589824
#define OW_HH_LH 884736
#define W_TOTAL  1081344

// ---------------- static device scratch (~2.1GB, linker-safe) ----------------
__device__ __align__(16) float g_acc_news_all[(size_t)NNE * C_IN];
__device__ __align__(16) float g_accmc_all[(size_t)NSTE * C_IN];
__device__ __align__(16) __half g_gi_li_all[(size_t)NSTE * G3];
__device__ __align__(16) __half g_gi_c_all[(size_t)NNE * G3];
__device__ __align__(16) __half g_gi_lh1_all[(size_t)NSTE * G3];
__device__ float g_inv_news_all[NNE];
__device__ float g_inv_stock_all[NSTE];
// CSR (stock-destination sorted edges, per t)
__device__ int g_deg[NSTE];
__device__ int g_csr_off[NSTE];
__device__ int g_cur[NSTE];
__device__ int g_csr_n[SEQ_L * NEDGE];
__device__ int g_tot[SEQ_L];
// per-step state
__device__ __align__(16) float g_mc[NNEWS * HID];
__device__ __align__(16) __nv_bfloat16 g_mc_hi[NNEWS * HID];
__device__ __align__(16) __nv_bfloat16 g_mc_lo[NNEWS * HID];
__device__ __align__(16) __nv_bfloat16 g_h_hi[NSTOCK * HID];
__device__ __align__(16) __nv_bfloat16 g_h_lo[NSTOCK * HID];
__device__ __align__(16) __nv_bfloat16 g_p_hi[NSTOCK * HID];
__device__ __align__(16) __nv_bfloat16 g_p_lo[NSTOCK * HID];
__device__ __align__(16) __nv_bfloat16 g_amc_hi[NSTOCK * HID];
__device__ __align__(16) __nv_bfloat16 g_amc_lo[NSTOCK * HID];
__device__ __align__(16) __half g_gh_li[NSTOCK * G3];
__device__ __align__(16) __half g_gh_lh[NSTOCK * G3];
__device__ __align__(16) __half g_gh_n[NNEWS * G3];
__device__ __align__(16) __half g_gis[NSTOCK * G3];
__device__ __align__(16) __nv_bfloat16 g_Whi[W_TOTAL];
__device__ __align__(16) __nv_bfloat16 g_Wlo[W_TOTAL];
__device__ unsigned g_bar_count = 0;

// ---------------- software grid barrier (monotonic) --------------------------
__device__ __forceinline__ void grid_sync() {
    __syncthreads();
    __threadfence();
    if (threadIdx.x == 0) {
        unsigned G = gridDim.x;
        unsigned arrival = atomicAdd(&g_bar_count, 1u) + 1u;
        unsigned target = ((arrival + G - 1u) / G) * G;
        volatile unsigned* vc = &g_bar_count;
        while (*vc < target) { __nanosleep(32); }
    }
    __syncthreads();
    __threadfence();
}

__device__ __forceinline__ void bsplit(float v, __nv_bfloat16* hp, __nv_bfloat16* lp) {
    __nv_bfloat16 h = __float2bfloat16(v);
    *hp = h;
    *lp = __float2bfloat16(v - __bfloat162float(h));
}

__device__ __forceinline__ void mma_bf16(float* c, const uint32_t* a, const uint32_t* b) {
    asm volatile("mma.sync.aligned.m16n8k16.row.col.f32.bf16.bf16.f32 "
                 "{%0,%1,%2,%3}, {%4,%5,%6,%7}, {%8,%9}, {%0,%1,%2,%3};"
                 : "+f"(c[0]), "+f"(c[1]), "+f"(c[2]), "+f"(c[3])
                 : "r"(a[0]), "r"(a[1]), "r"(a[2]), "r"(a[3]), "r"(b[0]), "r"(b[1]));
}

__device__ __forceinline__ void ldsm_x4(uint32_t addr, uint32_t* r) {
    asm volatile("ldmatrix.sync.aligned.m8n8.x4.shared.b16 {%0,%1,%2,%3}, [%4];"
                 : "=r"(r[0]), "=r"(r[1]), "=r"(r[2]), "=r"(r[3]) : "r"(addr));
}
__device__ __forceinline__ void ldsm_x2(uint32_t addr, uint32_t* r) {
    asm volatile("ldmatrix.sync.aligned.m8n8.x2.shared.b16 {%0,%1}, [%2];"
                 : "=r"(r[0]), "=r"(r[1]) : "r"(addr));
}

struct Acc { float v[4][4][4]; };

// ---------------- ldmatrix fragment compute over one staged chunk -------------
// sXh/sXl: smem byte addresses of the 4 operand arrays (row stride KP elems).
// aoff/boff: precomputed lane-dependent byte offsets (include mbase/nbase).
template <int BK, int KP>
__device__ __forceinline__ void mma_chunk_l(uint32_t sAh, uint32_t sAl,
                                            uint32_t sBh, uint32_t sBl,
                                            uint32_t aoff, uint32_t boff, Acc& A) {
#pragma unroll
    for (int kk = 0; kk < BK; kk += 16) {
        uint32_t ah[4][4], al[4][4];
#pragma unroll
        for (int mf = 0; mf < 4; mf++) {
            uint32_t o = aoff + (mf * 16 * KP + kk) * 2;
            ldsm_x4(sAh + o, ah[mf]);
            ldsm_x4(sAl + o, al[mf]);
        }
#pragma unroll
        for (int nf = 0; nf < 4; nf++) {
            uint32_t o = boff + (nf * 8 * KP + kk) * 2;
            uint32_t bh[2], bl[2];
            ldsm_x2(sBh + o, bh);
            ldsm_x2(sBl + o, bl);
#pragma unroll
            for (int mf = 0; mf < 4; mf++) {
                mma_bf16(A.v[mf][nf], ah[mf], bh);
                mma_bf16(A.v[mf][nf], ah[mf], bl);
                mma_bf16(A.v[mf][nf], al[mf], bh);
            }
        }
    }
}

// lane-dependent ldmatrix offsets (bytes) for row-major [row][k] smem tiles
template <int KP>
__device__ __forceinline__ uint32_t mk_aoff(int mbase, int lane) {
    int arow = (lane & 7) + ((lane >> 3) & 1) * 8;
    int acol = (lane >> 4) * 8;
    return (uint32_t)(((mbase + arow) * KP + acol) * 2);
}
template <int KP>
__device__ __forceinline__ uint32_t mk_boff(int nbase, int lane) {
    int brow = lane & 7;
    int bcol = ((lane >> 3) & 1) * 8;      // lanes >=16 ignored by x2
    return (uint32_t)(((nbase + brow) * KP + bcol) * 2);
}

// ---------------- per-step GEMM: cp.async 2-stage, ldmatrix, fp16 out --------
__device__ void gemm_step(const __nv_bfloat16* __restrict__ Ah,
                          const __nv_bfloat16* __restrict__ Al, int lda,
                          const __nv_bfloat16* __restrict__ Wh,
                          const __nv_bfloat16* __restrict__ Wl, int ldw,
                          const float* __restrict__ bias,
                          const __half* __restrict__ pre,
                          __half* __restrict__ Cc, int K, int M, int m0, int n0,
                          char* dsm) {
    const int tid = threadIdx.x;
    const int w = tid >> 5, lane = tid & 31;
    const int g = lane >> 2, t4 = lane & 3;
    const int mbase = (w >> 2) * 64, nbase = (w & 3) * 32;
    const uint32_t sb0 = (uint32_t)__cvta_generic_to_shared(dsm);
    const uint32_t aoff = mk_aoff<BKP32>(mbase, lane);
    const uint32_t boff = mk_boff<BKP32>(nbase, lane);
    Acc acc;
#pragma unroll
    for (int i = 0; i < 4; i++)
#pragma unroll
        for (int j = 0; j < 4; j++)
#pragma unroll
            for (int q = 0; q < 4; q++) acc.v[i][j][q] = 0.0f;

    const int NC = K >> 5;
    auto stage = [&](int c) {
        uint32_t sb = sb0 + (c & 1) * STAGE_SZ;
        int kt = c << 5;
        for (int it = tid; it < 512; it += NT) {
            int row = it >> 2;
            int c8 = (it & 3) << 3;
            int mm = m0 + row; if (mm >= M) mm = M - 1;
            const void* gah = Ah + (size_t)mm * lda + kt + c8;
            const void* gal = Al + (size_t)mm * lda + kt + c8;
            const void* gbh = Wh + (size_t)(n0 + row) * ldw + kt + c8;
            const void* gbl = Wl + (size_t)(n0 + row) * ldw + kt + c8;
            uint32_t so = sb + (row * BKP32 + c8) * 2;
            asm volatile("cp.async.ca.shared.global [%0], [%1], 16;" :: "r"(so), "l"(gah));
            asm volatile("cp.async.ca.shared.global [%0], [%1], 16;" :: "r"(so + SA_SZ), "l"(gal));
            asm volatile("cp.async.ca.shared.global [%0], [%1], 16;" :: "r"(so + 2 * SA_SZ), "l"(gbh));
            asm volatile("cp.async.ca.shared.global [%0], [%1], 16;" :: "r"(so + 3 * SA_SZ), "l"(gbl));
        }
        asm volatile("cp.async.commit_group;");
    };

    stage(0);
    for (int c = 0; c < NC; c++) {
        if (c + 1 < NC) {
            stage(c + 1);
            asm volatile("cp.async.wait_group 1;");
        } else {
            asm volatile("cp.async.wait_group 0;");
        }
        __syncthreads();
        uint32_t st = sb0 + (c & 1) * STAGE_SZ;
        mma_chunk_l<32, BKP32>(st, st + SA_SZ, st + 2 * SA_SZ, st + 3 * SA_SZ,
                               aoff, boff, acc);
        __syncthreads();
    }
#pragma unroll
    for (int mf = 0; mf < 4; mf++) {
#pragma unroll
        for (int nf = 0; nf < 4; nf++) {
            int m = m0 + mbase + mf * 16 + g;
            int n = n0 + nbase + nf * 8 + 2 * t4;
            if (pre == nullptr) {
                float b0 = bias[n], b1 = bias[n + 1];
                if (m < M)
                    *(__half2*)(Cc + (size_t)m * G3 + n) =
                        __floats2half2_rn(acc.v[mf][nf][0] + b0, acc.v[mf][nf][1] + b1);
                if (m + 8 < M)
                    *(__half2*)(Cc + (size_t)(m + 8) * G3 + n) =
                        __floats2half2_rn(acc.v[mf][nf][2] + b0, acc.v[mf][nf][3] + b1);
            } else {
                if (m < M) {
                    float2 p = __half22float2(*(const __half2*)(pre + (size_t)m * G3 + n));
                    *(__half2*)(Cc + (size_t)m * G3 + n) =
                        __floats2half2_rn(acc.v[mf][nf][0] + p.x, acc.v[mf][nf][1] + p.y);
                }
                if (m + 8 < M) {
                    float2 p = __half22float2(*(const __half2*)(pre + (size_t)(m + 8) * G3 + n));
                    *(__half2*)(Cc + (size_t)(m + 8) * G3 + n) =
                        __floats2half2_rn(acc.v[mf][nf][2] + p.x, acc.v[mf][nf][3] + p.y);
                }
            }
        }
    }
    __syncthreads();
}

// ---------------- bulk GEMM: fp32 A split on the fly, ldmatrix, fp16 out -----
__device__ void gemm_f32A_h16(const float* __restrict__ A, int lda,
                              const __nv_bfloat16* __restrict__ Wh,
                              const __nv_bfloat16* __restrict__ Wl, int ldw,
                              const float* __restrict__ bias,
                              __half* __restrict__ Cc, int K, int M, int m0, int n0,
                              uint16_t* sm) {
    uint16_t* sAh = sm;
    uint16_t* sAl = sm + 128 * BKP;
    uint16_t* sBh = sm + 2 * 128 * BKP;
    uint16_t* sBl = sm + 3 * 128 * BKP;
    const int tid = threadIdx.x;
    const int w = tid >> 5, lane = tid & 31;
    const int g = lane >> 2, t4 = lane & 3;
    const int mbase = (w >> 2) * 64, nbase = (w & 3) * 32;
    const uint32_t sb = (uint32_t)__cvta_generic_to_shared(sm);
    const uint32_t aoff = mk_aoff<BKP>(mbase, lane);
    const uint32_t boff = mk_boff<BKP>(nbase, lane);
    const uint32_t asz = 128 * BKP * 2;
    Acc acc;
#pragma unroll
    for (int i = 0; i < 4; i++)
#pragma unroll
        for (int j = 0; j < 4; j++)
#pragma unroll
            for (int q = 0; q < 4; q++) acc.v[i][j][q] = 0.0f;

    for (int kt = 0; kt < K; kt += 64) {
        for (int it = tid; it < 1024; it += NT) {
            int row = it >> 3;
            int c8 = (it & 7) << 3;
            int mm = m0 + row; if (mm >= M) mm = M - 1;
            const float* ap = A + (size_t)mm * lda + kt + c8;
            float4 v0 = *(const float4*)ap;
            float4 v1 = *(const float4*)(ap + 4);
            float f[8] = {v0.x, v0.y, v0.z, v0.w, v1.x, v1.y, v1.z, v1.w};
            int so = row * BKP + c8;
#pragma unroll
            for (int q = 0; q < 8; q++) {
                __nv_bfloat16 hh = __float2bfloat16(f[q]);
                sAh[so + q] = __bfloat16_as_ushort(hh);
                sAl[so + q] = __bfloat16_as_ushort(
                    __float2bfloat16(f[q] - __bfloat162float(hh)));
            }
            size_t bo = (size_t)(n0 + row) * ldw + kt + c8;
            *(uint4*)(sBh + so) = *(const uint4*)(Wh + bo);
            *(uint4*)(sBl + so) = *(const uint4*)(Wl + bo);
        }
        __syncthreads();
        mma_chunk_l<64, BKP>(sb, sb + asz, sb + 2 * asz, sb + 3 * asz, aoff, boff, acc);
        __syncthreads();
    }
#pragma unroll
    for (int mf = 0; mf < 4; mf++) {
#pragma unroll
        for (int nf = 0; nf < 4; nf++) {
            int m = m0 + mbase + mf * 16 + g;
            int n = n0 + nbase + nf * 8 + 2 * t4;
            float b0 = bias[n], b1 = bias[n + 1];
            if (m < M)
                *(__half2*)(Cc + (size_t)m * G3 + n) =
                    __floats2half2_rn(acc.v[mf][nf][0] + b0, acc.v[mf][nf][1] + b1);
            if (m + 8 < M)
                *(__half2*)(Cc + (size_t)(m + 8) * G3 + n) =
                    __floats2half2_rn(acc.v[mf][nf][2] + b0, acc.v[mf][nf][3] + b1);
        }
    }
    __syncthreads();
}

// ---------------- GRU gate (fp16 gi + fp16 gh) -------------------------------
__device__ __forceinline__ void gate_hh(const __half* __restrict__ gi,
                                        const __half* __restrict__ gh,
                                        float* __restrict__ h,
                                        __nv_bfloat16* __restrict__ hhi,
                                        __nv_bfloat16* __restrict__ hlo,
                                        int M, int gtid, int nthr) {
    int total = M * HID;
    for (int idx = gtid; idx < total; idx += nthr) {
        int m = idx >> 8;
        int j = idx & 255;
        const __half* gim = gi + (size_t)m * G3;
        const __half* ghm = gh + (size_t)m * G3;
        float r = 1.0f / (1.0f + __expf(-(__half2float(gim[j]) + __half2float(ghm[j]))));
        float z = 1.0f / (1.0f + __expf(-(__half2float(gim[HID + j]) + __half2float(ghm[HID + j]))));
        float n = tanhf(__half2float(gim[2 * HID + j]) + r * __half2float(ghm[2 * HID + j]));
        float v = (1.0f - z) * n + z * h[idx];
        h[idx] = v;
        bsplit(v, hhi + idx, hlo + idx);
    }
}

__device__ __forceinline__ void convW(const float* __restrict__ W, int off, int n,
                                      int gtid, int nthr) {
    for (int i = gtid; i < n; i += nthr) {
        float w = W[i];
        __nv_bfloat16 h = __float2bfloat16(w);
        g_Whi[off + i] = h;
        g_Wlo[off + i] = __float2bfloat16(w - __bfloat162float(h));
    }
}

#define ST_T 378
#define NW_T 78
#define PA_TOT (ST_T * 2 + NW_T)
#define BI3_TOT (24000 + 4800)

// ---------------- the persistent mega-kernel ---------------------------------
__global__ __launch_bounds__(NT, 2)
void mega_kernel(const float* __restrict__ inputs, const int* __restrict__ ei,
                 const float* __restrict__ h_start, const float* __restrict__ hi_start,
                 const float* __restrict__ mc_start,
                 const float* __restrict__ Wih_c,  const float* __restrict__ Whh_c,
                 const float* __restrict__ bih_c,  const float* __restrict__ bhh_c,
                 const float* __restrict__ Wih_lh, const float* __restrict__ Whh_lh,
                 const float* __restrict__ bih_lh, const float* __restrict__ bhh_lh,
                 const float* __restrict__ Wih_li, const float* __restrict__ Whh_li,
                 const float* __restrict__ bih_li, const float* __restrict__ bhh_li,
                 float* __restrict__ m_out, float* __restrict__ h_out,
                 float* __restrict__ hi_out) {
    extern __shared__ char dsm[];

    const int gtid = blockIdx.x * NT + threadIdx.x;
    const int nthr = gridDim.x * NT;
    const int gwarp = gtid >> 5;
    const int lane = threadIdx.x & 31;
    const int nwarp = nthr >> 5;

    // ==== I0: init states, weights, zero counters ====
    for (int i = gtid; i < NSTOCK * HID; i += nthr) {
        float hv = h_start[i & 255], pv = hi_start[i & 255];
        h_out[i] = hv; hi_out[i] = pv;
        bsplit(hv, g_h_hi + i, g_h_lo + i);
        bsplit(pv, g_p_hi + i, g_p_lo + i);
    }
    for (int i = gtid; i < NNEWS * HID; i += nthr) {
        float v = mc_start[i & 255];
        g_mc[i] = v;
        bsplit(v, g_mc_hi + i, g_mc_lo + i);
    }
    convW(Wih_li, OW_IH_LI, G3 * C_IN, gtid, nthr);
    convW(Whh_li, OW_HH_LI, G3 * HID,  gtid, nthr);
    convW(Wih_c,  OW_IH_C,  G3 * C_IN, gtid, nthr);
    convW(Whh_c,  OW_HH_C,  G3 * HID,  gtid, nthr);
    convW(Wih_lh, OW_IH_LH, G3 * CM,   gtid, nthr);
    convW(Whh_lh, OW_HH_LH, G3 * HID,  gtid, nthr);
    for (int i = gtid; i < NNE; i += nthr) g_inv_news_all[i] = 0.0f;
    for (int i = gtid; i < NSTE; i += nthr) { g_deg[i] = 0; }
    for (int i = gtid; i < SEQ_L; i += nthr) g_tot[i] = 0;
    for (size_t i = gtid; i < (size_t)NNE * C_IN; i += nthr) g_acc_news_all[i] = 0.0f;
    for (size_t i = gtid; i < (size_t)NSTE * C_IN; i += nthr) g_accmc_all[i] = 0.0f;
    grid_sync();
    // ==== I0b: degree counts ====
    for (int task = gtid; task < SEQ_L * NEDGE; task += nthr) {
        int t = task / NEDGE, e = task - t * NEDGE;
        const int* news = ei + (size_t)t * 2 * NEDGE;
        atomicAdd(&g_inv_news_all[t * NNEWS + news[e]], 1.0f);
        atomicAdd(&g_deg[t * NSTOCK + news[NEDGE + e]], 1);
    }
    grid_sync();
    // ==== I1: invert counts; CSR offsets; bulk scatter x -> news ====
    for (int i = gtid; i < NNE; i += nthr)
        g_inv_news_all[i] = 1.0f / fmaxf(g_inv_news_all[i], 1.0f);
    for (int i = gtid; i < NSTE; i += nthr) {
        int d = g_deg[i];
        g_inv_stock_all[i] = 1.0f / fmaxf((float)d, 1.0f);
        int off = atomicAdd(&g_tot[i / NSTOCK], d);
        g_csr_off[i] = off;
        g_cur[i] = off;
    }
    for (int task = gwarp; task < SEQ_L * NEDGE; task += nwarp) {
        int t = task / NEDGE, e = task - t * NEDGE;
        const int* news = ei + (size_t)t * 2 * NEDGE;
        int n = news[e], s = news[NEDGE + e];
        float4 v = ((const float4*)(inputs + ((size_t)t * NSTOCK + s) * C_IN))[lane];
        float* dst = g_acc_news_all + ((size_t)t * NNEWS + n) * C_IN + lane * 4;
        atomicAdd(dst + 0, v.x); atomicAdd(dst + 1, v.y);
        atomicAdd(dst + 2, v.z); atomicAdd(dst + 3, v.w);
    }
    grid_sync();
    // ==== I2: fill CSR edge lists; normalize center in place ====
    for (int task = gtid; task < SEQ_L * NEDGE; task += nthr) {
        int t = task / NEDGE, e = task - t * NEDGE;
        const int* news = ei + (size_t)t * 2 * NEDGE;
        int n = news[e], s = news[NEDGE + e];
        int slot = atomicAdd(&g_cur[t * NSTOCK + s], 1);
        g_csr_n[(size_t)t * NEDGE + slot] = n;
    }
    for (size_t i = gtid; i < (size_t)NNE * C_IN; i += nthr)
        g_acc_news_all[i] *= g_inv_news_all[i >> 7];
    grid_sync();
    // ==== I3: bulk GEMMs gi_li + gi_c (K=128) ====
    for (int tile = blockIdx.x; tile < BI3_TOT; tile += gridDim.x) {
        if (tile < 24000) {
            int mt = tile / 6, nt = tile % 6;
            gemm_f32A_h16(inputs, C_IN, g_Whi + OW_IH_LI, g_Wlo + OW_IH_LI, C_IN,
                          bih_li, g_gi_li_all, C_IN, NSTE, mt * 128, nt * 128, (uint16_t*)dsm);
        } else {
            int idx = tile - 24000, mt = idx / 6, nt = idx % 6;
            gemm_f32A_h16(g_acc_news_all, C_IN, g_Whi + OW_IH_C, g_Wlo + OW_IH_C, C_IN,
                          bih_c, g_gi_c_all, C_IN, NNE, mt * 128, nt * 128, (uint16_t*)dsm);
        }
    }
    grid_sync();
    // ==== I4: bulk scatter center -> stocks ====
    for (int task = gwarp; task < SEQ_L * NEDGE; task += nwarp) {
        int t = task / NEDGE, e = task - t * NEDGE;
        const int* news = ei + (size_t)t * 2 * NEDGE;
        int n = news[e], s = news[NEDGE + e];
        float4 v = ((const float4*)(g_acc_news_all + ((size_t)t * NNEWS + n) * C_IN))[lane];
        float* dst = g_accmc_all + ((size_t)t * NSTOCK + s) * C_IN + lane * 4;
        atomicAdd(dst + 0, v.x); atomicAdd(dst + 1, v.y);
        atomicAdd(dst + 2, v.z); atomicAdd(dst + 3, v.w);
    }
    grid_sync();
    // ==== I5: normalize mcenter in place; m_out center cols (t=63) ====
    for (size_t i = gtid; i < (size_t)NSTE * C_IN; i += nthr) {
        float v = g_accmc_all[i] * g_inv_stock_all[i >> 7];
        g_accmc_all[i] = v;
        if (i >= (size_t)63 * NSTOCK * C_IN) {
            size_t r = i - (size_t)63 * NSTOCK * C_IN;
            m_out[(r >> 7) * CM + (r & 127)] = v;
        }
    }
    grid_sync();
    // ==== I6: bulk GEMM gi_lh1 (K=128) ====
    for (int tile = blockIdx.x; tile < 24000; tile += gridDim.x) {
        int mt = tile / 6, nt = tile % 6;
        gemm_f32A_h16(g_accmc_all, C_IN, g_Whi + OW_IH_LH, g_Wlo + OW_IH_LH, CM,
                      bih_lh, g_gi_lh1_all, C_IN, NSTE, mt * 128, nt * 128, (uint16_t*)dsm);
    }
    grid_sync();

    // ==== sequential recurrence: K=256 cp.async+ldmatrix GEMMs, CSR gather ====
    for (int t = 0; t < SEQ_L; t++) {
        // ---- A: gh_li, gh_lh, gh_n ----
        for (int tile = blockIdx.x; tile < PA_TOT; tile += gridDim.x) {
            if (tile < ST_T) {
                int mt = tile / 6, nt = tile % 6;
                gemm_step(g_p_hi, g_p_lo, HID, g_Whi + OW_HH_LI, g_Wlo + OW_HH_LI, HID,
                          bhh_li, nullptr, g_gh_li, HID, NSTOCK, mt * 128, nt * 128, dsm);
            } else if (tile < 2 * ST_T) {
                int idx = tile - ST_T, mt = idx / 6, nt = idx % 6;
                gemm_step(g_h_hi, g_h_lo, HID, g_Whi + OW_HH_LH, g_Wlo + OW_HH_LH, HID,
                          bhh_lh, nullptr, g_gh_lh, HID, NSTOCK, mt * 128, nt * 128, dsm);
            } else {
                int idx = tile - 2 * ST_T, mt = idx / 6, nt = idx % 6;
                gemm_step(g_mc_hi, g_mc_lo, HID, g_Whi + OW_HH_C, g_Wlo + OW_HH_C, HID,
                          bhh_c, nullptr, g_gh_n, HID, NNEWS, mt * 128, nt * 128, dsm);
            }
        }
        grid_sync();

        // ---- B: gates m_c + h_input ----
        gate_hh(g_gi_c_all + (size_t)t * NNEWS * G3, g_gh_n,
                g_mc, g_mc_hi, g_mc_lo, NNEWS, gtid, nthr);
        gate_hh(g_gi_li_all + (size_t)t * NSTOCK * G3, g_gh_li,
                hi_out, g_p_hi, g_p_lo, NSTOCK, gtid, nthr);
        grid_sync();

        // ---- C': CSR gather m_c (news -> stocks) + normalize + split ----
        for (int s = gwarp; s < NSTOCK; s += nwarp) {
            int base = t * NSTOCK + s;
            int off = g_csr_off[base], deg = g_deg[base];
            const int* en = g_csr_n + (size_t)t * NEDGE;
            float4 a0 = make_float4(0.f, 0.f, 0.f, 0.f);
            float4 a1 = make_float4(0.f, 0.f, 0.f, 0.f);
            for (int e = off; e < off + deg; e++) {
                int n = en[e];
                const float4* mp = (const float4*)(g_mc + (size_t)n * HID);
                float4 v0 = mp[lane], v1 = mp[lane + 32];
                a0.x += v0.x; a0.y += v0.y; a0.z += v0.z; a0.w += v0.w;
                a1.x += v1.x; a1.y += v1.y; a1.z += v1.z; a1.w += v1.w;
            }
            float inv = g_inv_stock_all[base];
            float vs[8] = {a0.x * inv, a0.y * inv, a0.z * inv, a0.w * inv,
                           a1.x * inv, a1.y * inv, a1.z * inv, a1.w * inv};
            int c0 = s * HID + lane * 4;
#pragma unroll
            for (int q = 0; q < 4; q++) {
                bsplit(vs[q], g_amc_hi + c0 + q, g_amc_lo + c0 + q);
                bsplit(vs[4 + q], g_amc_hi + c0 + 128 + q, g_amc_lo + c0 + 128 + q);
            }
            if (t == SEQ_L - 1) {
                float* mo = m_out + (size_t)s * CM + C_IN + lane * 4;
#pragma unroll
                for (int q = 0; q < 4; q++) { mo[q] = vs[q]; mo[128 + q] = vs[4 + q]; }
            }
        }
        grid_sync();

        // ---- E: gis = gi_lh1[t] + amc @ Wih_lh[:, 128:]^T ----
        for (int tile = blockIdx.x; tile < ST_T; tile += gridDim.x) {
            int mt = tile / 6, nt = tile % 6;
            gemm_step(g_amc_hi, g_amc_lo, HID,
                      g_Whi + OW_IH_LH + C_IN, g_Wlo + OW_IH_LH + C_IN, CM,
                      nullptr, g_gi_lh1_all + (size_t)t * NSTOCK * G3,
                      g_gis, HID, NSTOCK, mt * 128, nt * 128, dsm);
        }
        grid_sync();

        // ---- F: gate h ----
        gate_hh(g_gis, g_gh_lh, h_out, g_h_hi, g_h_lo, NSTOCK, gtid, nthr);
        grid_sync();
    }
}

// ---------------- launch -----------------------------------------------------
extern "C" void kernel_launch(void* const* d_in, const int* in_sizes, int n_in,
                              void* d_out, int out_size) {
    const float* inputs   = (const float*)d_in[0];
    const int*   ei       = (const int*)d_in[1];
    const float* h_start  = (const float*)d_in[2];
    const float* hi_start = (const float*)d_in[3];
    const float* mc_start = (const float*)d_in[4];
    const float* Wih_c  = (const float*)d_in[5];
    const float* Whh_c  = (const float*)d_in[6];
    const float* bih_c  = (const float*)d_in[7];
    const float* bhh_c  = (const float*)d_in[8];
    const float* Wih_lh = (const float*)d_in[9];
    const float* Whh_lh = (const float*)d_in[10];
    const float* bih_lh = (const float*)d_in[11];
    const float* bhh_lh = (const float*)d_in[12];
    const float* Wih_li = (const float*)d_in[13];
    const float* Whh_li = (const float*)d_in[14];
    const float* bih_li = (const float*)d_in[15];
    const float* bhh_li = (const float*)d_in[16];

    float* out    = (float*)d_out;
    float* m_out  = out;
    float* h_out  = out + (size_t)NSTOCK * CM;
    float* hi_out = h_out + (size_t)NSTOCK * HID;

    cudaFuncSetAttribute(mega_kernel, cudaFuncAttributeMaxDynamicSharedMemorySize, SMEM_BYTES);

    int dev = 0, nsm = 0, occ = 0;
    cudaGetDevice(&dev);
    cudaDeviceGetAttribute(&nsm, cudaDevAttrMultiProcessorCount, dev);
    cudaOccupancyMaxActiveBlocksPerMultiprocessor(&occ, mega_kernel, NT, SMEM_BYTES);
    if (occ < 1) occ = 1;
    int nblk = nsm * occ;

    unsigned* bar = nullptr;
    cudaGetSymbolAddress((void**)&bar, g_bar_count);
    cudaMemsetAsync(bar, 0, sizeof(unsigned));

    mega_kernel<<<nblk, NT, SMEM_BYTES>>>(inputs, ei, h_start, hi_start, mc_start,
                                          Wih_c, Whh_c, bih_c, bhh_c,
                                          Wih_lh, Whh_lh, bih_lh, bhh_lh,
                                          Wih_li, Whh_li, bih_li, bhh_li,
                                          m_out, h_out, hi_out);
}

// round 12
// speedup vs baseline: 2.7365x; 1.0117x over previous
#include <cuda_runtime.h>
#include <cuda_bf16.h>
#include <cuda_fp16.h>
#include <math.h>
#include <stdint.h>

#define SEQ_L 64
#define NSTOCK 8000
#define NNEWS 1600
#define C_IN 128
#define HID 256
#define NEDGE 32000
#define G3 768
#define CM 384
#define NT 256
#define NSTE 512000
#define NNE  102400

// per-step cp.async GEMM: BK=32 double-buffered
#define BKP32 40
#define SA_ELEM (128 * BKP32)
#define SA_SZ (SA_ELEM * 2)            // 10240 B
#define STAGE_SZ (4 * SA_SZ)           // 40960 B
#define SMEM_BYTES (2 * STAGE_SZ)      // 81920 B
// bulk single-buffer GEMM: BK=64
#define BKP 72

// ---- weight bf16 hi/lo offsets (elements) -----------------------------------
#define OW_IH_LI 0
#define OW_HH_LI 98304
#define OW_IH_C  294912
#define OW_HH_C  393216
#define OW_IH_LH 589824
#define OW_HH_LH 884736
#define W_TOTAL  1081344

// ---------------- static device scratch (~2.1GB, linker-safe) ----------------
__device__ __align__(16) float g_acc_news_all[(size_t)NNE * C_IN];
__device__ __align__(16) float g_accmc_all[(size_t)NSTE * C_IN];
__device__ __align__(16) __half g_gi_li_all[(size_t)NSTE * G3];
__device__ __align__(16) __half g_gi_c_all[(size_t)NNE * G3];
__device__ __align__(16) __half g_gi_lh1_all[(size_t)NSTE * G3];
__device__ float g_inv_news_all[NNE];
__device__ float g_inv_stock_all[NSTE];
// CSR (stock-destination sorted edges, per t)
__device__ int g_deg[NSTE];
__device__ int g_csr_off[NSTE];
__device__ int g_cur[NSTE];
__device__ int g_csr_n[SEQ_L * NEDGE];
__device__ int g_tot[SEQ_L];
// per-step state
__device__ __align__(16) float g_mc[NNEWS * HID];
__device__ __align__(16) __nv_bfloat16 g_mc_hi[NNEWS * HID];
__device__ __align__(16) __nv_bfloat16 g_mc_lo[NNEWS * HID];
__device__ __align__(16) __nv_bfloat16 g_h_hi[NSTOCK * HID];
__device__ __align__(16) __nv_bfloat16 g_h_lo[NSTOCK * HID];
__device__ __align__(16) __nv_bfloat16 g_p_hi[NSTOCK * HID];
__device__ __align__(16) __nv_bfloat16 g_p_lo[NSTOCK * HID];
__device__ __align__(16) __nv_bfloat16 g_amc_hi[NSTOCK * HID];
__device__ __align__(16) __nv_bfloat16 g_amc_lo[NSTOCK * HID];
__device__ __align__(16) __half g_gh_li[NSTOCK * G3];
__device__ __align__(16) __half g_gh_lh[NSTOCK * G3];
__device__ __align__(16) __half g_gh_n[NNEWS * G3];
__device__ __align__(16) __half g_gis[NSTOCK * G3];
__device__ __align__(16) __nv_bfloat16 g_Whi[W_TOTAL];
__device__ __align__(16) __nv_bfloat16 g_Wlo[W_TOTAL];
__device__ unsigned g_bar_count = 0;

// ---------------- software grid barrier (monotonic) --------------------------
__device__ __forceinline__ void grid_sync() {
    __syncthreads();
    __threadfence();
    if (threadIdx.x == 0) {
        unsigned G = gridDim.x;
        unsigned arrival = atomicAdd(&g_bar_count, 1u) + 1u;
        unsigned target = ((arrival + G - 1u) / G) * G;
        volatile unsigned* vc = &g_bar_count;
        while (*vc < target) { __nanosleep(32); }
    }
    __syncthreads();
    __threadfence();
}

__device__ __forceinline__ void bsplit(float v, __nv_bfloat16* hp, __nv_bfloat16* lp) {
    __nv_bfloat16 h = __float2bfloat16(v);
    *hp = h;
    *lp = __float2bfloat16(v - __bfloat162float(h));
}

__device__ __forceinline__ void mma_bf16(float* c, const uint32_t* a, const uint32_t* b) {
    asm volatile("mma.sync.aligned.m16n8k16.row.col.f32.bf16.bf16.f32 "
                 "{%0,%1,%2,%3}, {%4,%5,%6,%7}, {%8,%9}, {%0,%1,%2,%3};"
                 : "+f"(c[0]), "+f"(c[1]), "+f"(c[2]), "+f"(c[3])
                 : "r"(a[0]), "r"(a[1]), "r"(a[2]), "r"(a[3]), "r"(b[0]), "r"(b[1]));
}

__device__ __forceinline__ void ldsm_x4(uint32_t addr, uint32_t* r) {
    asm volatile("ldmatrix.sync.aligned.m8n8.x4.shared.b16 {%0,%1,%2,%3}, [%4];"
                 : "=r"(r[0]), "=r"(r[1]), "=r"(r[2]), "=r"(r[3]) : "r"(addr));
}
__device__ __forceinline__ void ldsm_x2(uint32_t addr, uint32_t* r) {
    asm volatile("ldmatrix.sync.aligned.m8n8.x2.shared.b16 {%0,%1}, [%2];"
                 : "=r"(r[0]), "=r"(r[1]) : "r"(addr));
}

struct Acc { float v[4][4][4]; };

// ---------------- ldmatrix fragment compute over one staged chunk -------------
// Three passes per k16 so same-accumulator MMAs are 16 apart (dependency-free
// pipelining). A-fragment registers are reused for the Al pass (no extra regs).
template <int BK, int KP>
__device__ __forceinline__ void mma_chunk_l(uint32_t sAh, uint32_t sAl,
                                            uint32_t sBh, uint32_t sBl,
                                            uint32_t aoff, uint32_t boff, Acc& A) {
#pragma unroll
    for (int kk = 0; kk < BK; kk += 16) {
        uint32_t bh[4][2], bl[4][2], af[4][4];
#pragma unroll
        for (int nf = 0; nf < 4; nf++) {
            uint32_t o = boff + (nf * 8 * KP + kk) * 2;
            ldsm_x2(sBh + o, bh[nf]);
            ldsm_x2(sBl + o, bl[nf]);
        }
#pragma unroll
        for (int mf = 0; mf < 4; mf++)
            ldsm_x4(sAh + aoff + (mf * 16 * KP + kk) * 2, af[mf]);
        // pass 1: Ah * Bh  (16 independent MMAs)
#pragma unroll
        for (int nf = 0; nf < 4; nf++)
#pragma unroll
            for (int mf = 0; mf < 4; mf++)
                mma_bf16(A.v[mf][nf], af[mf], bh[nf]);
        // pass 2: Ah * Bl
#pragma unroll
        for (int nf = 0; nf < 4; nf++)
#pragma unroll
            for (int mf = 0; mf < 4; mf++)
                mma_bf16(A.v[mf][nf], af[mf], bl[nf]);
        // reload A regs with Al, pass 3: Al * Bh
#pragma unroll
        for (int mf = 0; mf < 4; mf++)
            ldsm_x4(sAl + aoff + (mf * 16 * KP + kk) * 2, af[mf]);
#pragma unroll
        for (int nf = 0; nf < 4; nf++)
#pragma unroll
            for (int mf = 0; mf < 4; mf++)
                mma_bf16(A.v[mf][nf], af[mf], bh[nf]);
    }
}

// lane-dependent ldmatrix offsets (bytes) for row-major [row][k] smem tiles
template <int KP>
__device__ __forceinline__ uint32_t mk_aoff(int mbase, int lane) {
    int arow = (lane & 7) + ((lane >> 3) & 1) * 8;
    int acol = (lane >> 4) * 8;
    return (uint32_t)(((mbase + arow) * KP + acol) * 2);
}
template <int KP>
__device__ __forceinline__ uint32_t mk_boff(int nbase, int lane) {
    int brow = lane & 7;
    int bcol = ((lane >> 3) & 1) * 8;
    return (uint32_t)(((nbase + brow) * KP + bcol) * 2);
}

// ---------------- per-step GEMM: cp.async 2-stage, ldmatrix, fp16 out --------
__device__ void gemm_step(const __nv_bfloat16* __restrict__ Ah,
                          const __nv_bfloat16* __restrict__ Al, int lda,
                          const __nv_bfloat16* __restrict__ Wh,
                          const __nv_bfloat16* __restrict__ Wl, int ldw,
                          const float* __restrict__ bias,
                          const __half* __restrict__ pre,
                          __half* __restrict__ Cc, int K, int M, int m0, int n0,
                          char* dsm) {
    const int tid = threadIdx.x;
    const int w = tid >> 5, lane = tid & 31;
    const int g = lane >> 2, t4 = lane & 3;
    const int mbase = (w >> 2) * 64, nbase = (w & 3) * 32;
    const uint32_t sb0 = (uint32_t)__cvta_generic_to_shared(dsm);
    const uint32_t aoff = mk_aoff<BKP32>(mbase, lane);
    const uint32_t boff = mk_boff<BKP32>(nbase, lane);
    Acc acc;
#pragma unroll
    for (int i = 0; i < 4; i++)
#pragma unroll
        for (int j = 0; j < 4; j++)
#pragma unroll
            for (int q = 0; q < 4; q++) acc.v[i][j][q] = 0.0f;

    const int NC = K >> 5;
    auto stage = [&](int c) {
        uint32_t sb = sb0 + (c & 1) * STAGE_SZ;
        int kt = c << 5;
        for (int it = tid; it < 512; it += NT) {
            int row = it >> 2;
            int c8 = (it & 3) << 3;
            int mm = m0 + row; if (mm >= M) mm = M - 1;
            const void* gah = Ah + (size_t)mm * lda + kt + c8;
            const void* gal = Al + (size_t)mm * lda + kt + c8;
            const void* gbh = Wh + (size_t)(n0 + row) * ldw + kt + c8;
            const void* gbl = Wl + (size_t)(n0 + row) * ldw + kt + c8;
            uint32_t so = sb + (row * BKP32 + c8) * 2;
            asm volatile("cp.async.ca.shared.global [%0], [%1], 16;" :: "r"(so), "l"(gah));
            asm volatile("cp.async.ca.shared.global [%0], [%1], 16;" :: "r"(so + SA_SZ), "l"(gal));
            asm volatile("cp.async.ca.shared.global [%0], [%1], 16;" :: "r"(so + 2 * SA_SZ), "l"(gbh));
            asm volatile("cp.async.ca.shared.global [%0], [%1], 16;" :: "r"(so + 3 * SA_SZ), "l"(gbl));
        }
        asm volatile("cp.async.commit_group;");
    };

    stage(0);
    for (int c = 0; c < NC; c++) {
        if (c + 1 < NC) {
            stage(c + 1);
            asm volatile("cp.async.wait_group 1;");
        } else {
            asm volatile("cp.async.wait_group 0;");
        }
        __syncthreads();
        uint32_t st = sb0 + (c & 1) * STAGE_SZ;
        mma_chunk_l<32, BKP32>(st, st + SA_SZ, st + 2 * SA_SZ, st + 3 * SA_SZ,
                               aoff, boff, acc);
        __syncthreads();
    }
#pragma unroll
    for (int mf = 0; mf < 4; mf++) {
#pragma unroll
        for (int nf = 0; nf < 4; nf++) {
            int m = m0 + mbase + mf * 16 + g;
            int n = n0 + nbase + nf * 8 + 2 * t4;
            if (pre == nullptr) {
                float b0 = bias[n], b1 = bias[n + 1];
                if (m < M)
                    *(__half2*)(Cc + (size_t)m * G3 + n) =
                        __floats2half2_rn(acc.v[mf][nf][0] + b0, acc.v[mf][nf][1] + b1);
                if (m + 8 < M)
                    *(__half2*)(Cc + (size_t)(m + 8) * G3 + n) =
                        __floats2half2_rn(acc.v[mf][nf][2] + b0, acc.v[mf][nf][3] + b1);
            } else {
                if (m < M) {
                    float2 p = __half22float2(*(const __half2*)(pre + (size_t)m * G3 + n));
                    *(__half2*)(Cc + (size_t)m * G3 + n) =
                        __floats2half2_rn(acc.v[mf][nf][0] + p.x, acc.v[mf][nf][1] + p.y);
                }
                if (m + 8 < M) {
                    float2 p = __half22float2(*(const __half2*)(pre + (size_t)(m + 8) * G3 + n));
                    *(__half2*)(Cc + (size_t)(m + 8) * G3 + n) =
                        __floats2half2_rn(acc.v[mf][nf][2] + p.x, acc.v[mf][nf][3] + p.y);
                }
            }
        }
    }
    __syncthreads();
}

// ---------------- bulk GEMM: fp32 A split on the fly, ldmatrix, fp16 out -----
__device__ void gemm_f32A_h16(const float* __restrict__ A, int lda,
                              const __nv_bfloat16* __restrict__ Wh,
                              const __nv_bfloat16* __restrict__ Wl, int ldw,
                              const float* __restrict__ bias,
                              __half* __restrict__ Cc, int K, int M, int m0, int n0,
                              uint16_t* sm) {
    uint16_t* sAh = sm;
    uint16_t* sAl = sm + 128 * BKP;
    uint16_t* sBh = sm + 2 * 128 * BKP;
    uint16_t* sBl = sm + 3 * 128 * BKP;
    const int tid = threadIdx.x;
    const int w = tid >> 5, lane = tid & 31;
    const int g = lane >> 2, t4 = lane & 3;
    const int mbase = (w >> 2) * 64, nbase = (w & 3) * 32;
    const uint32_t sb = (uint32_t)__cvta_generic_to_shared(sm);
    const uint32_t aoff = mk_aoff<BKP>(mbase, lane);
    const uint32_t boff = mk_boff<BKP>(nbase, lane);
    const uint32_t asz = 128 * BKP * 2;
    Acc acc;
#pragma unroll
    for (int i = 0; i < 4; i++)
#pragma unroll
        for (int j = 0; j < 4; j++)
#pragma unroll
            for (int q = 0; q < 4; q++) acc.v[i][j][q] = 0.0f;

    for (int kt = 0; kt < K; kt += 64) {
        for (int it = tid; it < 1024; it += NT) {
            int row = it >> 3;
            int c8 = (it & 7) << 3;
            int mm = m0 + row; if (mm >= M) mm = M - 1;
            const float* ap = A + (size_t)mm * lda + kt + c8;
            float4 v0 = *(const float4*)ap;
            float4 v1 = *(const float4*)(ap + 4);
            float f[8] = {v0.x, v0.y, v0.z, v0.w, v1.x, v1.y, v1.z, v1.w};
            int so = row * BKP + c8;
#pragma unroll
            for (int q = 0; q < 8; q++) {
                __nv_bfloat16 hh = __float2bfloat16(f[q]);
                sAh[so + q] = __bfloat16_as_ushort(hh);
                sAl[so + q] = __bfloat16_as_ushort(
                    __float2bfloat16(f[q] - __bfloat162float(hh)));
            }
            size_t bo = (size_t)(n0 + row) * ldw + kt + c8;
            *(uint4*)(sBh + so) = *(const uint4*)(Wh + bo);
            *(uint4*)(sBl + so) = *(const uint4*)(Wl + bo);
        }
        __syncthreads();
        mma_chunk_l<64, BKP>(sb, sb + asz, sb + 2 * asz, sb + 3 * asz, aoff, boff, acc);
        __syncthreads();
    }
#pragma unroll
    for (int mf = 0; mf < 4; mf++) {
#pragma unroll
        for (int nf = 0; nf < 4; nf++) {
            int m = m0 + mbase + mf * 16 + g;
            int n = n0 + nbase + nf * 8 + 2 * t4;
            float b0 = bias[n], b1 = bias[n + 1];
            if (m < M)
                *(__half2*)(Cc + (size_t)m * G3 + n) =
                    __floats2half2_rn(acc.v[mf][nf][0] + b0, acc.v[mf][nf][1] + b1);
            if (m + 8 < M)
                *(__half2*)(Cc + (size_t)(m + 8) * G3 + n) =
                    __floats2half2_rn(acc.v[mf][nf][2] + b0, acc.v[mf][nf][3] + b1);
        }
    }
    __syncthreads();
}

// ---------------- GRU gate (fp16 gi + fp16 gh) -------------------------------
__device__ __forceinline__ void gate_hh(const __half* __restrict__ gi,
                                        const __half* __restrict__ gh,
                                        float* __restrict__ h,
                                        __nv_bfloat16* __restrict__ hhi,
                                        __nv_bfloat16* __restrict__ hlo,
                                        int M, int gtid, int nthr) {
    int total = M * HID;
    for (int idx = gtid; idx < total; idx += nthr) {
        int m = idx >> 8;
        int j = idx & 255;
        const __half* gim = gi + (size_t)m * G3;
        const __half* ghm = gh + (size_t)m * G3;
        float r = 1.0f / (1.0f + __expf(-(__half2float(gim[j]) + __half2float(ghm[j]))));
        float z = 1.0f / (1.0f + __expf(-(__half2float(gim[HID + j]) + __half2float(ghm[HID + j]))));
        float n = tanhf(__half2float(gim[2 * HID + j]) + r * __half2float(ghm[2 * HID + j]));
        float v = (1.0f - z) * n + z * h[idx];
        h[idx] = v;
        bsplit(v, hhi + idx, hlo + idx);
    }
}

__device__ __forceinline__ void convW(const float* __restrict__ W, int off, int n,
                                      int gtid, int nthr) {
    for (int i = gtid; i < n; i += nthr) {
        float w = W[i];
        __nv_bfloat16 h = __float2bfloat16(w);
        g_Whi[off + i] = h;
        g_Wlo[off + i] = __float2bfloat16(w - __bfloat162float(h));
    }
}

#define ST_T 378
#define NW_T 78
#define PA_TOT (ST_T * 2 + NW_T)
#define BI3_TOT (24000 + 4800)

// ---------------- the persistent mega-kernel ---------------------------------
__global__ __launch_bounds__(NT, 2)
void mega_kernel(const float* __restrict__ inputs, const int* __restrict__ ei,
                 const float* __restrict__ h_start, const float* __restrict__ hi_start,
                 const float* __restrict__ mc_start,
                 const float* __restrict__ Wih_c,  const float* __restrict__ Whh_c,
                 const float* __restrict__ bih_c,  const float* __restrict__ bhh_c,
                 const float* __restrict__ Wih_lh, const float* __restrict__ Whh_lh,
                 const float* __restrict__ bih_lh, const float* __restrict__ bhh_lh,
                 const float* __restrict__ Wih_li, const float* __restrict__ Whh_li,
                 const float* __restrict__ bih_li, const float* __restrict__ bhh_li,
                 float* __restrict__ m_out, float* __restrict__ h_out,
                 float* __restrict__ hi_out) {
    extern __shared__ char dsm[];

    const int gtid = blockIdx.x * NT + threadIdx.x;
    const int nthr = gridDim.x * NT;
    const int gwarp = gtid >> 5;
    const int lane = threadIdx.x & 31;
    const int nwarp = nthr >> 5;

    // ==== I0: init states, weights, zero counters ====
    for (int i = gtid; i < NSTOCK * HID; i += nthr) {
        float hv = h_start[i & 255], pv = hi_start[i & 255];
        h_out[i] = hv; hi_out[i] = pv;
        bsplit(hv, g_h_hi + i, g_h_lo + i);
        bsplit(pv, g_p_hi + i, g_p_lo + i);
    }
    for (int i = gtid; i < NNEWS * HID; i += nthr) {
        float v = mc_start[i & 255];
        g_mc[i] = v;
        bsplit(v, g_mc_hi + i, g_mc_lo + i);
    }
    convW(Wih_li, OW_IH_LI, G3 * C_IN, gtid, nthr);
    convW(Whh_li, OW_HH_LI, G3 * HID,  gtid, nthr);
    convW(Wih_c,  OW_IH_C,  G3 * C_IN, gtid, nthr);
    convW(Whh_c,  OW_HH_C,  G3 * HID,  gtid, nthr);
    convW(Wih_lh, OW_IH_LH, G3 * CM,   gtid, nthr);
    convW(Whh_lh, OW_HH_LH, G3 * HID,  gtid, nthr);
    for (int i = gtid; i < NNE; i += nthr) g_inv_news_all[i] = 0.0f;
    for (int i = gtid; i < NSTE; i += nthr) { g_deg[i] = 0; }
    for (int i = gtid; i < SEQ_L; i += nthr) g_tot[i] = 0;
    for (size_t i = gtid; i < (size_t)NNE * C_IN; i += nthr) g_acc_news_all[i] = 0.0f;
    for (size_t i = gtid; i < (size_t)NSTE * C_IN; i += nthr) g_accmc_all[i] = 0.0f;
    grid_sync();
    // ==== I0b: degree counts ====
    for (int task = gtid; task < SEQ_L * NEDGE; task += nthr) {
        int t = task / NEDGE, e = task - t * NEDGE;
        const int* news = ei + (size_t)t * 2 * NEDGE;
        atomicAdd(&g_inv_news_all[t * NNEWS + news[e]], 1.0f);
        atomicAdd(&g_deg[t * NSTOCK + news[NEDGE + e]], 1);
    }
    grid_sync();
    // ==== I1: invert counts; CSR offsets; bulk scatter x -> news ====
    for (int i = gtid; i < NNE; i += nthr)
        g_inv_news_all[i] = 1.0f / fmaxf(g_inv_news_all[i], 1.0f);
    for (int i = gtid; i < NSTE; i += nthr) {
        int d = g_deg[i];
        g_inv_stock_all[i] = 1.0f / fmaxf((float)d, 1.0f);
        int off = atomicAdd(&g_tot[i / NSTOCK], d);
        g_csr_off[i] = off;
        g_cur[i] = off;
    }
    for (int task = gwarp; task < SEQ_L * NEDGE; task += nwarp) {
        int t = task / NEDGE, e = task - t * NEDGE;
        const int* news = ei + (size_t)t * 2 * NEDGE;
        int n = news[e], s = news[NEDGE + e];
        float4 v = ((const float4*)(inputs + ((size_t)t * NSTOCK + s) * C_IN))[lane];
        float* dst = g_acc_news_all + ((size_t)t * NNEWS + n) * C_IN + lane * 4;
        atomicAdd(dst + 0, v.x); atomicAdd(dst + 1, v.y);
        atomicAdd(dst + 2, v.z); atomicAdd(dst + 3, v.w);
    }
    grid_sync();
    // ==== I2: fill CSR edge lists; normalize center in place ====
    for (int task = gtid; task < SEQ_L * NEDGE; task += nthr) {
        int t = task / NEDGE, e = task - t * NEDGE;
        const int* news = ei + (size_t)t * 2 * NEDGE;
        int n = news[e], s = news[NEDGE + e];
        int slot = atomicAdd(&g_cur[t * NSTOCK + s], 1);
        g_csr_n[(size_t)t * NEDGE + slot] = n;
    }
    for (size_t i = gtid; i < (size_t)NNE * C_IN; i += nthr)
        g_acc_news_all[i] *= g_inv_news_all[i >> 7];
    grid_sync();
    // ==== I3: bulk GEMMs gi_li + gi_c (K=128) ====
    for (int tile = blockIdx.x; tile < BI3_TOT; tile += gridDim.x) {
        if (tile < 24000) {
            int mt = tile / 6, nt = tile % 6;
            gemm_f32A_h16(inputs, C_IN, g_Whi + OW_IH_LI, g_Wlo + OW_IH_LI, C_IN,
                          bih_li, g_gi_li_all, C_IN, NSTE, mt * 128, nt * 128, (uint16_t*)dsm);
        } else {
            int idx = tile - 24000, mt = idx / 6, nt = idx % 6;
            gemm_f32A_h16(g_acc_news_all, C_IN, g_Whi + OW_IH_C, g_Wlo + OW_IH_C, C_IN,
                          bih_c, g_gi_c_all, C_IN, NNE, mt * 128, nt * 128, (uint16_t*)dsm);
        }
    }
    grid_sync();
    // ==== I4: bulk scatter center -> stocks ====
    for (int task = gwarp; task < SEQ_L * NEDGE; task += nwarp) {
        int t = task / NEDGE, e = task - t * NEDGE;
        const int* news = ei + (size_t)t * 2 * NEDGE;
        int n = news[e], s = news[NEDGE + e];
        float4 v = ((const float4*)(g_acc_news_all + ((size_t)t * NNEWS + n) * C_IN))[lane];
        float* dst = g_accmc_all + ((size_t)t * NSTOCK + s) * C_IN + lane * 4;
        atomicAdd(dst + 0, v.x); atomicAdd(dst + 1, v.y);
        atomicAdd(dst + 2, v.z); atomicAdd(dst + 3, v.w);
    }
    grid_sync();
    // ==== I5: normalize mcenter in place; m_out center cols (t=63) ====
    for (size_t i = gtid; i < (size_t)NSTE * C_IN; i += nthr) {
        float v = g_accmc_all[i] * g_inv_stock_all[i >> 7];
        g_accmc_all[i] = v;
        if (i >= (size_t)63 * NSTOCK * C_IN) {
            size_t r = i - (size_t)63 * NSTOCK * C_IN;
            m_out[(r >> 7) * CM + (r & 127)] = v;
        }
    }
    grid_sync();
    // ==== I6: bulk GEMM gi_lh1 (K=128) ====
    for (int tile = blockIdx.x; tile < 24000; tile += gridDim.x) {
        int mt = tile / 6, nt = tile % 6;
        gemm_f32A_h16(g_accmc_all, C_IN, g_Whi + OW_IH_LH, g_Wlo + OW_IH_LH, CM,
                      bih_lh, g_gi_lh1_all, C_IN, NSTE, mt * 128, nt * 128, (uint16_t*)dsm);
    }
    grid_sync();

    // ==== sequential recurrence: K=256 cp.async+ldmatrix GEMMs, CSR gather ====
    for (int t = 0; t < SEQ_L; t++) {
        // ---- A: gh_li, gh_lh, gh_n ----
        for (int tile = blockIdx.x; tile < PA_TOT; tile += gridDim.x) {
            if (tile < ST_T) {
                int mt = tile / 6, nt = tile % 6;
                gemm_step(g_p_hi, g_p_lo, HID, g_Whi + OW_HH_LI, g_Wlo + OW_HH_LI, HID,
                          bhh_li, nullptr, g_gh_li, HID, NSTOCK, mt * 128, nt * 128, dsm);
            } else if (tile < 2 * ST_T) {
                int idx = tile - ST_T, mt = idx / 6, nt = idx % 6;
                gemm_step(g_h_hi, g_h_lo, HID, g_Whi + OW_HH_LH, g_Wlo + OW_HH_LH, HID,
                          bhh_lh, nullptr, g_gh_lh, HID, NSTOCK, mt * 128, nt * 128, dsm);
            } else {
                int idx = tile - 2 * ST_T, mt = idx / 6, nt = idx % 6;
                gemm_step(g_mc_hi, g_mc_lo, HID, g_Whi + OW_HH_C, g_Wlo + OW_HH_C, HID,
                          bhh_c, nullptr, g_gh_n, HID, NNEWS, mt * 128, nt * 128, dsm);
            }
        }
        grid_sync();

        // ---- B: gates m_c + h_input ----
        gate_hh(g_gi_c_all + (size_t)t * NNEWS * G3, g_gh_n,
                g_mc, g_mc_hi, g_mc_lo, NNEWS, gtid, nthr);
        gate_hh(g_gi_li_all + (size_t)t * NSTOCK * G3, g_gh_li,
                hi_out, g_p_hi, g_p_lo, NSTOCK, gtid, nthr);
        grid_sync();

        // ---- C': CSR gather m_c (news -> stocks) + normalize + split ----
        for (int s = gwarp; s < NSTOCK; s += nwarp) {
            int base = t * NSTOCK + s;
            int off = g_csr_off[base], deg = g_deg[base];
            const int* en = g_csr_n + (size_t)t * NEDGE;
            float4 a0 = make_float4(0.f, 0.f, 0.f, 0.f);
            float4 a1 = make_float4(0.f, 0.f, 0.f, 0.f);
            for (int e = off; e < off + deg; e++) {
                int n = en[e];
                const float4* mp = (const float4*)(g_mc + (size_t)n * HID);
                float4 v0 = mp[lane], v1 = mp[lane + 32];
                a0.x += v0.x; a0.y += v0.y; a0.z += v0.z; a0.w += v0.w;
                a1.x += v1.x; a1.y += v1.y; a1.z += v1.z; a1.w += v1.w;
            }
            float inv = g_inv_stock_all[base];
            float vs[8] = {a0.x * inv, a0.y * inv, a0.z * inv, a0.w * inv,
                           a1.x * inv, a1.y * inv, a1.z * inv, a1.w * inv};
            int c0 = s * HID + lane * 4;
#pragma unroll
            for (int q = 0; q < 4; q++) {
                bsplit(vs[q], g_amc_hi + c0 + q, g_amc_lo + c0 + q);
                bsplit(vs[4 + q], g_amc_hi + c0 + 128 + q, g_amc_lo + c0 + 128 + q);
            }
            if (t == SEQ_L - 1) {
                float* mo = m_out + (size_t)s * CM + C_IN + lane * 4;
#pragma unroll
                for (int q = 0; q < 4; q++) { mo[q] = vs[q]; mo[128 + q] = vs[4 + q]; }
            }
        }
        grid_sync();

        // ---- E: gis = gi_lh1[t] + amc @ Wih_lh[:, 128:]^T ----
        for (int tile = blockIdx.x; tile < ST_T; tile += gridDim.x) {
            int mt = tile / 6, nt = tile % 6;
            gemm_step(g_amc_hi, g_amc_lo, HID,
                      g_Whi + OW_IH_LH + C_IN, g_Wlo + OW_IH_LH + C_IN, CM,
                      nullptr, g_gi_lh1_all + (size_t)t * NSTOCK * G3,
                      g_gis, HID, NSTOCK, mt * 128, nt * 128, dsm);
        }
        grid_sync();

        // ---- F: gate h ----
        gate_hh(g_gis, g_gh_lh, h_out, g_h_hi, g_h_lo, NSTOCK, gtid, nthr);
        grid_sync();
    }
}

// ---------------- launch -----------------------------------------------------
extern "C" void kernel_launch(void* const* d_in, const int* in_sizes, int n_in,
                              void* d_out, int out_size) {
    const float* inputs   = (const float*)d_in[0];
    const int*   ei       = (const int*)d_in[1];
    const float* h_start  = (const float*)d_in[2];
    const float* hi_start = (const float*)d_in[3];
    const float* mc_start = (const float*)d_in[4];
    const float* Wih_c  = (const float*)d_in[5];
    const float* Whh_c  = (const float*)d_in[6];
    const float* bih_c  = (const float*)d_in[7];
    const float* bhh_c  = (const float*)d_in[8];
    const float* Wih_lh = (const float*)d_in[9];
    const float* Whh_lh = (const float*)d_in[10];
    const float* bih_lh = (const float*)d_in[11];
    const float* bhh_lh = (const float*)d_in[12];
    const float* Wih_li = (const float*)d_in[13];
    const float* Whh_li = (const float*)d_in[14];
    const float* bih_li = (const float*)d_in[15];
    const float* bhh_li = (const float*)d_in[16];

    float* out    = (float*)d_out;
    float* m_out  = out;
    float* h_out  = out + (size_t)NSTOCK * CM;
    float* hi_out = h_out + (size_t)NSTOCK * HID;

    cudaFuncSetAttribute(mega_kernel, cudaFuncAttributeMaxDynamicSharedMemorySize, SMEM_BYTES);

    int dev = 0, nsm = 0, occ = 0;
    cudaGetDevice(&dev);
    cudaDeviceGetAttribute(&nsm, cudaDevAttrMultiProcessorCount, dev);
    cudaOccupancyMaxActiveBlocksPerMultiprocessor(&occ, mega_kernel, NT, SMEM_BYTES);
    if (occ < 1) occ = 1;
    int nblk = nsm * occ;

    unsigned* bar = nullptr;
    cudaGetSymbolAddress((void**)&bar, g_bar_count);
    cudaMemsetAsync(bar, 0, sizeof(unsigned));

    mega_kernel<<<nblk, NT, SMEM_BYTES>>>(inputs, ei, h_start, hi_start, mc_start,
                                          Wih_c, Whh_c, bih_c, bhh_c,
                                          Wih_lh, Whh_lh, bih_lh, bhh_lh,
                                          Wih_li, Whh_li, bih_li, bhh_li,
                                          m_out, h_out, hi_out);
}

// round 13
// speedup vs baseline: 3.1086x; 1.1360x over previous
#include <cuda_runtime.h>
#include <cuda_bf16.h>
#include <cuda_fp16.h>
#include <math.h>
#include <stdint.h>

#define SEQ_L 64
#define NSTOCK 8000
#define NNEWS 1600
#define C_IN 128
#define HID 256
#define NEDGE 32000
#define G3 768
#define CM 384
#define NT 256
#define NSTE 512000
#define NNE  102400

// per-step cp.async GEMM: BK=32 double-buffered, 3 operand arrays (A, Bh, Bl)
#define BKP32 40
#define SA_ELEM (128 * BKP32)
#define SA_SZ (SA_ELEM * 2)            // 10240 B
#define STAGE_SZ (3 * SA_SZ)           // 30720 B
#define SMEM_BYTES (2 * STAGE_SZ)      // 61440 B
// bulk single-buffer GEMM: BK=64, 3 arrays of 128*BKP halves (55296 B total)
#define BKP 72

// ---- weight fp16 hi/lo offsets (elements) -----------------------------------
#define OW_IH_LI 0
#define OW_HH_LI 98304
#define OW_IH_C  294912
#define OW_HH_C  393216
#define OW_IH_LH 589824
#define OW_HH_LH 884736
#define W_TOTAL  1081344

// ---------------- static device scratch (~2GB, linker-safe) ------------------
__device__ __align__(16) float g_acc_news_all[(size_t)NNE * C_IN];
__device__ __align__(16) float g_accmc_all[(size_t)NSTE * C_IN];
__device__ __align__(16) __half g_gi_li_all[(size_t)NSTE * G3];
__device__ __align__(16) __half g_gi_c_all[(size_t)NNE * G3];
__device__ __align__(16) __half g_gi_lh1_all[(size_t)NSTE * G3];
__device__ float g_inv_news_all[NNE];
__device__ float g_inv_stock_all[NSTE];
// CSR (stock-destination sorted edges, per t)
__device__ int g_deg[NSTE];
__device__ int g_csr_off[NSTE];
__device__ int g_cur[NSTE];
__device__ int g_csr_n[SEQ_L * NEDGE];
__device__ int g_tot[SEQ_L];
// per-step state (fp32 master where needed + fp16 GEMM operand copies)
__device__ __align__(16) float g_mc[NNEWS * HID];
__device__ __align__(16) __half g_mc16[NNEWS * HID];
__device__ __align__(16) __half g_h16[NSTOCK * HID];
__device__ __align__(16) __half g_p16[NSTOCK * HID];
__device__ __align__(16) __half g_amc16[NSTOCK * HID];
__device__ __align__(16) __half g_gh_li[NSTOCK * G3];
__device__ __align__(16) __half g_gh_lh[NSTOCK * G3];
__device__ __align__(16) __half g_gh_n[NNEWS * G3];
__device__ __align__(16) __half g_gis[NSTOCK * G3];
__device__ __align__(16) __half g_Whi[W_TOTAL];
__device__ __align__(16) __half g_Wlo[W_TOTAL];
__device__ unsigned g_bar_count = 0;

// ---------------- software grid barrier (monotonic) --------------------------
__device__ __forceinline__ void grid_sync() {
    __syncthreads();
    __threadfence();
    if (threadIdx.x == 0) {
        unsigned G = gridDim.x;
        unsigned arrival = atomicAdd(&g_bar_count, 1u) + 1u;
        unsigned target = ((arrival + G - 1u) / G) * G;
        volatile unsigned* vc = &g_bar_count;
        while (*vc < target) { __nanosleep(32); }
    }
    __syncthreads();
    __threadfence();
}

__device__ __forceinline__ void mma_f16(float* c, const uint32_t* a, const uint32_t* b) {
    asm volatile("mma.sync.aligned.m16n8k16.row.col.f32.f16.f16.f32 "
                 "{%0,%1,%2,%3}, {%4,%5,%6,%7}, {%8,%9}, {%0,%1,%2,%3};"
                 : "+f"(c[0]), "+f"(c[1]), "+f"(c[2]), "+f"(c[3])
                 : "r"(a[0]), "r"(a[1]), "r"(a[2]), "r"(a[3]), "r"(b[0]), "r"(b[1]));
}

__device__ __forceinline__ void ldsm_x4(uint32_t addr, uint32_t* r) {
    asm volatile("ldmatrix.sync.aligned.m8n8.x4.shared.b16 {%0,%1,%2,%3}, [%4];"
                 : "=r"(r[0]), "=r"(r[1]), "=r"(r[2]), "=r"(r[3]) : "r"(addr));
}
__device__ __forceinline__ void ldsm_x2(uint32_t addr, uint32_t* r) {
    asm volatile("ldmatrix.sync.aligned.m8n8.x2.shared.b16 {%0,%1}, [%2];"
                 : "=r"(r[0]), "=r"(r[1]) : "r"(addr));
}

struct Acc { float v[4][4][4]; };

// ---------------- 2-term fp16 fragment compute over one staged chunk ---------
template <int BK, int KP>
__device__ __forceinline__ void mma_chunk_l(uint32_t sA, uint32_t sBh, uint32_t sBl,
                                            uint32_t aoff, uint32_t boff, Acc& A) {
#pragma unroll
    for (int kk = 0; kk < BK; kk += 16) {
        uint32_t bh[4][2], bl[4][2], af[4][4];
#pragma unroll
        for (int nf = 0; nf < 4; nf++) {
            uint32_t o = boff + (nf * 8 * KP + kk) * 2;
            ldsm_x2(sBh + o, bh[nf]);
            ldsm_x2(sBl + o, bl[nf]);
        }
#pragma unroll
        for (int mf = 0; mf < 4; mf++)
            ldsm_x4(sA + aoff + (mf * 16 * KP + kk) * 2, af[mf]);
        // pass 1: A * Wh (16 independent MMAs)
#pragma unroll
        for (int nf = 0; nf < 4; nf++)
#pragma unroll
            for (int mf = 0; mf < 4; mf++)
                mma_f16(A.v[mf][nf], af[mf], bh[nf]);
        // pass 2: A * Wl
#pragma unroll
        for (int nf = 0; nf < 4; nf++)
#pragma unroll
            for (int mf = 0; mf < 4; mf++)
                mma_f16(A.v[mf][nf], af[mf], bl[nf]);
    }
}

// lane-dependent ldmatrix offsets (bytes) for row-major [row][k] smem tiles
template <int KP>
__device__ __forceinline__ uint32_t mk_aoff(int mbase, int lane) {
    int arow = (lane & 7) + ((lane >> 3) & 1) * 8;
    int acol = (lane >> 4) * 8;
    return (uint32_t)(((mbase + arow) * KP + acol) * 2);
}
template <int KP>
__device__ __forceinline__ uint32_t mk_boff(int nbase, int lane) {
    int brow = lane & 7;
    int bcol = ((lane >> 3) & 1) * 8;
    return (uint32_t)(((nbase + brow) * KP + bcol) * 2);
}

// ---------------- per-step GEMM: cp.async 2-stage, fp16 A, fp16 out ----------
__device__ void gemm_step(const __half* __restrict__ A, int lda,
                          const __half* __restrict__ Wh,
                          const __half* __restrict__ Wl, int ldw,
                          const float* __restrict__ bias,
                          const __half* __restrict__ pre,
                          __half* __restrict__ Cc, int K, int M, int m0, int n0,
                          char* dsm) {
    const int tid = threadIdx.x;
    const int w = tid >> 5, lane = tid & 31;
    const int g = lane >> 2, t4 = lane & 3;
    const int mbase = (w >> 2) * 64, nbase = (w & 3) * 32;
    const uint32_t sb0 = (uint32_t)__cvta_generic_to_shared(dsm);
    const uint32_t aoff = mk_aoff<BKP32>(mbase, lane);
    const uint32_t boff = mk_boff<BKP32>(nbase, lane);
    Acc acc;
#pragma unroll
    for (int i = 0; i < 4; i++)
#pragma unroll
        for (int j = 0; j < 4; j++)
#pragma unroll
            for (int q = 0; q < 4; q++) acc.v[i][j][q] = 0.0f;

    const int NC = K >> 5;
    auto stage = [&](int c) {
        uint32_t sb = sb0 + (c & 1) * STAGE_SZ;
        int kt = c << 5;
        for (int it = tid; it < 512; it += NT) {
            int row = it >> 2;
            int c8 = (it & 3) << 3;
            int mm = m0 + row; if (mm >= M) mm = M - 1;
            const void* ga  = A + (size_t)mm * lda + kt + c8;
            const void* gbh = Wh + (size_t)(n0 + row) * ldw + kt + c8;
            const void* gbl = Wl + (size_t)(n0 + row) * ldw + kt + c8;
            uint32_t so = sb + (row * BKP32 + c8) * 2;
            asm volatile("cp.async.ca.shared.global [%0], [%1], 16;" :: "r"(so), "l"(ga));
            asm volatile("cp.async.ca.shared.global [%0], [%1], 16;" :: "r"(so + SA_SZ), "l"(gbh));
            asm volatile("cp.async.ca.shared.global [%0], [%1], 16;" :: "r"(so + 2 * SA_SZ), "l"(gbl));
        }
        asm volatile("cp.async.commit_group;");
    };

    stage(0);
    for (int c = 0; c < NC; c++) {
        if (c + 1 < NC) {
            stage(c + 1);
            asm volatile("cp.async.wait_group 1;");
        } else {
            asm volatile("cp.async.wait_group 0;");
        }
        __syncthreads();
        uint32_t st = sb0 + (c & 1) * STAGE_SZ;
        mma_chunk_l<32, BKP32>(st, st + SA_SZ, st + 2 * SA_SZ, aoff, boff, acc);
        __syncthreads();
    }
#pragma unroll
    for (int mf = 0; mf < 4; mf++) {
#pragma unroll
        for (int nf = 0; nf < 4; nf++) {
            int m = m0 + mbase + mf * 16 + g;
            int n = n0 + nbase + nf * 8 + 2 * t4;
            if (pre == nullptr) {
                float b0 = bias[n], b1 = bias[n + 1];
                if (m < M)
                    *(__half2*)(Cc + (size_t)m * G3 + n) =
                        __floats2half2_rn(acc.v[mf][nf][0] + b0, acc.v[mf][nf][1] + b1);
                if (m + 8 < M)
                    *(__half2*)(Cc + (size_t)(m + 8) * G3 + n) =
                        __floats2half2_rn(acc.v[mf][nf][2] + b0, acc.v[mf][nf][3] + b1);
            } else {
                if (m < M) {
                    float2 p = __half22float2(*(const __half2*)(pre + (size_t)m * G3 + n));
                    *(__half2*)(Cc + (size_t)m * G3 + n) =
                        __floats2half2_rn(acc.v[mf][nf][0] + p.x, acc.v[mf][nf][1] + p.y);
                }
                if (m + 8 < M) {
                    float2 p = __half22float2(*(const __half2*)(pre + (size_t)(m + 8) * G3 + n));
                    *(__half2*)(Cc + (size_t)(m + 8) * G3 + n) =
                        __floats2half2_rn(acc.v[mf][nf][2] + p.x, acc.v[mf][nf][3] + p.y);
                }
            }
        }
    }
    __syncthreads();
}

// ---------------- bulk GEMM: fp32 A -> fp16 on the fly, fp16 out -------------
__device__ void gemm_f32A_h16(const float* __restrict__ A, int lda,
                              const __half* __restrict__ Wh,
                              const __half* __restrict__ Wl, int ldw,
                              const float* __restrict__ bias,
                              __half* __restrict__ Cc, int K, int M, int m0, int n0,
                              uint16_t* sm) {
    uint16_t* sA  = sm;
    uint16_t* sBh = sm + 128 * BKP;
    uint16_t* sBl = sm + 2 * 128 * BKP;
    const int tid = threadIdx.x;
    const int w = tid >> 5, lane = tid & 31;
    const int g = lane >> 2, t4 = lane & 3;
    const int mbase = (w >> 2) * 64, nbase = (w & 3) * 32;
    const uint32_t sb = (uint32_t)__cvta_generic_to_shared(sm);
    const uint32_t aoff = mk_aoff<BKP>(mbase, lane);
    const uint32_t boff = mk_boff<BKP>(nbase, lane);
    const uint32_t asz = 128 * BKP * 2;
    Acc acc;
#pragma unroll
    for (int i = 0; i < 4; i++)
#pragma unroll
        for (int j = 0; j < 4; j++)
#pragma unroll
            for (int q = 0; q < 4; q++) acc.v[i][j][q] = 0.0f;

    for (int kt = 0; kt < K; kt += 64) {
        for (int it = tid; it < 1024; it += NT) {
            int row = it >> 3;
            int c8 = (it & 7) << 3;
            int mm = m0 + row; if (mm >= M) mm = M - 1;
            const float* ap = A + (size_t)mm * lda + kt + c8;
            float4 v0 = *(const float4*)ap;
            float4 v1 = *(const float4*)(ap + 4);
            __half hv[8];
            hv[0] = __float2half_rn(v0.x); hv[1] = __float2half_rn(v0.y);
            hv[2] = __float2half_rn(v0.z); hv[3] = __float2half_rn(v0.w);
            hv[4] = __float2half_rn(v1.x); hv[5] = __float2half_rn(v1.y);
            hv[6] = __float2half_rn(v1.z); hv[7] = __float2half_rn(v1.w);
            int so = row * BKP + c8;
            *(uint4*)(sA + so) = *(const uint4*)hv;
            size_t bo = (size_t)(n0 + row) * ldw + kt + c8;
            *(uint4*)(sBh + so) = *(const uint4*)(Wh + bo);
            *(uint4*)(sBl + so) = *(const uint4*)(Wl + bo);
        }
        __syncthreads();
        mma_chunk_l<64, BKP>(sb, sb + asz, sb + 2 * asz, aoff, boff, acc);
        __syncthreads();
    }
#pragma unroll
    for (int mf = 0; mf < 4; mf++) {
#pragma unroll
        for (int nf = 0; nf < 4; nf++) {
            int m = m0 + mbase + mf * 16 + g;
            int n = n0 + nbase + nf * 8 + 2 * t4;
            float b0 = bias[n], b1 = bias[n + 1];
            if (m < M)
                *(__half2*)(Cc + (size_t)m * G3 + n) =
                    __floats2half2_rn(acc.v[mf][nf][0] + b0, acc.v[mf][nf][1] + b1);
            if (m + 8 < M)
                *(__half2*)(Cc + (size_t)(m + 8) * G3 + n) =
                    __floats2half2_rn(acc.v[mf][nf][2] + b0, acc.v[mf][nf][3] + b1);
        }
    }
    __syncthreads();
}

// ---------------- GRU gate (fp16 gi + fp16 gh -> fp32 master + fp16 state) ---
__device__ __forceinline__ void gate_hh(const __half* __restrict__ gi,
                                        const __half* __restrict__ gh,
                                        float* __restrict__ hf,
                                        __half* __restrict__ h16,
                                        int M, int gtid, int nthr) {
    int total = M * HID;
    for (int idx = gtid; idx < total; idx += nthr) {
        int m = idx >> 8;
        int j = idx & 255;
        const __half* gim = gi + (size_t)m * G3;
        const __half* ghm = gh + (size_t)m * G3;
        float r = 1.0f / (1.0f + __expf(-(__half2float(gim[j]) + __half2float(ghm[j]))));
        float z = 1.0f / (1.0f + __expf(-(__half2float(gim[HID + j]) + __half2float(ghm[HID + j]))));
        float n = tanhf(__half2float(gim[2 * HID + j]) + r * __half2float(ghm[2 * HID + j]));
        float v = (1.0f - z) * n + z * hf[idx];
        hf[idx] = v;
        h16[idx] = __float2half_rn(v);
    }
}

__device__ __forceinline__ void convW(const float* __restrict__ W, int off, int n,
                                      int gtid, int nthr) {
    for (int i = gtid; i < n; i += nthr) {
        float w = W[i];
        __half h = __float2half_rn(w);
        g_Whi[off + i] = h;
        g_Wlo[off + i] = __float2half_rn(w - __half2float(h));
    }
}

#define ST_T 378
#define NW_T 78
#define PA_TOT (ST_T * 2 + NW_T)
#define BI3_TOT (24000 + 4800)

// ---------------- the persistent mega-kernel ---------------------------------
__global__ __launch_bounds__(NT, 2)
void mega_kernel(const float* __restrict__ inputs, const int* __restrict__ ei,
                 const float* __restrict__ h_start, const float* __restrict__ hi_start,
                 const float* __restrict__ mc_start,
                 const float* __restrict__ Wih_c,  const float* __restrict__ Whh_c,
                 const float* __restrict__ bih_c,  const float* __restrict__ bhh_c,
                 const float* __restrict__ Wih_lh, const float* __restrict__ Whh_lh,
                 const float* __restrict__ bih_lh, const float* __restrict__ bhh_lh,
                 const float* __restrict__ Wih_li, const float* __restrict__ Whh_li,
                 const float* __restrict__ bih_li, const float* __restrict__ bhh_li,
                 float* __restrict__ m_out, float* __restrict__ h_out,
                 float* __restrict__ hi_out) {
    extern __shared__ char dsm[];

    const int gtid = blockIdx.x * NT + threadIdx.x;
    const int nthr = gridDim.x * NT;
    const int gwarp = gtid >> 5;
    const int lane = threadIdx.x & 31;
    const int nwarp = nthr >> 5;

    // ==== I0: init states, weights, zero counters ====
    for (int i = gtid; i < NSTOCK * HID; i += nthr) {
        float hv = h_start[i & 255], pv = hi_start[i & 255];
        h_out[i] = hv; hi_out[i] = pv;
        g_h16[i] = __float2half_rn(hv);
        g_p16[i] = __float2half_rn(pv);
    }
    for (int i = gtid; i < NNEWS * HID; i += nthr) {
        float v = mc_start[i & 255];
        g_mc[i] = v;
        g_mc16[i] = __float2half_rn(v);
    }
    convW(Wih_li, OW_IH_LI, G3 * C_IN, gtid, nthr);
    convW(Whh_li, OW_HH_LI, G3 * HID,  gtid, nthr);
    convW(Wih_c,  OW_IH_C,  G3 * C_IN, gtid, nthr);
    convW(Whh_c,  OW_HH_C,  G3 * HID,  gtid, nthr);
    convW(Wih_lh, OW_IH_LH, G3 * CM,   gtid, nthr);
    convW(Whh_lh, OW_HH_LH, G3 * HID,  gtid, nthr);
    for (int i = gtid; i < NNE; i += nthr) g_inv_news_all[i] = 0.0f;
    for (int i = gtid; i < NSTE; i += nthr) { g_deg[i] = 0; }
    for (int i = gtid; i < SEQ_L; i += nthr) g_tot[i] = 0;
    for (size_t i = gtid; i < (size_t)NNE * C_IN; i += nthr) g_acc_news_all[i] = 0.0f;
    for (size_t i = gtid; i < (size_t)NSTE * C_IN; i += nthr) g_accmc_all[i] = 0.0f;
    grid_sync();
    // ==== I0b: degree counts ====
    for (int task = gtid; task < SEQ_L * NEDGE; task += nthr) {
        int t = task / NEDGE, e = task - t * NEDGE;
        const int* news = ei + (size_t)t * 2 * NEDGE;
        atomicAdd(&g_inv_news_all[t * NNEWS + news[e]], 1.0f);
        atomicAdd(&g_deg[t * NSTOCK + news[NEDGE + e]], 1);
    }
    grid_sync();
    // ==== I1: invert counts; CSR offsets; bulk scatter x -> news ====
    for (int i = gtid; i < NNE; i += nthr)
        g_inv_news_all[i] = 1.0f / fmaxf(g_inv_news_all[i], 1.0f);
    for (int i = gtid; i < NSTE; i += nthr) {
        int d = g_deg[i];
        g_inv_stock_all[i] = 1.0f / fmaxf((float)d, 1.0f);
        int off = atomicAdd(&g_tot[i / NSTOCK], d);
        g_csr_off[i] = off;
        g_cur[i] = off;
    }
    for (int task = gwarp; task < SEQ_L * NEDGE; task += nwarp) {
        int t = task / NEDGE, e = task - t * NEDGE;
        const int* news = ei + (size_t)t * 2 * NEDGE;
        int n = news[e], s = news[NEDGE + e];
        float4 v = ((const float4*)(inputs + ((size_t)t * NSTOCK + s) * C_IN))[lane];
        float* dst = g_acc_news_all + ((size_t)t * NNEWS + n) * C_IN + lane * 4;
        atomicAdd(dst + 0, v.x); atomicAdd(dst + 1, v.y);
        atomicAdd(dst + 2, v.z); atomicAdd(dst + 3, v.w);
    }
    grid_sync();
    // ==== I2: fill CSR edge lists; normalize center in place ====
    for (int task = gtid; task < SEQ_L * NEDGE; task += nthr) {
        int t = task / NEDGE, e = task - t * NEDGE;
        const int* news = ei + (size_t)t * 2 * NEDGE;
        int n = news[e], s = news[NEDGE + e];
        int slot = atomicAdd(&g_cur[t * NSTOCK + s], 1);
        g_csr_n[(size_t)t * NEDGE + slot] = n;
    }
    for (size_t i = gtid; i < (size_t)NNE * C_IN; i += nthr)
        g_acc_news_all[i] *= g_inv_news_all[i >> 7];
    grid_sync();
    // ==== I3: bulk GEMMs gi_li + gi_c (K=128) ====
    for (int tile = blockIdx.x; tile < BI3_TOT; tile += gridDim.x) {
        if (tile < 24000) {
            int mt = tile / 6, nt = tile % 6;
            gemm_f32A_h16(inputs, C_IN, g_Whi + OW_IH_LI, g_Wlo + OW_IH_LI, C_IN,
                          bih_li, g_gi_li_all, C_IN, NSTE, mt * 128, nt * 128, (uint16_t*)dsm);
        } else {
            int idx = tile - 24000, mt = idx / 6, nt = idx % 6;
            gemm_f32A_h16(g_acc_news_all, C_IN, g_Whi + OW_IH_C, g_Wlo + OW_IH_C, C_IN,
                          bih_c, g_gi_c_all, C_IN, NNE, mt * 128, nt * 128, (uint16_t*)dsm);
        }
    }
    grid_sync();
    // ==== I4: bulk scatter center -> stocks ====
    for (int task = gwarp; task < SEQ_L * NEDGE; task += nwarp) {
        int t = task / NEDGE, e = task - t * NEDGE;
        const int* news = ei + (size_t)t * 2 * NEDGE;
        int n = news[e], s = news[NEDGE + e];
        float4 v = ((const float4*)(g_acc_news_all + ((size_t)t * NNEWS + n) * C_IN))[lane];
        float* dst = g_accmc_all + ((size_t)t * NSTOCK + s) * C_IN + lane * 4;
        atomicAdd(dst + 0, v.x); atomicAdd(dst + 1, v.y);
        atomicAdd(dst + 2, v.z); atomicAdd(dst + 3, v.w);
    }
    grid_sync();
    // ==== I5: normalize mcenter in place; m_out center cols (t=63) ====
    for (size_t i = gtid; i < (size_t)NSTE * C_IN; i += nthr) {
        float v = g_accmc_all[i] * g_inv_stock_all[i >> 7];
        g_accmc_all[i] = v;
        if (i >= (size_t)63 * NSTOCK * C_IN) {
            size_t r = i - (size_t)63 * NSTOCK * C_IN;
            m_out[(r >> 7) * CM + (r & 127)] = v;
        }
    }
    grid_sync();
    // ==== I6: bulk GEMM gi_lh1 (K=128) ====
    for (int tile = blockIdx.x; tile < 24000; tile += gridDim.x) {
        int mt = tile / 6, nt = tile % 6;
        gemm_f32A_h16(g_accmc_all, C_IN, g_Whi + OW_IH_LH, g_Wlo + OW_IH_LH, CM,
                      bih_lh, g_gi_lh1_all, C_IN, NSTE, mt * 128, nt * 128, (uint16_t*)dsm);
    }
    grid_sync();

    // ==== sequential recurrence: K=256 fp16 2-term GEMMs, CSR gather ====
    for (int t = 0; t < SEQ_L; t++) {
        // ---- A: gh_li, gh_lh, gh_n ----
        for (int tile = blockIdx.x; tile < PA_TOT; tile += gridDim.x) {
            if (tile < ST_T) {
                int mt = tile / 6, nt = tile % 6;
                gemm_step(g_p16, HID, g_Whi + OW_HH_LI, g_Wlo + OW_HH_LI, HID,
                          bhh_li, nullptr, g_gh_li, HID, NSTOCK, mt * 128, nt * 128, dsm);
            } else if (tile < 2 * ST_T) {
                int idx = tile - ST_T, mt = idx / 6, nt = idx % 6;
                gemm_step(g_h16, HID, g_Whi + OW_HH_LH, g_Wlo + OW_HH_LH, HID,
                          bhh_lh, nullptr, g_gh_lh, HID, NSTOCK, mt * 128, nt * 128, dsm);
            } else {
                int idx = tile - 2 * ST_T, mt = idx / 6, nt = idx % 6;
                gemm_step(g_mc16, HID, g_Whi + OW_HH_C, g_Wlo + OW_HH_C, HID,
                          bhh_c, nullptr, g_gh_n, HID, NNEWS, mt * 128, nt * 128, dsm);
            }
        }
        grid_sync();

        // ---- B: gates m_c + h_input ----
        gate_hh(g_gi_c_all + (size_t)t * NNEWS * G3, g_gh_n,
                g_mc, g_mc16, NNEWS, gtid, nthr);
        gate_hh(g_gi_li_all + (size_t)t * NSTOCK * G3, g_gh_li,
                hi_out, g_p16, NSTOCK, gtid, nthr);
        grid_sync();

        // ---- C': CSR gather m_c (news -> stocks) + normalize -> fp16 ----
        for (int s = gwarp; s < NSTOCK; s += nwarp) {
            int base = t * NSTOCK + s;
            int off = g_csr_off[base], deg = g_deg[base];
            const int* en = g_csr_n + (size_t)t * NEDGE;
            float4 a0 = make_float4(0.f, 0.f, 0.f, 0.f);
            float4 a1 = make_float4(0.f, 0.f, 0.f, 0.f);
            for (int e = off; e < off + deg; e++) {
                int n = en[e];
                const float4* mp = (const float4*)(g_mc + (size_t)n * HID);
                float4 v0 = mp[lane], v1 = mp[lane + 32];
                a0.x += v0.x; a0.y += v0.y; a0.z += v0.z; a0.w += v0.w;
                a1.x += v1.x; a1.y += v1.y; a1.z += v1.z; a1.w += v1.w;
            }
            float inv = g_inv_stock_all[base];
            float vs[8] = {a0.x * inv, a0.y * inv, a0.z * inv, a0.w * inv,
                           a1.x * inv, a1.y * inv, a1.z * inv, a1.w * inv};
            int c0 = s * HID + lane * 4;
#pragma unroll
            for (int q = 0; q < 4; q++) {
                g_amc16[c0 + q] = __float2half_rn(vs[q]);
                g_amc16[c0 + 128 + q] = __float2half_rn(vs[4 + q]);
            }
            if (t == SEQ_L - 1) {
                float* mo = m_out + (size_t)s * CM + C_IN + lane * 4;
#pragma unroll
                for (int q = 0; q < 4; q++) { mo[q] = vs[q]; mo[128 + q] = vs[4 + q]; }
            }
        }
        grid_sync();

        // ---- E: gis = gi_lh1[t] + amc @ Wih_lh[:, 128:]^T ----
        for (int tile = blockIdx.x; tile < ST_T; tile += gridDim.x) {
            int mt = tile / 6, nt = tile % 6;
            gemm_step(g_amc16, HID,
                      g_Whi + OW_IH_LH + C_IN, g_Wlo + OW_IH_LH + C_IN, CM,
                      nullptr, g_gi_lh1_all + (size_t)t * NSTOCK * G3,
                      g_gis, HID, NSTOCK, mt * 128, nt * 128, dsm);
        }
        grid_sync();

        // ---- F: gate h ----
        gate_hh(g_gis, g_gh_lh, h_out, g_h16, NSTOCK, gtid, nthr);
        grid_sync();
    }
}

// ---------------- launch -----------------------------------------------------
extern "C" void kernel_launch(void* const* d_in, const int* in_sizes, int n_in,
                              void* d_out, int out_size) {
    const float* inputs   = (const float*)d_in[0];
    const int*   ei       = (const int*)d_in[1];
    const float* h_start  = (const float*)d_in[2];
    const float* hi_start = (const float*)d_in[3];
    const float* mc_start = (const float*)d_in[4];
    const float* Wih_c  = (const float*)d_in[5];
    const float* Whh_c  = (const float*)d_in[6];
    const float* bih_c  = (const float*)d_in[7];
    const float* bhh_c  = (const float*)d_in[8];
    const float* Wih_lh = (const float*)d_in[9];
    const float* Whh_lh = (const float*)d_in[10];
    const float* bih_lh = (const float*)d_in[11];
    const float* bhh_lh = (const float*)d_in[12];
    const float* Wih_li = (const float*)d_in[13];
    const float* Whh_li = (const float*)d_in[14];
    const float* bih_li = (const float*)d_in[15];
    const float* bhh_li = (const float*)d_in[16];

    float* out    = (float*)d_out;
    float* m_out  = out;
    float* h_out  = out + (size_t)NSTOCK * CM;
    float* hi_out = h_out + (size_t)NSTOCK * HID;

    cudaFuncSetAttribute(mega_kernel, cudaFuncAttributeMaxDynamicSharedMemorySize, SMEM_BYTES);

    int dev = 0, nsm = 0, occ = 0;
    cudaGetDevice(&dev);
    cudaDeviceGetAttribute(&nsm, cudaDevAttrMultiProcessorCount, dev);
    cudaOccupancyMaxActiveBlocksPerMultiprocessor(&occ, mega_kernel, NT, SMEM_BYTES);
    if (occ < 1) occ = 1;
    int nblk = nsm * occ;

    unsigned* bar = nullptr;
    cudaGetSymbolAddress((void**)&bar, g_bar_count);
    cudaMemsetAsync(bar, 0, sizeof(unsigned));

    mega_kernel<<<nblk, NT, SMEM_BYTES>>>(inputs, ei, h_start, hi_start, mc_start,
                                          Wih_c, Whh_c, bih_c, bhh_c,
                                          Wih_lh, Whh_lh, bih_lh, bhh_lh,
                                          Wih_li, Whh_li, bih_li, bhh_li,
                                          m_out, h_out, hi_out);
}

// round 14
// speedup vs baseline: 3.4927x; 1.1235x over previous
#include <cuda_runtime.h>
#include <cuda_bf16.h>
#include <cuda_fp16.h>
#include <math.h>
#include <stdint.h>

#define SEQ_L 64
#define NSTOCK 8000
#define NNEWS 1600
#define C_IN 128
#define HID 256
#define NEDGE 32000
#define G3 768
#define CM 384
#define NT 256
#define NSTE 512000
#define NNE  102400

// per-step cp.async GEMM: BK=32, 3-stage, 2 operand arrays (A, B)
#define BKP32 40
#define SA_ELEM (128 * BKP32)
#define SA_SZ (SA_ELEM * 2)            // 10240 B
#define STAGE_SZ (2 * SA_SZ)           // 20480 B
#define SMEM_BYTES (3 * STAGE_SZ)      // 61440 B
// bulk single-buffer GEMM: BK=64, 2 arrays of 128*BKP halves (36864 B)
#define BKP 72

// ---- weight fp16 offsets (elements) -----------------------------------------
#define OW_IH_LI 0
#define OW_HH_LI 98304
#define OW_IH_C  294912
#define OW_HH_C  393216
#define OW_IH_LH 589824
#define OW_HH_LH 884736
#define W_TOTAL  1081344

// ---------------- static device scratch (~2GB, linker-safe) ------------------
__device__ __align__(16) float g_acc_news_all[(size_t)NNE * C_IN];
__device__ __align__(16) float g_accmc_all[(size_t)NSTE * C_IN];
__device__ __align__(16) __half g_gi_li_all[(size_t)NSTE * G3];
__device__ __align__(16) __half g_gi_c_all[(size_t)NNE * G3];
__device__ __align__(16) __half g_gi_lh1_all[(size_t)NSTE * G3];
__device__ float g_inv_news_all[NNE];
__device__ float g_inv_stock_all[NSTE];
// CSR (stock-destination sorted edges, per t)
__device__ int g_deg[NSTE];
__device__ int g_csr_off[NSTE];
__device__ int g_cur[NSTE];
__device__ int g_csr_n[SEQ_L * NEDGE];
__device__ int g_tot[SEQ_L];
// per-step state (fp32 master + fp16 GEMM operand copies)
__device__ __align__(16) float g_mc[NNEWS * HID];
__device__ __align__(16) __half g_mc16[NNEWS * HID];
__device__ __align__(16) __half g_h16[NSTOCK * HID];
__device__ __align__(16) __half g_p16[NSTOCK * HID];
__device__ __align__(16) __half g_amc16[NSTOCK * HID];
__device__ __align__(16) __half g_gh_li[NSTOCK * G3];
__device__ __align__(16) __half g_gh_lh[NSTOCK * G3];
__device__ __align__(16) __half g_gh_n[NNEWS * G3];
__device__ __align__(16) __half g_gis[NSTOCK * G3];
__device__ __align__(16) __half g_Whi[W_TOTAL];
__device__ unsigned g_bar_count = 0;

// ---------------- software grid barrier (monotonic) --------------------------
__device__ __forceinline__ void grid_sync() {
    __syncthreads();
    __threadfence();
    if (threadIdx.x == 0) {
        unsigned G = gridDim.x;
        unsigned arrival = atomicAdd(&g_bar_count, 1u) + 1u;
        unsigned target = ((arrival + G - 1u) / G) * G;
        volatile unsigned* vc = &g_bar_count;
        while (*vc < target) { __nanosleep(32); }
    }
    __syncthreads();
    __threadfence();
}

__device__ __forceinline__ void mma_f16(float* c, const uint32_t* a, const uint32_t* b) {
    asm volatile("mma.sync.aligned.m16n8k16.row.col.f32.f16.f16.f32 "
                 "{%0,%1,%2,%3}, {%4,%5,%6,%7}, {%8,%9}, {%0,%1,%2,%3};"
                 : "+f"(c[0]), "+f"(c[1]), "+f"(c[2]), "+f"(c[3])
                 : "r"(a[0]), "r"(a[1]), "r"(a[2]), "r"(a[3]), "r"(b[0]), "r"(b[1]));
}

__device__ __forceinline__ void ldsm_x4(uint32_t addr, uint32_t* r) {
    asm volatile("ldmatrix.sync.aligned.m8n8.x4.shared.b16 {%0,%1,%2,%3}, [%4];"
                 : "=r"(r[0]), "=r"(r[1]), "=r"(r[2]), "=r"(r[3]) : "r"(addr));
}
__device__ __forceinline__ void ldsm_x2(uint32_t addr, uint32_t* r) {
    asm volatile("ldmatrix.sync.aligned.m8n8.x2.shared.b16 {%0,%1}, [%2];"
                 : "=r"(r[0]), "=r"(r[1]) : "r"(addr));
}

struct Acc { float v[4][4][4]; };

// ---------------- fp16 fragment compute over one staged chunk ----------------
template <int BK, int KP>
__device__ __forceinline__ void mma_chunk_l(uint32_t sA, uint32_t sB,
                                            uint32_t aoff, uint32_t boff, Acc& A) {
#pragma unroll
    for (int kk = 0; kk < BK; kk += 16) {
        uint32_t bh[4][2], af[4][4];
#pragma unroll
        for (int nf = 0; nf < 4; nf++)
            ldsm_x2(sB + boff + (nf * 8 * KP + kk) * 2, bh[nf]);
#pragma unroll
        for (int mf = 0; mf < 4; mf++)
            ldsm_x4(sA + aoff + (mf * 16 * KP + kk) * 2, af[mf]);
#pragma unroll
        for (int nf = 0; nf < 4; nf++)
#pragma unroll
            for (int mf = 0; mf < 4; mf++)
                mma_f16(A.v[mf][nf], af[mf], bh[nf]);
    }
}

// lane-dependent ldmatrix offsets (bytes) for row-major [row][k] smem tiles
template <int KP>
__device__ __forceinline__ uint32_t mk_aoff(int mbase, int lane) {
    int arow = (lane & 7) + ((lane >> 3) & 1) * 8;
    int acol = (lane >> 4) * 8;
    return (uint32_t)(((mbase + arow) * KP + acol) * 2);
}
template <int KP>
__device__ __forceinline__ uint32_t mk_boff(int nbase, int lane) {
    int brow = lane & 7;
    int bcol = ((lane >> 3) & 1) * 8;
    return (uint32_t)(((nbase + brow) * KP + bcol) * 2);
}

// ---------------- per-step GEMM: cp.async 3-stage, fp16, fp16 out ------------
__device__ void gemm_step(const __half* __restrict__ A, int lda,
                          const __half* __restrict__ Wh, int ldw,
                          const float* __restrict__ bias,
                          const __half* __restrict__ pre,
                          __half* __restrict__ Cc, int K, int M, int m0, int n0,
                          char* dsm) {
    const int tid = threadIdx.x;
    const int w = tid >> 5, lane = tid & 31;
    const int g = lane >> 2, t4 = lane & 3;
    const int mbase = (w >> 2) * 64, nbase = (w & 3) * 32;
    const uint32_t sb0 = (uint32_t)__cvta_generic_to_shared(dsm);
    const uint32_t aoff = mk_aoff<BKP32>(mbase, lane);
    const uint32_t boff = mk_boff<BKP32>(nbase, lane);
    Acc acc;
#pragma unroll
    for (int i = 0; i < 4; i++)
#pragma unroll
        for (int j = 0; j < 4; j++)
#pragma unroll
            for (int q = 0; q < 4; q++) acc.v[i][j][q] = 0.0f;

    const int NC = K >> 5;
    auto stage = [&](int c) {
        uint32_t sb = sb0 + (c % 3) * STAGE_SZ;
        int kt = c << 5;
        for (int it = tid; it < 512; it += NT) {
            int row = it >> 2;
            int c8 = (it & 3) << 3;
            int mm = m0 + row; if (mm >= M) mm = M - 1;
            const void* ga = A + (size_t)mm * lda + kt + c8;
            const void* gb = Wh + (size_t)(n0 + row) * ldw + kt + c8;
            uint32_t so = sb + (row * BKP32 + c8) * 2;
            asm volatile("cp.async.ca.shared.global [%0], [%1], 16;" :: "r"(so), "l"(ga));
            asm volatile("cp.async.ca.shared.global [%0], [%1], 16;" :: "r"(so + SA_SZ), "l"(gb));
        }
        asm volatile("cp.async.commit_group;");
    };

    stage(0);
    if (NC > 1) stage(1);
    for (int c = 0; c < NC; c++) {
        if (c + 2 < NC) {
            stage(c + 2);
            asm volatile("cp.async.wait_group 2;");
        } else if (c + 1 < NC) {
            asm volatile("cp.async.wait_group 1;");
        } else {
            asm volatile("cp.async.wait_group 0;");
        }
        __syncthreads();
        uint32_t st = sb0 + (c % 3) * STAGE_SZ;
        mma_chunk_l<32, BKP32>(st, st + SA_SZ, aoff, boff, acc);
        __syncthreads();
    }
#pragma unroll
    for (int mf = 0; mf < 4; mf++) {
#pragma unroll
        for (int nf = 0; nf < 4; nf++) {
            int m = m0 + mbase + mf * 16 + g;
            int n = n0 + nbase + nf * 8 + 2 * t4;
            if (pre == nullptr) {
                float b0 = bias[n], b1 = bias[n + 1];
                if (m < M)
                    *(__half2*)(Cc + (size_t)m * G3 + n) =
                        __floats2half2_rn(acc.v[mf][nf][0] + b0, acc.v[mf][nf][1] + b1);
                if (m + 8 < M)
                    *(__half2*)(Cc + (size_t)(m + 8) * G3 + n) =
                        __floats2half2_rn(acc.v[mf][nf][2] + b0, acc.v[mf][nf][3] + b1);
            } else {
                if (m < M) {
                    float2 p = __half22float2(*(const __half2*)(pre + (size_t)m * G3 + n));
                    *(__half2*)(Cc + (size_t)m * G3 + n) =
                        __floats2half2_rn(acc.v[mf][nf][0] + p.x, acc.v[mf][nf][1] + p.y);
                }
                if (m + 8 < M) {
                    float2 p = __half22float2(*(const __half2*)(pre + (size_t)(m + 8) * G3 + n));
                    *(__half2*)(Cc + (size_t)(m + 8) * G3 + n) =
                        __floats2half2_rn(acc.v[mf][nf][2] + p.x, acc.v[mf][nf][3] + p.y);
                }
            }
        }
    }
    __syncthreads();
}

// ---------------- bulk GEMM: fp32 A -> fp16 on the fly, fp16 out -------------
__device__ void gemm_f32A_h16(const float* __restrict__ A, int lda,
                              const __half* __restrict__ Wh, int ldw,
                              const float* __restrict__ bias,
                              __half* __restrict__ Cc, int K, int M, int m0, int n0,
                              uint16_t* sm) {
    uint16_t* sA = sm;
    uint16_t* sB = sm + 128 * BKP;
    const int tid = threadIdx.x;
    const int w = tid >> 5, lane = tid & 31;
    const int g = lane >> 2, t4 = lane & 3;
    const int mbase = (w >> 2) * 64, nbase = (w & 3) * 32;
    const uint32_t sb = (uint32_t)__cvta_generic_to_shared(sm);
    const uint32_t aoff = mk_aoff<BKP>(mbase, lane);
    const uint32_t boff = mk_boff<BKP>(nbase, lane);
    const uint32_t asz = 128 * BKP * 2;
    Acc acc;
#pragma unroll
    for (int i = 0; i < 4; i++)
#pragma unroll
        for (int j = 0; j < 4; j++)
#pragma unroll
            for (int q = 0; q < 4; q++) acc.v[i][j][q] = 0.0f;

    for (int kt = 0; kt < K; kt += 64) {
        for (int it = tid; it < 1024; it += NT) {
            int row = it >> 3;
            int c8 = (it & 7) << 3;
            int mm = m0 + row; if (mm >= M) mm = M - 1;
            const float* ap = A + (size_t)mm * lda + kt + c8;
            float4 v0 = *(const float4*)ap;
            float4 v1 = *(const float4*)(ap + 4);
            __half hv[8];
            hv[0] = __float2half_rn(v0.x); hv[1] = __float2half_rn(v0.y);
            hv[2] = __float2half_rn(v0.z); hv[3] = __float2half_rn(v0.w);
            hv[4] = __float2half_rn(v1.x); hv[5] = __float2half_rn(v1.y);
            hv[6] = __float2half_rn(v1.z); hv[7] = __float2half_rn(v1.w);
            int so = row * BKP + c8;
            *(uint4*)(sA + so) = *(const uint4*)hv;
            size_t bo = (size_t)(n0 + row) * ldw + kt + c8;
            *(uint4*)(sB + so) = *(const uint4*)(Wh + bo);
        }
        __syncthreads();
        mma_chunk_l<64, BKP>(sb, sb + asz, aoff, boff, acc);
        __syncthreads();
    }
#pragma unroll
    for (int mf = 0; mf < 4; mf++) {
#pragma unroll
        for (int nf = 0; nf < 4; nf++) {
            int m = m0 + mbase + mf * 16 + g;
            int n = n0 + nbase + nf * 8 + 2 * t4;
            float b0 = bias[n], b1 = bias[n + 1];
            if (m < M)
                *(__half2*)(Cc + (size_t)m * G3 + n) =
                    __floats2half2_rn(acc.v[mf][nf][0] + b0, acc.v[mf][nf][1] + b1);
            if (m + 8 < M)
                *(__half2*)(Cc + (size_t)(m + 8) * G3 + n) =
                    __floats2half2_rn(acc.v[mf][nf][2] + b0, acc.v[mf][nf][3] + b1);
        }
    }
    __syncthreads();
}

// ---------------- GRU gate (fp16 gi + fp16 gh -> fp32 master + fp16 state) ---
__device__ __forceinline__ void gate_hh(const __half* __restrict__ gi,
                                        const __half* __restrict__ gh,
                                        float* __restrict__ hf,
                                        __half* __restrict__ h16,
                                        int M, int gtid, int nthr) {
    int total = M * HID;
    for (int idx = gtid; idx < total; idx += nthr) {
        int m = idx >> 8;
        int j = idx & 255;
        const __half* gim = gi + (size_t)m * G3;
        const __half* ghm = gh + (size_t)m * G3;
        float r = 1.0f / (1.0f + __expf(-(__half2float(gim[j]) + __half2float(ghm[j]))));
        float z = 1.0f / (1.0f + __expf(-(__half2float(gim[HID + j]) + __half2float(ghm[HID + j]))));
        float n = tanhf(__half2float(gim[2 * HID + j]) + r * __half2float(ghm[2 * HID + j]));
        float v = (1.0f - z) * n + z * hf[idx];
        hf[idx] = v;
        h16[idx] = __float2half_rn(v);
    }
}

__device__ __forceinline__ void convW(const float* __restrict__ W, int off, int n,
                                      int gtid, int nthr) {
    for (int i = gtid; i < n; i += nthr)
        g_Whi[off + i] = __float2half_rn(W[i]);
}

#define ST_T 378
#define NW_T 78
#define PA_TOT (ST_T * 2 + NW_T)
#define BI3_TOT (24000 + 4800)

// ---------------- the persistent mega-kernel ---------------------------------
__global__ __launch_bounds__(NT, 2)
void mega_kernel(const float* __restrict__ inputs, const int* __restrict__ ei,
                 const float* __restrict__ h_start, const float* __restrict__ hi_start,
                 const float* __restrict__ mc_start,
                 const float* __restrict__ Wih_c,  const float* __restrict__ Whh_c,
                 const float* __restrict__ bih_c,  const float* __restrict__ bhh_c,
                 const float* __restrict__ Wih_lh, const float* __restrict__ Whh_lh,
                 const float* __restrict__ bih_lh, const float* __restrict__ bhh_lh,
                 const float* __restrict__ Wih_li, const float* __restrict__ Whh_li,
                 const float* __restrict__ bih_li, const float* __restrict__ bhh_li,
                 float* __restrict__ m_out, float* __restrict__ h_out,
                 float* __restrict__ hi_out) {
    extern __shared__ char dsm[];

    const int gtid = blockIdx.x * NT + threadIdx.x;
    const int nthr = gridDim.x * NT;
    const int gwarp = gtid >> 5;
    const int lane = threadIdx.x & 31;
    const int nwarp = nthr >> 5;

    // ==== I0: init states, weights, zero counters ====
    for (int i = gtid; i < NSTOCK * HID; i += nthr) {
        float hv = h_start[i & 255], pv = hi_start[i & 255];
        h_out[i] = hv; hi_out[i] = pv;
        g_h16[i] = __float2half_rn(hv);
        g_p16[i] = __float2half_rn(pv);
    }
    for (int i = gtid; i < NNEWS * HID; i += nthr) {
        float v = mc_start[i & 255];
        g_mc[i] = v;
        g_mc16[i] = __float2half_rn(v);
    }
    convW(Wih_li, OW_IH_LI, G3 * C_IN, gtid, nthr);
    convW(Whh_li, OW_HH_LI, G3 * HID,  gtid, nthr);
    convW(Wih_c,  OW_IH_C,  G3 * C_IN, gtid, nthr);
    convW(Whh_c,  OW_HH_C,  G3 * HID,  gtid, nthr);
    convW(Wih_lh, OW_IH_LH, G3 * CM,   gtid, nthr);
    convW(Whh_lh, OW_HH_LH, G3 * HID,  gtid, nthr);
    for (int i = gtid; i < NNE; i += nthr) g_inv_news_all[i] = 0.0f;
    for (int i = gtid; i < NSTE; i += nthr) { g_deg[i] = 0; }
    for (int i = gtid; i < SEQ_L; i += nthr) g_tot[i] = 0;
    for (size_t i = gtid; i < (size_t)NNE * C_IN; i += nthr) g_acc_news_all[i] = 0.0f;
    for (size_t i = gtid; i < (size_t)NSTE * C_IN; i += nthr) g_accmc_all[i] = 0.0f;
    grid_sync();
    // ==== I0b: degree counts ====
    for (int task = gtid; task < SEQ_L * NEDGE; task += nthr) {
        int t = task / NEDGE, e = task - t * NEDGE;
        const int* news = ei + (size_t)t * 2 * NEDGE;
        atomicAdd(&g_inv_news_all[t * NNEWS + news[e]], 1.0f);
        atomicAdd(&g_deg[t * NSTOCK + news[NEDGE + e]], 1);
    }
    grid_sync();
    // ==== I1: invert counts; CSR offsets; bulk scatter x -> news ====
    for (int i = gtid; i < NNE; i += nthr)
        g_inv_news_all[i] = 1.0f / fmaxf(g_inv_news_all[i], 1.0f);
    for (int i = gtid; i < NSTE; i += nthr) {
        int d = g_deg[i];
        g_inv_stock_all[i] = 1.0f / fmaxf((float)d, 1.0f);
        int off = atomicAdd(&g_tot[i / NSTOCK], d);
        g_csr_off[i] = off;
        g_cur[i] = off;
    }
    for (int task = gwarp; task < SEQ_L * NEDGE; task += nwarp) {
        int t = task / NEDGE, e = task - t * NEDGE;
        const int* news = ei + (size_t)t * 2 * NEDGE;
        int n = news[e], s = news[NEDGE + e];
        float4 v = ((const float4*)(inputs + ((size_t)t * NSTOCK + s) * C_IN))[lane];
        float* dst = g_acc_news_all + ((size_t)t * NNEWS + n) * C_IN + lane * 4;
        atomicAdd(dst + 0, v.x); atomicAdd(dst + 1, v.y);
        atomicAdd(dst + 2, v.z); atomicAdd(dst + 3, v.w);
    }
    grid_sync();
    // ==== I2: fill CSR edge lists; normalize center in place ====
    for (int task = gtid; task < SEQ_L * NEDGE; task += nthr) {
        int t = task / NEDGE, e = task - t * NEDGE;
        const int* news = ei + (size_t)t * 2 * NEDGE;
        int n = news[e], s = news[NEDGE + e];
        int slot = atomicAdd(&g_cur[t * NSTOCK + s], 1);
        g_csr_n[(size_t)t * NEDGE + slot] = n;
    }
    for (size_t i = gtid; i < (size_t)NNE * C_IN; i += nthr)
        g_acc_news_all[i] *= g_inv_news_all[i >> 7];
    grid_sync();
    // ==== I3: bulk GEMMs gi_li + gi_c (K=128) ====
    for (int tile = blockIdx.x; tile < BI3_TOT; tile += gridDim.x) {
        if (tile < 24000) {
            int mt = tile / 6, nt = tile % 6;
            gemm_f32A_h16(inputs, C_IN, g_Whi + OW_IH_LI, C_IN,
                          bih_li, g_gi_li_all, C_IN, NSTE, mt * 128, nt * 128, (uint16_t*)dsm);
        } else {
            int idx = tile - 24000, mt = idx / 6, nt = idx % 6;
            gemm_f32A_h16(g_acc_news_all, C_IN, g_Whi + OW_IH_C, C_IN,
                          bih_c, g_gi_c_all, C_IN, NNE, mt * 128, nt * 128, (uint16_t*)dsm);
        }
    }
    grid_sync();
    // ==== I4: bulk scatter center -> stocks ====
    for (int task = gwarp; task < SEQ_L * NEDGE; task += nwarp) {
        int t = task / NEDGE, e = task - t * NEDGE;
        const int* news = ei + (size_t)t * 2 * NEDGE;
        int n = news[e], s = news[NEDGE + e];
        float4 v = ((const float4*)(g_acc_news_all + ((size_t)t * NNEWS + n) * C_IN))[lane];
        float* dst = g_accmc_all + ((size_t)t * NSTOCK + s) * C_IN + lane * 4;
        atomicAdd(dst + 0, v.x); atomicAdd(dst + 1, v.y);
        atomicAdd(dst + 2, v.z); atomicAdd(dst + 3, v.w);
    }
    grid_sync();
    // ==== I5: normalize mcenter in place; m_out center cols (t=63) ====
    for (size_t i = gtid; i < (size_t)NSTE * C_IN; i += nthr) {
        float v = g_accmc_all[i] * g_inv_stock_all[i >> 7];
        g_accmc_all[i] = v;
        if (i >= (size_t)63 * NSTOCK * C_IN) {
            size_t r = i - (size_t)63 * NSTOCK * C_IN;
            m_out[(r >> 7) * CM + (r & 127)] = v;
        }
    }
    grid_sync();
    // ==== I6: bulk GEMM gi_lh1 (K=128) ====
    for (int tile = blockIdx.x; tile < 24000; tile += gridDim.x) {
        int mt = tile / 6, nt = tile % 6;
        gemm_f32A_h16(g_accmc_all, C_IN, g_Whi + OW_IH_LH, CM,
                      bih_lh, g_gi_lh1_all, C_IN, NSTE, mt * 128, nt * 128, (uint16_t*)dsm);
    }
    grid_sync();

    // ==== sequential recurrence: K=256 fp16 GEMMs, CSR gather ====
    for (int t = 0; t < SEQ_L; t++) {
        // ---- A: gh_li, gh_lh, gh_n ----
        for (int tile = blockIdx.x; tile < PA_TOT; tile += gridDim.x) {
            if (tile < ST_T) {
                int mt = tile / 6, nt = tile % 6;
                gemm_step(g_p16, HID, g_Whi + OW_HH_LI, HID,
                          bhh_li, nullptr, g_gh_li, HID, NSTOCK, mt * 128, nt * 128, dsm);
            } else if (tile < 2 * ST_T) {
                int idx = tile - ST_T, mt = idx / 6, nt = idx % 6;
                gemm_step(g_h16, HID, g_Whi + OW_HH_LH, HID,
                          bhh_lh, nullptr, g_gh_lh, HID, NSTOCK, mt * 128, nt * 128, dsm);
            } else {
                int idx = tile - 2 * ST_T, mt = idx / 6, nt = idx % 6;
                gemm_step(g_mc16, HID, g_Whi + OW_HH_C, HID,
                          bhh_c, nullptr, g_gh_n, HID, NNEWS, mt * 128, nt * 128, dsm);
            }
        }
        grid_sync();

        // ---- B: gates m_c + h_input ----
        gate_hh(g_gi_c_all + (size_t)t * NNEWS * G3, g_gh_n,
                g_mc, g_mc16, NNEWS, gtid, nthr);
        gate_hh(g_gi_li_all + (size_t)t * NSTOCK * G3, g_gh_li,
                hi_out, g_p16, NSTOCK, gtid, nthr);
        grid_sync();

        // ---- C': CSR gather m_c (news -> stocks) + normalize -> fp16 ----
        for (int s = gwarp; s < NSTOCK; s += nwarp) {
            int base = t * NSTOCK + s;
            int off = g_csr_off[base], deg = g_deg[base];
            const int* en = g_csr_n + (size_t)t * NEDGE;
            float4 a0 = make_float4(0.f, 0.f, 0.f, 0.f);
            float4 a1 = make_float4(0.f, 0.f, 0.f, 0.f);
            for (int e = off; e < off + deg; e++) {
                int n = en[e];
                const float4* mp = (const float4*)(g_mc + (size_t)n * HID);
                float4 v0 = mp[lane], v1 = mp[lane + 32];
                a0.x += v0.x; a0.y += v0.y; a0.z += v0.z; a0.w += v0.w;
                a1.x += v1.x; a1.y += v1.y; a1.z += v1.z; a1.w += v1.w;
            }
            float inv = g_inv_stock_all[base];
            float vs[8] = {a0.x * inv, a0.y * inv, a0.z * inv, a0.w * inv,
                           a1.x * inv, a1.y * inv, a1.z * inv, a1.w * inv};
            int c0 = s * HID + lane * 4;
#pragma unroll
            for (int q = 0; q < 4; q++) {
                g_amc16[c0 + q] = __float2half_rn(vs[q]);
                g_amc16[c0 + 128 + q] = __float2half_rn(vs[4 + q]);
            }
            if (t == SEQ_L - 1) {
                float* mo = m_out + (size_t)s * CM + C_IN + lane * 4;
#pragma unroll
                for (int q = 0; q < 4; q++) { mo[q] = vs[q]; mo[128 + q] = vs[4 + q]; }
            }
        }
        grid_sync();

        // ---- E: gis = gi_lh1[t] + amc @ Wih_lh[:, 128:]^T ----
        for (int tile = blockIdx.x; tile < ST_T; tile += gridDim.x) {
            int mt = tile / 6, nt = tile % 6;
            gemm_step(g_amc16, HID, g_Whi + OW_IH_LH + C_IN, CM,
                      nullptr, g_gi_lh1_all + (size_t)t * NSTOCK * G3,
                      g_gis, HID, NSTOCK, mt * 128, nt * 128, dsm);
        }
        grid_sync();

        // ---- F: gate h ----
        gate_hh(g_gis, g_gh_lh, h_out, g_h16, NSTOCK, gtid, nthr);
        grid_sync();
    }
}

// ---------------- launch -----------------------------------------------------
extern "C" void kernel_launch(void* const* d_in, const int* in_sizes, int n_in,
                              void* d_out, int out_size) {
    const float* inputs   = (const float*)d_in[0];
    const int*   ei       = (const int*)d_in[1];
    const float* h_start  = (const float*)d_in[2];
    const float* hi_start = (const float*)d_in[3];
    const float* mc_start = (const float*)d_in[4];
    const float* Wih_c  = (const float*)d_in[5];
    const float* Whh_c  = (const float*)d_in[6];
    const float* bih_c  = (const float*)d_in[7];
    const float* bhh_c  = (const float*)d_in[8];
    const float* Wih_lh = (const float*)d_in[9];
    const float* Whh_lh = (const float*)d_in[10];
    const float* bih_lh = (const float*)d_in[11];
    const float* bhh_lh = (const float*)d_in[12];
    const float* Wih_li = (const float*)d_in[13];
    const float* Whh_li = (const float*)d_in[14];
    const float* bih_li = (const float*)d_in[15];
    const float* bhh_li = (const float*)d_in[16];

    float* out    = (float*)d_out;
    float* m_out  = out;
    float* h_out  = out + (size_t)NSTOCK * CM;
    float* hi_out = h_out + (size_t)NSTOCK * HID;

    cudaFuncSetAttribute(mega_kernel, cudaFuncAttributeMaxDynamicSharedMemorySize, SMEM_BYTES);

    int dev = 0, nsm = 0, occ = 0;
    cudaGetDevice(&dev);
    cudaDeviceGetAttribute(&nsm, cudaDevAttrMultiProcessorCount, dev);
    cudaOccupancyMaxActiveBlocksPerMultiprocessor(&occ, mega_kernel, NT, SMEM_BYTES);
    if (occ < 1) occ = 1;
    int nblk = nsm * occ;

    unsigned* bar = nullptr;
    cudaGetSymbolAddress((void**)&bar, g_bar_count);
    cudaMemsetAsync(bar, 0, sizeof(unsigned));

    mega_kernel<<<nblk, NT, SMEM_BYTES>>>(inputs, ei, h_start, hi_start, mc_start,
                                          Wih_c, Whh_c, bih_c, bhh_c,
                                          Wih_lh, Whh_lh, bih_lh, bhh_lh,
                                          Wih_li, Whh_li, bih_li, bhh_li,
                                          m_out, h_out, hi_out);
}

// round 15
// speedup vs baseline: 3.8025x; 1.0887x over previous
#include <cuda_runtime.h>
#include <cuda_bf16.h>
#include <cuda_fp16.h>
#include <math.h>
#include <stdint.h>

#define SEQ_L 64
#define NSTOCK 8000
#define NNEWS 1600
#define C_IN 128
#define HID 256
#define NEDGE 32000
#define G3 768
#define CM 384
#define NT 256
#define NSTE 512000
#define NNE  102400

// GEMM tiles: BM=128, BN=64, BK=32, 3-stage cp.async
#define BKP32 40
#define SA_SZ (128 * BKP32 * 2)        // 10240 B (A: 128 rows)
#define SB_SZ (64 * BKP32 * 2)         // 5120 B  (B: 64 rows)
#define STAGE_SZ (SA_SZ + SB_SZ)       // 15360 B
#define SMEM_BYTES (3 * STAGE_SZ)      // 46080 B -> 3 CTAs/SM by smem

// ---- weight fp16 offsets (elements) -----------------------------------------
#define OW_IH_LI 0
#define OW_HH_LI 98304
#define OW_IH_C  294912
#define OW_HH_C  393216
#define OW_IH_LH 589824
#define OW_HH_LH 884736
#define W_TOTAL  1081344

// ---------------- static device scratch (~2.4GB, linker-safe) ----------------
__device__ __align__(16) float g_acc_news_all[(size_t)NNE * C_IN];
__device__ __align__(16) float g_accmc_all[(size_t)NSTE * C_IN];
__device__ __align__(16) __half g_x16[(size_t)NSTE * C_IN];
__device__ __align__(16) __half g_cen16[(size_t)NNE * C_IN];
__device__ __align__(16) __half g_mce16[(size_t)NSTE * C_IN];
__device__ __align__(16) __half g_gi_li_all[(size_t)NSTE * G3];
__device__ __align__(16) __half g_gi_c_all[(size_t)NNE * G3];
__device__ __align__(16) __half g_gi_lh1_all[(size_t)NSTE * G3];
__device__ float g_inv_news_all[NNE];
__device__ float g_inv_stock_all[NSTE];
// CSR (stock-destination sorted edges, per t)
__device__ int g_deg[NSTE];
__device__ int g_csr_off[NSTE];
__device__ int g_cur[NSTE];
__device__ int g_csr_n[SEQ_L * NEDGE];
__device__ int g_tot[SEQ_L];
// per-step state (fp32 master + fp16 GEMM operand copies)
__device__ __align__(16) float g_mc[NNEWS * HID];
__device__ __align__(16) __half g_mc16[NNEWS * HID];
__device__ __align__(16) __half g_h16[NSTOCK * HID];
__device__ __align__(16) __half g_p16[NSTOCK * HID];
__device__ __align__(16) __half g_amc16[NSTOCK * HID];
__device__ __align__(16) __half g_gh_li[NSTOCK * G3];
__device__ __align__(16) __half g_gh_lh[NSTOCK * G3];
__device__ __align__(16) __half g_gh_n[NNEWS * G3];
__device__ __align__(16) __half g_gis[NSTOCK * G3];
__device__ __align__(16) __half g_Whi[W_TOTAL];
__device__ unsigned g_bar_count = 0;

// ---------------- software grid barrier (monotonic) --------------------------
__device__ __forceinline__ void grid_sync() {
    __syncthreads();
    __threadfence();
    if (threadIdx.x == 0) {
        unsigned G = gridDim.x;
        unsigned arrival = atomicAdd(&g_bar_count, 1u) + 1u;
        unsigned target = ((arrival + G - 1u) / G) * G;
        volatile unsigned* vc = &g_bar_count;
        while (*vc < target) { __nanosleep(32); }
    }
    __syncthreads();
    __threadfence();
}

__device__ __forceinline__ void mma_f16(float* c, const uint32_t* a, const uint32_t* b) {
    asm volatile("mma.sync.aligned.m16n8k16.row.col.f32.f16.f16.f32 "
                 "{%0,%1,%2,%3}, {%4,%5,%6,%7}, {%8,%9}, {%0,%1,%2,%3};"
                 : "+f"(c[0]), "+f"(c[1]), "+f"(c[2]), "+f"(c[3])
                 : "r"(a[0]), "r"(a[1]), "r"(a[2]), "r"(a[3]), "r"(b[0]), "r"(b[1]));
}

__device__ __forceinline__ void ldsm_x4(uint32_t addr, uint32_t* r) {
    asm volatile("ldmatrix.sync.aligned.m8n8.x4.shared.b16 {%0,%1,%2,%3}, [%4];"
                 : "=r"(r[0]), "=r"(r[1]), "=r"(r[2]), "=r"(r[3]) : "r"(addr));
}
__device__ __forceinline__ void ldsm_x2(uint32_t addr, uint32_t* r) {
    asm volatile("ldmatrix.sync.aligned.m8n8.x2.shared.b16 {%0,%1}, [%2];"
                 : "=r"(r[0]), "=r"(r[1]) : "r"(addr));
}

struct Acc { float v[2][4][4]; };   // 32 regs: 2 m-frags x 4 n-frags

// ---------------- fp16 fragment compute over one staged chunk ----------------
// Warp layout: 8 warps as 4(M) x 2(N); each warp owns 32 rows x 32 cols.
template <int BK, int KP>
__device__ __forceinline__ void mma_chunk_l(uint32_t sA, uint32_t sB,
                                            uint32_t aoff, uint32_t boff, Acc& A) {
#pragma unroll
    for (int kk = 0; kk < BK; kk += 16) {
        uint32_t bh[4][2], af[2][4];
#pragma unroll
        for (int nf = 0; nf < 4; nf++)
            ldsm_x2(sB + boff + (nf * 8 * KP + kk) * 2, bh[nf]);
#pragma unroll
        for (int mf = 0; mf < 2; mf++)
            ldsm_x4(sA + aoff + (mf * 16 * KP + kk) * 2, af[mf]);
#pragma unroll
        for (int nf = 0; nf < 4; nf++)
#pragma unroll
            for (int mf = 0; mf < 2; mf++)
                mma_f16(A.v[mf][nf], af[mf], bh[nf]);
    }
}

// lane-dependent ldmatrix offsets (bytes) for row-major [row][k] smem tiles
template <int KP>
__device__ __forceinline__ uint32_t mk_aoff(int mbase, int lane) {
    int arow = (lane & 7) + ((lane >> 3) & 1) * 8;
    int acol = (lane >> 4) * 8;
    return (uint32_t)(((mbase + arow) * KP + acol) * 2);
}
template <int KP>
__device__ __forceinline__ uint32_t mk_boff(int nbase, int lane) {
    int brow = lane & 7;
    int bcol = ((lane >> 3) & 1) * 8;
    return (uint32_t)(((nbase + brow) * KP + bcol) * 2);
}

// ---------------- universal GEMM: cp.async 3-stage, fp16, fp16 out -----------
// C[m0:+128, n0:+64] = A[M,lda] @ W[:,ldw]^T (+bias[n] or +pre[m*G3+n])
__device__ void gemm_step(const __half* __restrict__ A, int lda,
                          const __half* __restrict__ Wh, int ldw,
                          const float* __restrict__ bias,
                          const __half* __restrict__ pre,
                          __half* __restrict__ Cc, int K, int M, int m0, int n0,
                          char* dsm) {
    const int tid = threadIdx.x;
    const int w = tid >> 5, lane = tid & 31;
    const int g = lane >> 2, t4 = lane & 3;
    const int mbase = (w >> 1) * 32, nbase = (w & 1) * 32;
    const uint32_t sb0 = (uint32_t)__cvta_generic_to_shared(dsm);
    const uint32_t aoff = mk_aoff<BKP32>(mbase, lane);
    const uint32_t boff = mk_boff<BKP32>(nbase, lane);
    Acc acc;
#pragma unroll
    for (int i = 0; i < 2; i++)
#pragma unroll
        for (int j = 0; j < 4; j++)
#pragma unroll
            for (int q = 0; q < 4; q++) acc.v[i][j][q] = 0.0f;

    const int NC = K >> 5;
    auto stage = [&](int c) {
        uint32_t sb = sb0 + (c % 3) * STAGE_SZ;
        int kt = c << 5;
        for (int it = tid; it < 768; it += NT) {
            if (it < 512) {
                int row = it >> 2;
                int c8 = (it & 3) << 3;
                int mm = m0 + row; if (mm >= M) mm = M - 1;
                const void* ga = A + (size_t)mm * lda + kt + c8;
                uint32_t so = sb + (row * BKP32 + c8) * 2;
                asm volatile("cp.async.ca.shared.global [%0], [%1], 16;" :: "r"(so), "l"(ga));
            } else {
                int j = it - 512;
                int row = j >> 2;
                int c8 = (j & 3) << 3;
                const void* gb = Wh + (size_t)(n0 + row) * ldw + kt + c8;
                uint32_t so = sb + SA_SZ + (row * BKP32 + c8) * 2;
                asm volatile("cp.async.ca.shared.global [%0], [%1], 16;" :: "r"(so), "l"(gb));
            }
        }
        asm volatile("cp.async.commit_group;");
    };

    stage(0);
    if (NC > 1) stage(1);
    for (int c = 0; c < NC; c++) {
        if (c + 2 < NC) {
            stage(c + 2);
            asm volatile("cp.async.wait_group 2;");
        } else if (c + 1 < NC) {
            asm volatile("cp.async.wait_group 1;");
        } else {
            asm volatile("cp.async.wait_group 0;");
        }
        __syncthreads();
        uint32_t st = sb0 + (c % 3) * STAGE_SZ;
        mma_chunk_l<32, BKP32>(st, st + SA_SZ, aoff, boff, acc);
        __syncthreads();
    }
#pragma unroll
    for (int mf = 0; mf < 2; mf++) {
#pragma unroll
        for (int nf = 0; nf < 4; nf++) {
            int m = m0 + mbase + mf * 16 + g;
            int n = n0 + nbase + nf * 8 + 2 * t4;
            if (pre == nullptr) {
                float b0 = bias[n], b1 = bias[n + 1];
                if (m < M)
                    *(__half2*)(Cc + (size_t)m * G3 + n) =
                        __floats2half2_rn(acc.v[mf][nf][0] + b0, acc.v[mf][nf][1] + b1);
                if (m + 8 < M)
                    *(__half2*)(Cc + (size_t)(m + 8) * G3 + n) =
                        __floats2half2_rn(acc.v[mf][nf][2] + b0, acc.v[mf][nf][3] + b1);
            } else {
                if (m < M) {
                    float2 p = __half22float2(*(const __half2*)(pre + (size_t)m * G3 + n));
                    *(__half2*)(Cc + (size_t)m * G3 + n) =
                        __floats2half2_rn(acc.v[mf][nf][0] + p.x, acc.v[mf][nf][1] + p.y);
                }
                if (m + 8 < M) {
                    float2 p = __half22float2(*(const __half2*)(pre + (size_t)(m + 8) * G3 + n));
                    *(__half2*)(Cc + (size_t)(m + 8) * G3 + n) =
                        __floats2half2_rn(acc.v[mf][nf][2] + p.x, acc.v[mf][nf][3] + p.y);
                }
            }
        }
    }
    __syncthreads();
}

// ---------------- GRU gate (fp16 gi + fp16 gh -> fp32 master + fp16 state) ---
__device__ __forceinline__ void gate_hh(const __half* __restrict__ gi,
                                        const __half* __restrict__ gh,
                                        float* __restrict__ hf,
                                        __half* __restrict__ h16,
                                        int M, int gtid, int nthr) {
    int total = M * HID;
    for (int idx = gtid; idx < total; idx += nthr) {
        int m = idx >> 8;
        int j = idx & 255;
        const __half* gim = gi + (size_t)m * G3;
        const __half* ghm = gh + (size_t)m * G3;
        float r = 1.0f / (1.0f + __expf(-(__half2float(gim[j]) + __half2float(ghm[j]))));
        float z = 1.0f / (1.0f + __expf(-(__half2float(gim[HID + j]) + __half2float(ghm[HID + j]))));
        float n = tanhf(__half2float(gim[2 * HID + j]) + r * __half2float(ghm[2 * HID + j]));
        float v = (1.0f - z) * n + z * hf[idx];
        hf[idx] = v;
        h16[idx] = __float2half_rn(v);
    }
}

__device__ __forceinline__ void convW(const float* __restrict__ W, int off, int n,
                                      int gtid, int nthr) {
    for (int i = gtid; i < n; i += nthr)
        g_Whi[off + i] = __float2half_rn(W[i]);
}

// tile counts (BM=128, BN=64): stocks 63x12=756, news 13x12=156
#define ST_T 756
#define NW_T 156
#define PA_TOT (ST_T * 2 + NW_T)       // 1668
#define BI3_TOT (48000 + 9600)         // bulk gi_li + gi_c
#define BI6_TOT 48000

// ---------------- the persistent mega-kernel ---------------------------------
__global__ __launch_bounds__(NT, 3)
void mega_kernel(const float* __restrict__ inputs, const int* __restrict__ ei,
                 const float* __restrict__ h_start, const float* __restrict__ hi_start,
                 const float* __restrict__ mc_start,
                 const float* __restrict__ Wih_c,  const float* __restrict__ Whh_c,
                 const float* __restrict__ bih_c,  const float* __restrict__ bhh_c,
                 const float* __restrict__ Wih_lh, const float* __restrict__ Whh_lh,
                 const float* __restrict__ bih_lh, const float* __restrict__ bhh_lh,
                 const float* __restrict__ Wih_li, const float* __restrict__ Whh_li,
                 const float* __restrict__ bih_li, const float* __restrict__ bhh_li,
                 float* __restrict__ m_out, float* __restrict__ h_out,
                 float* __restrict__ hi_out) {
    extern __shared__ char dsm[];

    const int gtid = blockIdx.x * NT + threadIdx.x;
    const int nthr = gridDim.x * NT;
    const int gwarp = gtid >> 5;
    const int lane = threadIdx.x & 31;
    const int nwarp = nthr >> 5;

    // ==== I0: init states, weights, x conversion, zero counters ====
    for (int i = gtid; i < NSTOCK * HID; i += nthr) {
        float hv = h_start[i & 255], pv = hi_start[i & 255];
        h_out[i] = hv; hi_out[i] = pv;
        g_h16[i] = __float2half_rn(hv);
        g_p16[i] = __float2half_rn(pv);
    }
    for (int i = gtid; i < NNEWS * HID; i += nthr) {
        float v = mc_start[i & 255];
        g_mc[i] = v;
        g_mc16[i] = __float2half_rn(v);
    }
    convW(Wih_li, OW_IH_LI, G3 * C_IN, gtid, nthr);
    convW(Whh_li, OW_HH_LI, G3 * HID,  gtid, nthr);
    convW(Wih_c,  OW_IH_C,  G3 * C_IN, gtid, nthr);
    convW(Whh_c,  OW_HH_C,  G3 * HID,  gtid, nthr);
    convW(Wih_lh, OW_IH_LH, G3 * CM,   gtid, nthr);
    convW(Whh_lh, OW_HH_LH, G3 * HID,  gtid, nthr);
    for (size_t i = gtid; i < (size_t)NSTE * C_IN; i += nthr)
        g_x16[i] = __float2half_rn(inputs[i]);
    for (int i = gtid; i < NNE; i += nthr) g_inv_news_all[i] = 0.0f;
    for (int i = gtid; i < NSTE; i += nthr) { g_deg[i] = 0; }
    for (int i = gtid; i < SEQ_L; i += nthr) g_tot[i] = 0;
    for (size_t i = gtid; i < (size_t)NNE * C_IN; i += nthr) g_acc_news_all[i] = 0.0f;
    for (size_t i = gtid; i < (size_t)NSTE * C_IN; i += nthr) g_accmc_all[i] = 0.0f;
    grid_sync();
    // ==== I0b: degree counts ====
    for (int task = gtid; task < SEQ_L * NEDGE; task += nthr) {
        int t = task / NEDGE, e = task - t * NEDGE;
        const int* news = ei + (size_t)t * 2 * NEDGE;
        atomicAdd(&g_inv_news_all[t * NNEWS + news[e]], 1.0f);
        atomicAdd(&g_deg[t * NSTOCK + news[NEDGE + e]], 1);
    }
    grid_sync();
    // ==== I1: invert counts; CSR offsets; bulk scatter x -> news ====
    for (int i = gtid; i < NNE; i += nthr)
        g_inv_news_all[i] = 1.0f / fmaxf(g_inv_news_all[i], 1.0f);
    for (int i = gtid; i < NSTE; i += nthr) {
        int d = g_deg[i];
        g_inv_stock_all[i] = 1.0f / fmaxf((float)d, 1.0f);
        int off = atomicAdd(&g_tot[i / NSTOCK], d);
        g_csr_off[i] = off;
        g_cur[i] = off;
    }
    for (int task = gwarp; task < SEQ_L * NEDGE; task += nwarp) {
        int t = task / NEDGE, e = task - t * NEDGE;
        const int* news = ei + (size_t)t * 2 * NEDGE;
        int n = news[e], s = news[NEDGE + e];
        float4 v = ((const float4*)(inputs + ((size_t)t * NSTOCK + s) * C_IN))[lane];
        float* dst = g_acc_news_all + ((size_t)t * NNEWS + n) * C_IN + lane * 4;
        atomicAdd(dst + 0, v.x); atomicAdd(dst + 1, v.y);
        atomicAdd(dst + 2, v.z); atomicAdd(dst + 3, v.w);
    }
    grid_sync();
    // ==== I2: fill CSR; normalize center in place + fp16 copy ====
    for (int task = gtid; task < SEQ_L * NEDGE; task += nthr) {
        int t = task / NEDGE, e = task - t * NEDGE;
        const int* news = ei + (size_t)t * 2 * NEDGE;
        int n = news[e], s = news[NEDGE + e];
        int slot = atomicAdd(&g_cur[t * NSTOCK + s], 1);
        g_csr_n[(size_t)t * NEDGE + slot] = n;
    }
    for (size_t i = gtid; i < (size_t)NNE * C_IN; i += nthr) {
        float v = g_acc_news_all[i] * g_inv_news_all[i >> 7];
        g_acc_news_all[i] = v;
        g_cen16[i] = __float2half_rn(v);
    }
    grid_sync();
    // ==== I3: bulk GEMMs gi_li + gi_c (K=128) ====
    for (int tile = blockIdx.x; tile < BI3_TOT; tile += gridDim.x) {
        if (tile < 48000) {
            int mt = tile / 12, nt = tile % 12;
            gemm_step(g_x16, C_IN, g_Whi + OW_IH_LI, C_IN,
                      bih_li, nullptr, g_gi_li_all, C_IN, NSTE, mt * 128, nt * 64, dsm);
        } else {
            int idx = tile - 48000, mt = idx / 12, nt = idx % 12;
            gemm_step(g_cen16, C_IN, g_Whi + OW_IH_C, C_IN,
                      bih_c, nullptr, g_gi_c_all, C_IN, NNE, mt * 128, nt * 64, dsm);
        }
    }
    grid_sync();
    // ==== I4: bulk scatter center -> stocks ====
    for (int task = gwarp; task < SEQ_L * NEDGE; task += nwarp) {
        int t = task / NEDGE, e = task - t * NEDGE;
        const int* news = ei + (size_t)t * 2 * NEDGE;
        int n = news[e], s = news[NEDGE + e];
        float4 v = ((const float4*)(g_acc_news_all + ((size_t)t * NNEWS + n) * C_IN))[lane];
        float* dst = g_accmc_all + ((size_t)t * NSTOCK + s) * C_IN + lane * 4;
        atomicAdd(dst + 0, v.x); atomicAdd(dst + 1, v.y);
        atomicAdd(dst + 2, v.z); atomicAdd(dst + 3, v.w);
    }
    grid_sync();
    // ==== I5: normalize mcenter -> fp16; m_out center cols (t=63) ====
    for (size_t i = gtid; i < (size_t)NSTE * C_IN; i += nthr) {
        float v = g_accmc_all[i] * g_inv_stock_all[i >> 7];
        g_mce16[i] = __float2half_rn(v);
        if (i >= (size_t)63 * NSTOCK * C_IN) {
            size_t r = i - (size_t)63 * NSTOCK * C_IN;
            m_out[(r >> 7) * CM + (r & 127)] = v;
        }
    }
    grid_sync();
    // ==== I6: bulk GEMM gi_lh1 (K=128) ====
    for (int tile = blockIdx.x; tile < BI6_TOT; tile += gridDim.x) {
        int mt = tile / 12, nt = tile % 12;
        gemm_step(g_mce16, C_IN, g_Whi + OW_IH_LH, CM,
                  bih_lh, nullptr, g_gi_lh1_all, C_IN, NSTE, mt * 128, nt * 64, dsm);
    }
    grid_sync();

    // ==== sequential recurrence: K=256 fp16 GEMMs, CSR gather ====
    for (int t = 0; t < SEQ_L; t++) {
        // ---- A: gh_li, gh_lh, gh_n ----
        for (int tile = blockIdx.x; tile < PA_TOT; tile += gridDim.x) {
            if (tile < ST_T) {
                int mt = tile / 12, nt = tile % 12;
                gemm_step(g_p16, HID, g_Whi + OW_HH_LI, HID,
                          bhh_li, nullptr, g_gh_li, HID, NSTOCK, mt * 128, nt * 64, dsm);
            } else if (tile < 2 * ST_T) {
                int idx = tile - ST_T, mt = idx / 12, nt = idx % 12;
                gemm_step(g_h16, HID, g_Whi + OW_HH_LH, HID,
                          bhh_lh, nullptr, g_gh_lh, HID, NSTOCK, mt * 128, nt * 64, dsm);
            } else {
                int idx = tile - 2 * ST_T, mt = idx / 12, nt = idx % 12;
                gemm_step(g_mc16, HID, g_Whi + OW_HH_C, HID,
                          bhh_c, nullptr, g_gh_n, HID, NNEWS, mt * 128, nt * 64, dsm);
            }
        }
        grid_sync();

        // ---- B: gates m_c + h_input ----
        gate_hh(g_gi_c_all + (size_t)t * NNEWS * G3, g_gh_n,
                g_mc, g_mc16, NNEWS, gtid, nthr);
        gate_hh(g_gi_li_all + (size_t)t * NSTOCK * G3, g_gh_li,
                hi_out, g_p16, NSTOCK, gtid, nthr);
        grid_sync();

        // ---- C': CSR gather m_c (news -> stocks) + normalize -> fp16 ----
        for (int s = gwarp; s < NSTOCK; s += nwarp) {
            int base = t * NSTOCK + s;
            int off = g_csr_off[base], deg = g_deg[base];
            const int* en = g_csr_n + (size_t)t * NEDGE;
            float4 a0 = make_float4(0.f, 0.f, 0.f, 0.f);
            float4 a1 = make_float4(0.f, 0.f, 0.f, 0.f);
            for (int e = off; e < off + deg; e++) {
                int n = en[e];
                const float4* mp = (const float4*)(g_mc + (size_t)n * HID);
                float4 v0 = mp[lane], v1 = mp[lane + 32];
                a0.x += v0.x; a0.y += v0.y; a0.z += v0.z; a0.w += v0.w;
                a1.x += v1.x; a1.y += v1.y; a1.z += v1.z; a1.w += v1.w;
            }
            float inv = g_inv_stock_all[base];
            float vs[8] = {a0.x * inv, a0.y * inv, a0.z * inv, a0.w * inv,
                           a1.x * inv, a1.y * inv, a1.z * inv, a1.w * inv};
            int c0 = s * HID + lane * 4;
#pragma unroll
            for (int q = 0; q < 4; q++) {
                g_amc16[c0 + q] = __float2half_rn(vs[q]);
                g_amc16[c0 + 128 + q] = __float2half_rn(vs[4 + q]);
            }
            if (t == SEQ_L - 1) {
                float* mo = m_out + (size_t)s * CM + C_IN + lane * 4;
#pragma unroll
                for (int q = 0; q < 4; q++) { mo[q] = vs[q]; mo[128 + q] = vs[4 + q]; }
            }
        }
        grid_sync();

        // ---- E: gis = gi_lh1[t] + amc @ Wih_lh[:, 128:]^T ----
        for (int tile = blockIdx.x; tile < ST_T; tile += gridDim.x) {
            int mt = tile / 12, nt = tile % 12;
            gemm_step(g_amc16, HID, g_Whi + OW_IH_LH + C_IN, CM,
                      nullptr, g_gi_lh1_all + (size_t)t * NSTOCK * G3,
                      g_gis, HID, NSTOCK, mt * 128, nt * 64, dsm);
        }
        grid_sync();

        // ---- F: gate h ----
        gate_hh(g_gis, g_gh_lh, h_out, g_h16, NSTOCK, gtid, nthr);
        grid_sync();
    }
}

// ---------------- launch -----------------------------------------------------
extern "C" void kernel_launch(void* const* d_in, const int* in_sizes, int n_in,
                              void* d_out, int out_size) {
    const float* inputs   = (const float*)d_in[0];
    const int*   ei       = (const int*)d_in[1];
    const float* h_start  = (const float*)d_in[2];
    const float* hi_start = (const float*)d_in[3];
    const float* mc_start = (const float*)d_in[4];
    const float* Wih_c  = (const float*)d_in[5];
    const float* Whh_c  = (const float*)d_in[6];
    const float* bih_c  = (const float*)d_in[7];
    const float* bhh_c  = (const float*)d_in[8];
    const float* Wih_lh = (const float*)d_in[9];
    const float* Whh_lh = (const float*)d_in[10];
    const float* bih_lh = (const float*)d_in[11];
    const float* bhh_lh = (const float*)d_in[12];
    const float* Wih_li = (const float*)d_in[13];
    const float* Whh_li = (const float*)d_in[14];
    const float* bih_li = (const float*)d_in[15];
    const float* bhh_li = (const float*)d_in[16];

    float* out    = (float*)d_out;
    float* m_out  = out;
    float* h_out  = out + (size_t)NSTOCK * CM;
    float* hi_out = h_out + (size_t)NSTOCK * HID;

    cudaFuncSetAttribute(mega_kernel, cudaFuncAttributeMaxDynamicSharedMemorySize, SMEM_BYTES);

    int dev = 0, nsm = 0, occ = 0;
    cudaGetDevice(&dev);
    cudaDeviceGetAttribute(&nsm, cudaDevAttrMultiProcessorCount, dev);
    cudaOccupancyMaxActiveBlocksPerMultiprocessor(&occ, mega_kernel, NT, SMEM_BYTES);
    if (occ < 1) occ = 1;
    int nblk = nsm * occ;

    unsigned* bar = nullptr;
    cudaGetSymbolAddress((void**)&bar, g_bar_count);
    cudaMemsetAsync(bar, 0, sizeof(unsigned));

    mega_kernel<<<nblk, NT, SMEM_BYTES>>>(inputs, ei, h_start, hi_start, mc_start,
                                          Wih_c, Whh_c, bih_c, bhh_c,
                                          Wih_lh, Whh_lh, bih_lh, bhh_lh,
                                          Wih_li, Whh_li, bih_li, bhh_li,
                                          m_out, h_out, hi_out);
}

// round 16
// speedup vs baseline: 4.7053x; 1.2374x over previous
#include <cuda_runtime.h>
#include <cuda_bf16.h>
#include <cuda_fp16.h>
#include <math.h>
#include <stdint.h>

#define SEQ_L 64
#define NSTOCK 8000
#define NNEWS 1600
#define C_IN 128
#define HID 256
#define NEDGE 32000
#define G3 768
#define CM 384
#define NT 256
#define NSTE 512000
#define NNE  102400

// GEMM tiles: BM=128, BN=64, BK=32, 4-stage cp.async
#define BKP32 40
#define SA_SZ (128 * BKP32 * 2)        // 10240 B (A: 128 rows)
#define SB_SZ (64 * BKP32 * 2)         // 5120 B  (B: 64 rows)
#define STAGE_SZ (SA_SZ + SB_SZ)       // 15360 B
#define SMEM_BYTES (4 * STAGE_SZ)      // 61440 B -> 3 CTAs/SM by smem

// ---- weight fp16 offsets (elements) -----------------------------------------
#define OW_IH_LI 0
#define OW_HH_LI 98304
#define OW_IH_C  294912
#define OW_HH_C  393216
#define OW_IH_LH 589824
#define OW_HH_LH 884736
#define W_TOTAL  1081344

// ---------------- static device scratch (~2.4GB, linker-safe) ----------------
__device__ __align__(16) float g_acc_news_all[(size_t)NNE * C_IN];
__device__ __align__(16) float g_accmc_all[(size_t)NSTE * C_IN];
__device__ __align__(16) __half g_x16[(size_t)NSTE * C_IN];
__device__ __align__(16) __half g_cen16[(size_t)NNE * C_IN];
__device__ __align__(16) __half g_mce16[(size_t)NSTE * C_IN];
__device__ __align__(16) __half g_gi_li_all[(size_t)NSTE * G3];
__device__ __align__(16) __half g_gi_c_all[(size_t)NNE * G3];
__device__ __align__(16) __half g_gi_lh1_all[(size_t)NSTE * G3];
__device__ float g_inv_news_all[NNE];
__device__ float g_inv_stock_all[NSTE];
// CSR (stock-destination sorted edges, per t)
__device__ int g_deg[NSTE];
__device__ int g_csr_off[NSTE];
__device__ int g_cur[NSTE];
__device__ int g_csr_n[SEQ_L * NEDGE];
__device__ int g_tot[SEQ_L];
// per-step state (fp32 master + fp16 GEMM operand copies)
__device__ __align__(16) float g_mc[NNEWS * HID];
__device__ __align__(16) __half g_mc16[NNEWS * HID];
__device__ __align__(16) __half g_h16[NSTOCK * HID];
__device__ __align__(16) __half g_p16[NSTOCK * HID];
__device__ __align__(16) __half g_amc16[NSTOCK * HID];
__device__ __align__(16) __half g_gh_li[NSTOCK * G3];
__device__ __align__(16) __half g_gh_lh[NSTOCK * G3];
__device__ __align__(16) __half g_gh_n[NNEWS * G3];
__device__ __align__(16) __half g_gis[NSTOCK * G3];
__device__ __align__(16) __half g_Whi[W_TOTAL];
__device__ unsigned g_bar_count = 0;

// ---------------- software grid barrier (monotonic) --------------------------
__device__ __forceinline__ void grid_sync() {
    __syncthreads();
    __threadfence();
    if (threadIdx.x == 0) {
        unsigned G = gridDim.x;
        unsigned arrival = atomicAdd(&g_bar_count, 1u) + 1u;
        unsigned target = ((arrival + G - 1u) / G) * G;
        volatile unsigned* vc = &g_bar_count;
        while (*vc < target) { __nanosleep(32); }
    }
    __syncthreads();
    __threadfence();
}

__device__ __forceinline__ void mma_f16(float* c, const uint32_t* a, const uint32_t* b) {
    asm volatile("mma.sync.aligned.m16n8k16.row.col.f32.f16.f16.f32 "
                 "{%0,%1,%2,%3}, {%4,%5,%6,%7}, {%8,%9}, {%0,%1,%2,%3};"
                 : "+f"(c[0]), "+f"(c[1]), "+f"(c[2]), "+f"(c[3])
                 : "r"(a[0]), "r"(a[1]), "r"(a[2]), "r"(a[3]), "r"(b[0]), "r"(b[1]));
}

__device__ __forceinline__ void ldsm_x4(uint32_t addr, uint32_t* r) {
    asm volatile("ldmatrix.sync.aligned.m8n8.x4.shared.b16 {%0,%1,%2,%3}, [%4];"
                 : "=r"(r[0]), "=r"(r[1]), "=r"(r[2]), "=r"(r[3]) : "r"(addr));
}
__device__ __forceinline__ void ldsm_x2(uint32_t addr, uint32_t* r) {
    asm volatile("ldmatrix.sync.aligned.m8n8.x2.shared.b16 {%0,%1}, [%2];"
                 : "=r"(r[0]), "=r"(r[1]) : "r"(addr));
}

struct Acc { float v[2][4][4]; };   // 32 regs: 2 m-frags x 4 n-frags

// ---------------- fp16 fragment compute over one staged chunk ----------------
// Warp layout: 8 warps as 4(M) x 2(N); each warp owns 32 rows x 32 cols.
template <int BK, int KP>
__device__ __forceinline__ void mma_chunk_l(uint32_t sA, uint32_t sB,
                                            uint32_t aoff, uint32_t boff, Acc& A) {
#pragma unroll
    for (int kk = 0; kk < BK; kk += 16) {
        uint32_t bh[4][2], af[2][4];
#pragma unroll
        for (int nf = 0; nf < 4; nf++)
            ldsm_x2(sB + boff + (nf * 8 * KP + kk) * 2, bh[nf]);
#pragma unroll
        for (int mf = 0; mf < 2; mf++)
            ldsm_x4(sA + aoff + (mf * 16 * KP + kk) * 2, af[mf]);
#pragma unroll
        for (int nf = 0; nf < 4; nf++)
#pragma unroll
            for (int mf = 0; mf < 2; mf++)
                mma_f16(A.v[mf][nf], af[mf], bh[nf]);
    }
}

// lane-dependent ldmatrix offsets (bytes) for row-major [row][k] smem tiles
template <int KP>
__device__ __forceinline__ uint32_t mk_aoff(int mbase, int lane) {
    int arow = (lane & 7) + ((lane >> 3) & 1) * 8;
    int acol = (lane >> 4) * 8;
    return (uint32_t)(((mbase + arow) * KP + acol) * 2);
}
template <int KP>
__device__ __forceinline__ uint32_t mk_boff(int nbase, int lane) {
    int brow = lane & 7;
    int bcol = ((lane >> 3) & 1) * 8;
    return (uint32_t)(((nbase + brow) * KP + bcol) * 2);
}

// ---------------- universal GEMM: cp.async 4-stage, fp16, fp16 out -----------
// C[m0:+128, n0:+64] = A[M,lda] @ W[:,ldw]^T (+bias[n] or +pre[m*G3+n])
__device__ void gemm_step(const __half* __restrict__ A, int lda,
                          const __half* __restrict__ Wh, int ldw,
                          const float* __restrict__ bias,
                          const __half* __restrict__ pre,
                          __half* __restrict__ Cc, int K, int M, int m0, int n0,
                          char* dsm) {
    const int tid = threadIdx.x;
    const int w = tid >> 5, lane = tid & 31;
    const int g = lane >> 2, t4 = lane & 3;
    const int mbase = (w >> 1) * 32, nbase = (w & 1) * 32;
    const uint32_t sb0 = (uint32_t)__cvta_generic_to_shared(dsm);
    const uint32_t aoff = mk_aoff<BKP32>(mbase, lane);
    const uint32_t boff = mk_boff<BKP32>(nbase, lane);
    Acc acc;
#pragma unroll
    for (int i = 0; i < 2; i++)
#pragma unroll
        for (int j = 0; j < 4; j++)
#pragma unroll
            for (int q = 0; q < 4; q++) acc.v[i][j][q] = 0.0f;

    const int NC = K >> 5;
    auto stage = [&](int c) {
        uint32_t sb = sb0 + (c & 3) * STAGE_SZ;
        int kt = c << 5;
        for (int it = tid; it < 768; it += NT) {
            if (it < 512) {
                int row = it >> 2;
                int c8 = (it & 3) << 3;
                int mm = m0 + row; if (mm >= M) mm = M - 1;
                const void* ga = A + (size_t)mm * lda + kt + c8;
                uint32_t so = sb + (row * BKP32 + c8) * 2;
                asm volatile("cp.async.ca.shared.global [%0], [%1], 16;" :: "r"(so), "l"(ga));
            } else {
                int j = it - 512;
                int row = j >> 2;
                int c8 = (j & 3) << 3;
                const void* gb = Wh + (size_t)(n0 + row) * ldw + kt + c8;
                uint32_t so = sb + SA_SZ + (row * BKP32 + c8) * 2;
                asm volatile("cp.async.ca.shared.global [%0], [%1], 16;" :: "r"(so), "l"(gb));
            }
        }
        asm volatile("cp.async.commit_group;");
    };

    stage(0);
    if (NC > 1) stage(1);
    if (NC > 2) stage(2);
    for (int c = 0; c < NC; c++) {
        if (c + 3 < NC) {
            stage(c + 3);
            asm volatile("cp.async.wait_group 3;");
        } else if (c + 2 < NC) {
            asm volatile("cp.async.wait_group 2;");
        } else if (c + 1 < NC) {
            asm volatile("cp.async.wait_group 1;");
        } else {
            asm volatile("cp.async.wait_group 0;");
        }
        __syncthreads();
        uint32_t st = sb0 + (c & 3) * STAGE_SZ;
        mma_chunk_l<32, BKP32>(st, st + SA_SZ, aoff, boff, acc);
        __syncthreads();
    }
#pragma unroll
    for (int mf = 0; mf < 2; mf++) {
#pragma unroll
        for (int nf = 0; nf < 4; nf++) {
            int m = m0 + mbase + mf * 16 + g;
            int n = n0 + nbase + nf * 8 + 2 * t4;
            if (pre == nullptr) {
                float b0 = bias[n], b1 = bias[n + 1];
                if (m < M)
                    *(__half2*)(Cc + (size_t)m * G3 + n) =
                        __floats2half2_rn(acc.v[mf][nf][0] + b0, acc.v[mf][nf][1] + b1);
                if (m + 8 < M)
                    *(__half2*)(Cc + (size_t)(m + 8) * G3 + n) =
                        __floats2half2_rn(acc.v[mf][nf][2] + b0, acc.v[mf][nf][3] + b1);
            } else {
                if (m < M) {
                    float2 p = __half22float2(*(const __half2*)(pre + (size_t)m * G3 + n));
                    *(__half2*)(Cc + (size_t)m * G3 + n) =
                        __floats2half2_rn(acc.v[mf][nf][0] + p.x, acc.v[mf][nf][1] + p.y);
                }
                if (m + 8 < M) {
                    float2 p = __half22float2(*(const __half2*)(pre + (size_t)(m + 8) * G3 + n));
                    *(__half2*)(Cc + (size_t)(m + 8) * G3 + n) =
                        __floats2half2_rn(acc.v[mf][nf][2] + p.x, acc.v[mf][nf][3] + p.y);
                }
            }
        }
    }
    __syncthreads();
}

// ---------------- GRU gate, half2-vectorized ---------------------------------
__device__ __forceinline__ void gate_hh(const __half* __restrict__ gi,
                                        const __half* __restrict__ gh,
                                        float* __restrict__ hf,
                                        __half* __restrict__ h16,
                                        int M, int gtid, int nthr) {
    int total = (M * HID) >> 1;
    for (int p = gtid; p < total; p += nthr) {
        int idx = p << 1;
        int m = idx >> 8;
        int j = idx & 255;
        const __half* gim = gi + (size_t)m * G3 + j;
        const __half* ghm = gh + (size_t)m * G3 + j;
        float2 gr = __half22float2(*(const __half2*)(gim));
        float2 gz = __half22float2(*(const __half2*)(gim + HID));
        float2 gn = __half22float2(*(const __half2*)(gim + 2 * HID));
        float2 hr = __half22float2(*(const __half2*)(ghm));
        float2 hz = __half22float2(*(const __half2*)(ghm + HID));
        float2 hn = __half22float2(*(const __half2*)(ghm + 2 * HID));
        float r0 = 1.0f / (1.0f + __expf(-(gr.x + hr.x)));
        float r1 = 1.0f / (1.0f + __expf(-(gr.y + hr.y)));
        float z0 = 1.0f / (1.0f + __expf(-(gz.x + hz.x)));
        float z1 = 1.0f / (1.0f + __expf(-(gz.y + hz.y)));
        float n0 = tanhf(gn.x + r0 * hn.x);
        float n1 = tanhf(gn.y + r1 * hn.y);
        float2 hv = *(const float2*)(hf + idx);
        float v0 = (1.0f - z0) * n0 + z0 * hv.x;
        float v1 = (1.0f - z1) * n1 + z1 * hv.y;
        *(float2*)(hf + idx) = make_float2(v0, v1);
        *(__half2*)(h16 + idx) = __floats2half2_rn(v0, v1);
    }
}

__device__ __forceinline__ void convW(const float* __restrict__ W, int off, int n,
                                      int gtid, int nthr) {
    for (int i = gtid; i < n; i += nthr)
        g_Whi[off + i] = __float2half_rn(W[i]);
}

// tile counts (BM=128, BN=64): stocks 63x12=756, news 13x12=156
#define ST_T 756
#define NW_T 156
#define PA_TOT (ST_T + NW_T)           // 912 = exactly 2.0 waves at grid 456
#define PE_TOT (ST_T * 2)              // 1512 (gis + gh_lh)
#define BI3_TOT (48000 + 9600)
#define BI6_TOT 48000

// ---------------- the persistent mega-kernel ---------------------------------
__global__ __launch_bounds__(NT, 3)
void mega_kernel(const float* __restrict__ inputs, const int* __restrict__ ei,
                 const float* __restrict__ h_start, const float* __restrict__ hi_start,
                 const float* __restrict__ mc_start,
                 const float* __restrict__ Wih_c,  const float* __restrict__ Whh_c,
                 const float* __restrict__ bih_c,  const float* __restrict__ bhh_c,
                 const float* __restrict__ Wih_lh, const float* __restrict__ Whh_lh,
                 const float* __restrict__ bih_lh, const float* __restrict__ bhh_lh,
                 const float* __restrict__ Wih_li, const float* __restrict__ Whh_li,
                 const float* __restrict__ bih_li, const float* __restrict__ bhh_li,
                 float* __restrict__ m_out, float* __restrict__ h_out,
                 float* __restrict__ hi_out) {
    extern __shared__ char dsm[];

    const int gtid = blockIdx.x * NT + threadIdx.x;
    const int nthr = gridDim.x * NT;
    const int gwarp = gtid >> 5;
    const int lane = threadIdx.x & 31;
    const int nwarp = nthr >> 5;

    // ==== I0: init states, weights, x conversion, zero counters ====
    for (int i = gtid; i < NSTOCK * HID; i += nthr) {
        float hv = h_start[i & 255], pv = hi_start[i & 255];
        h_out[i] = hv; hi_out[i] = pv;
        g_h16[i] = __float2half_rn(hv);
        g_p16[i] = __float2half_rn(pv);
    }
    for (int i = gtid; i < NNEWS * HID; i += nthr) {
        float v = mc_start[i & 255];
        g_mc[i] = v;
        g_mc16[i] = __float2half_rn(v);
    }
    convW(Wih_li, OW_IH_LI, G3 * C_IN, gtid, nthr);
    convW(Whh_li, OW_HH_LI, G3 * HID,  gtid, nthr);
    convW(Wih_c,  OW_IH_C,  G3 * C_IN, gtid, nthr);
    convW(Whh_c,  OW_HH_C,  G3 * HID,  gtid, nthr);
    convW(Wih_lh, OW_IH_LH, G3 * CM,   gtid, nthr);
    convW(Whh_lh, OW_HH_LH, G3 * HID,  gtid, nthr);
    for (size_t i = gtid; i < (size_t)NSTE * C_IN; i += nthr)
        g_x16[i] = __float2half_rn(inputs[i]);
    for (int i = gtid; i < NNE; i += nthr) g_inv_news_all[i] = 0.0f;
    for (int i = gtid; i < NSTE; i += nthr) { g_deg[i] = 0; }
    for (int i = gtid; i < SEQ_L; i += nthr) g_tot[i] = 0;
    for (size_t i = gtid; i < (size_t)NNE * C_IN; i += nthr) g_acc_news_all[i] = 0.0f;
    for (size_t i = gtid; i < (size_t)NSTE * C_IN; i += nthr) g_accmc_all[i] = 0.0f;
    grid_sync();
    // ==== I0b: degree counts ====
    for (int task = gtid; task < SEQ_L * NEDGE; task += nthr) {
        int t = task / NEDGE, e = task - t * NEDGE;
        const int* news = ei + (size_t)t * 2 * NEDGE;
        atomicAdd(&g_inv_news_all[t * NNEWS + news[e]], 1.0f);
        atomicAdd(&g_deg[t * NSTOCK + news[NEDGE + e]], 1);
    }
    grid_sync();
    // ==== I1: invert counts; CSR offsets; bulk scatter x -> news ====
    for (int i = gtid; i < NNE; i += nthr)
        g_inv_news_all[i] = 1.0f / fmaxf(g_inv_news_all[i], 1.0f);
    for (int i = gtid; i < NSTE; i += nthr) {
        int d = g_deg[i];
        g_inv_stock_all[i] = 1.0f / fmaxf((float)d, 1.0f);
        int off = atomicAdd(&g_tot[i / NSTOCK], d);
        g_csr_off[i] = off;
        g_cur[i] = off;
    }
    for (int task = gwarp; task < SEQ_L * NEDGE; task += nwarp) {
        int t = task / NEDGE, e = task - t * NEDGE;
        const int* news = ei + (size_t)t * 2 * NEDGE;
        int n = news[e], s = news[NEDGE + e];
        float4 v = ((const float4*)(inputs + ((size_t)t * NSTOCK + s) * C_IN))[lane];
        float* dst = g_acc_news_all + ((size_t)t * NNEWS + n) * C_IN + lane * 4;
        atomicAdd(dst + 0, v.x); atomicAdd(dst + 1, v.y);
        atomicAdd(dst + 2, v.z); atomicAdd(dst + 3, v.w);
    }
    grid_sync();
    // ==== I2: fill CSR; normalize center in place + fp16 copy ====
    for (int task = gtid; task < SEQ_L * NEDGE; task += nthr) {
        int t = task / NEDGE, e = task - t * NEDGE;
        const int* news = ei + (size_t)t * 2 * NEDGE;
        int n = news[e], s = news[NEDGE + e];
        int slot = atomicAdd(&g_cur[t * NSTOCK + s], 1);
        g_csr_n[(size_t)t * NEDGE + slot] = n;
    }
    for (size_t i = gtid; i < (size_t)NNE * C_IN; i += nthr) {
        float v = g_acc_news_all[i] * g_inv_news_all[i >> 7];
        g_acc_news_all[i] = v;
        g_cen16[i] = __float2half_rn(v);
    }
    grid_sync();
    // ==== I3: bulk GEMMs gi_li + gi_c (K=128) ====
    for (int tile = blockIdx.x; tile < BI3_TOT; tile += gridDim.x) {
        if (tile < 48000) {
            int mt = tile / 12, nt = tile % 12;
            gemm_step(g_x16, C_IN, g_Whi + OW_IH_LI, C_IN,
                      bih_li, nullptr, g_gi_li_all, C_IN, NSTE, mt * 128, nt * 64, dsm);
        } else {
            int idx = tile - 48000, mt = idx / 12, nt = idx % 12;
            gemm_step(g_cen16, C_IN, g_Whi + OW_IH_C, C_IN,
                      bih_c, nullptr, g_gi_c_all, C_IN, NNE, mt * 128, nt * 64, dsm);
        }
    }
    grid_sync();
    // ==== I4: bulk scatter center -> stocks ====
    for (int task = gwarp; task < SEQ_L * NEDGE; task += nwarp) {
        int t = task / NEDGE, e = task - t * NEDGE;
        const int* news = ei + (size_t)t * 2 * NEDGE;
        int n = news[e], s = news[NEDGE + e];
        float4 v = ((const float4*)(g_acc_news_all + ((size_t)t * NNEWS + n) * C_IN))[lane];
        float* dst = g_accmc_all + ((size_t)t * NSTOCK + s) * C_IN + lane * 4;
        atomicAdd(dst + 0, v.x); atomicAdd(dst + 1, v.y);
        atomicAdd(dst + 2, v.z); atomicAdd(dst + 3, v.w);
    }
    grid_sync();
    // ==== I5: normalize mcenter -> fp16; m_out center cols (t=63) ====
    for (size_t i = gtid; i < (size_t)NSTE * C_IN; i += nthr) {
        float v = g_accmc_all[i] * g_inv_stock_all[i >> 7];
        g_mce16[i] = __float2half_rn(v);
        if (i >= (size_t)63 * NSTOCK * C_IN) {
            size_t r = i - (size_t)63 * NSTOCK * C_IN;
            m_out[(r >> 7) * CM + (r & 127)] = v;
        }
    }
    grid_sync();
    // ==== I6: bulk GEMM gi_lh1 (K=128) ====
    for (int tile = blockIdx.x; tile < BI6_TOT; tile += gridDim.x) {
        int mt = tile / 12, nt = tile % 12;
        gemm_step(g_mce16, C_IN, g_Whi + OW_IH_LH, CM,
                  bih_lh, nullptr, g_gi_lh1_all, C_IN, NSTE, mt * 128, nt * 64, dsm);
    }
    grid_sync();

    // ==== sequential recurrence: K=256 fp16 GEMMs, CSR gather ====
    for (int t = 0; t < SEQ_L; t++) {
        // ---- A: gh_li, gh_n (912 tiles = exactly 2 waves) ----
        for (int tile = blockIdx.x; tile < PA_TOT; tile += gridDim.x) {
            if (tile < ST_T) {
                int mt = tile / 12, nt = tile % 12;
                gemm_step(g_p16, HID, g_Whi + OW_HH_LI, HID,
                          bhh_li, nullptr, g_gh_li, HID, NSTOCK, mt * 128, nt * 64, dsm);
            } else {
                int idx = tile - ST_T, mt = idx / 12, nt = idx % 12;
                gemm_step(g_mc16, HID, g_Whi + OW_HH_C, HID,
                          bhh_c, nullptr, g_gh_n, HID, NNEWS, mt * 128, nt * 64, dsm);
            }
        }
        grid_sync();

        // ---- B: gates m_c + h_input ----
        gate_hh(g_gi_c_all + (size_t)t * NNEWS * G3, g_gh_n,
                g_mc, g_mc16, NNEWS, gtid, nthr);
        gate_hh(g_gi_li_all + (size_t)t * NSTOCK * G3, g_gh_li,
                hi_out, g_p16, NSTOCK, gtid, nthr);
        grid_sync();

        // ---- C': CSR gather m_c (news -> stocks) + normalize -> fp16 ----
        for (int s = gwarp; s < NSTOCK; s += nwarp) {
            int base = t * NSTOCK + s;
            int off = g_csr_off[base], deg = g_deg[base];
            const int* en = g_csr_n + (size_t)t * NEDGE;
            float4 a0 = make_float4(0.f, 0.f, 0.f, 0.f);
            float4 a1 = make_float4(0.f, 0.f, 0.f, 0.f);
            for (int e = off; e < off + deg; e++) {
                int n = en[e];
                const float4* mp = (const float4*)(g_mc + (size_t)n * HID);
                float4 v0 = mp[lane], v1 = mp[lane + 32];
                a0.x += v0.x; a0.y += v0.y; a0.z += v0.z; a0.w += v0.w;
                a1.x += v1.x; a1.y += v1.y; a1.z += v1.z; a1.w += v1.w;
            }
            float inv = g_inv_stock_all[base];
            float vs[8] = {a0.x * inv, a0.y * inv, a0.z * inv, a0.w * inv,
                           a1.x * inv, a1.y * inv, a1.z * inv, a1.w * inv};
            int c0 = s * HID + lane * 4;
#pragma unroll
            for (int q = 0; q < 4; q++) {
                g_amc16[c0 + q] = __float2half_rn(vs[q]);
                g_amc16[c0 + 128 + q] = __float2half_rn(vs[4 + q]);
            }
            if (t == SEQ_L - 1) {
                float* mo = m_out + (size_t)s * CM + C_IN + lane * 4;
#pragma unroll
                for (int q = 0; q < 4; q++) { mo[q] = vs[q]; mo[128 + q] = vs[4 + q]; }
            }
        }
        grid_sync();

        // ---- E: gis = gi_lh1[t] + amc @ Wih_lh[:, 128:]^T ; gh_lh GEMM ----
        for (int tile = blockIdx.x; tile < PE_TOT; tile += gridDim.x) {
            if (tile < ST_T) {
                int mt = tile / 12, nt = tile % 12;
                gemm_step(g_amc16, HID, g_Whi + OW_IH_LH + C_IN, CM,
                          nullptr, g_gi_lh1_all + (size_t)t * NSTOCK * G3,
                          g_gis, HID, NSTOCK, mt * 128, nt * 64, dsm);
            } else {
                int idx = tile - ST_T, mt = idx / 12, nt = idx % 12;
                gemm_step(g_h16, HID, g_Whi + OW_HH_LH, HID,
                          bhh_lh, nullptr, g_gh_lh, HID, NSTOCK, mt * 128, nt * 64, dsm);
            }
        }
        grid_sync();

        // ---- F: gate h ----
        gate_hh(g_gis, g_gh_lh, h_out, g_h16, NSTOCK, gtid, nthr);
        grid_sync();
    }
}

// ---------------- launch -----------------------------------------------------
extern "C" void kernel_launch(void* const* d_in, const int* in_sizes, int n_in,
                              void* d_out, int out_size) {
    const float* inputs   = (const float*)d_in[0];
    const int*   ei       = (const int*)d_in[1];
    const float* h_start  = (const float*)d_in[2];
    const float* hi_start = (const float*)d_in[3];
    const float* mc_start = (const float*)d_in[4];
    const float* Wih_c  = (const float*)d_in[5];
    const float* Whh_c  = (const float*)d_in[6];
    const float* bih_c  = (const float*)d_in[7];
    const float* bhh_c  = (const float*)d_in[8];
    const float* Wih_lh = (const float*)d_in[9];
    const float* Whh_lh = (const float*)d_in[10];
    const float* bih_lh = (const float*)d_in[11];
    const float* bhh_lh = (const float*)d_in[12];
    const float* Wih_li = (const float*)d_in[13];
    const float* Whh_li = (const float*)d_in[14];
    const float* bih_li = (const float*)d_in[15];
    const float* bhh_li = (const float*)d_in[16];

    float* out    = (float*)d_out;
    float* m_out  = out;
    float* h_out  = out + (size_t)NSTOCK * CM;
    float* hi_out = h_out + (size_t)NSTOCK * HID;

    cudaFuncSetAttribute(mega_kernel, cudaFuncAttributeMaxDynamicSharedMemorySize, SMEM_BYTES);

    int dev = 0, nsm = 0, occ = 0;
    cudaGetDevice(&dev);
    cudaDeviceGetAttribute(&nsm, cudaDevAttrMultiProcessorCount, dev);
    cudaOccupancyMaxActiveBlocksPerMultiprocessor(&occ, mega_kernel, NT, SMEM_BYTES);
    if (occ < 1) occ = 1;
    int nblk = nsm * occ;

    unsigned* bar = nullptr;
    cudaGetSymbolAddress((void**)&bar, g_bar_count);
    cudaMemsetAsync(bar, 0, sizeof(unsigned));

    mega_kernel<<<nblk, NT, SMEM_BYTES>>>(inputs, ei, h_start, hi_start, mc_start,
                                          Wih_c, Whh_c, bih_c, bhh_c,
                                          Wih_lh, Whh_lh, bih_lh, bhh_lh,
                                          Wih_li, Whh_li, bih_li, bhh_li,
                                          m_out, h_out, hi_out);
}

// round 17
// speedup vs baseline: 5.0619x; 1.0758x over previous
#include <cuda_runtime.h>
#include <cuda_bf16.h>
#include <cuda_fp16.h>
#include <math.h>
#include <stdint.h>

#define SEQ_L 64
#define NSTOCK 8000
#define NNEWS 1600
#define C_IN 128
#define HID 256
#define NEDGE 32000
#define G3 768
#define CM 384
#define NT 256
#define NSTE 512000
#define NNE  102400

// GEMM tiles: BM=128, BN=64, BK=32, 4-stage cp.async
#define BKP32 40
#define SA_SZ (128 * BKP32 * 2)        // 10240 B
#define SB_SZ (64 * BKP32 * 2)         // 5120 B
#define STAGE_SZ (SA_SZ + SB_SZ)       // 15360 B
#define SMEM_BYTES (4 * STAGE_SZ)      // 61440 B -> 3 CTAs/SM

// ---- weight fp16 offsets (elements) -----------------------------------------
#define OW_IH_LI 0
#define OW_HH_LI 98304
#define OW_IH_C  294912
#define OW_HH_C  393216
#define OW_IH_LH 589824
#define OW_HH_LH 884736
#define W_TOTAL  1081344

// ---------------- static device scratch (~700MB, linker-safe) ----------------
__device__ __align__(16) float g_acc_news_all[(size_t)NNE * C_IN];
__device__ __align__(16) float g_accmc_all[(size_t)NSTE * C_IN];
__device__ __align__(16) __half g_x16[(size_t)NSTE * C_IN];
__device__ __align__(16) __half g_cen16[(size_t)NNE * C_IN];
__device__ __align__(16) __half g_mce16[(size_t)NSTE * C_IN];
__device__ float g_inv_news_all[NNE];
__device__ float g_inv_stock_all[NSTE];
// CSR (stock-destination sorted edges, per t)
__device__ int g_deg[NSTE];
__device__ int g_csr_off[NSTE];
__device__ int g_cur[NSTE];
__device__ int g_csr_n[SEQ_L * NEDGE];
__device__ int g_tot[SEQ_L];
// per-step state (all L2-resident working set, ~70MB)
__device__ __align__(16) float g_mc[NNEWS * HID];
__device__ __align__(16) __half g_mc16[NNEWS * HID];
__device__ __align__(16) __half g_h16[NSTOCK * HID];
__device__ __align__(16) __half g_p16[NSTOCK * HID];
__device__ __align__(16) __half g_m16[NSTOCK * CM];      // [mcenter | amc] fp16
__device__ __align__(16) __half g_gi_s[NSTOCK * G3];
__device__ __align__(16) __half g_gi_n[NNEWS * G3];
__device__ __align__(16) __half g_gh_li[NSTOCK * G3];
__device__ __align__(16) __half g_gh_lh[NSTOCK * G3];
__device__ __align__(16) __half g_gh_n[NNEWS * G3];
__device__ __align__(16) __half g_gis[NSTOCK * G3];
__device__ __align__(16) __half g_Whi[W_TOTAL];
__device__ unsigned g_bar_count = 0;

// ---------------- software grid barrier (monotonic) --------------------------
__device__ __forceinline__ void grid_sync() {
    __syncthreads();
    __threadfence();
    if (threadIdx.x == 0) {
        unsigned G = gridDim.x;
        unsigned arrival = atomicAdd(&g_bar_count, 1u) + 1u;
        unsigned target = ((arrival + G - 1u) / G) * G;
        volatile unsigned* vc = &g_bar_count;
        while (*vc < target) { __nanosleep(32); }
    }
    __syncthreads();
    __threadfence();
}

__device__ __forceinline__ void mma_f16(float* c, const uint32_t* a, const uint32_t* b) {
    asm volatile("mma.sync.aligned.m16n8k16.row.col.f32.f16.f16.f32 "
                 "{%0,%1,%2,%3}, {%4,%5,%6,%7}, {%8,%9}, {%0,%1,%2,%3};"
                 : "+f"(c[0]), "+f"(c[1]), "+f"(c[2]), "+f"(c[3])
                 : "r"(a[0]), "r"(a[1]), "r"(a[2]), "r"(a[3]), "r"(b[0]), "r"(b[1]));
}

__device__ __forceinline__ void ldsm_x4(uint32_t addr, uint32_t* r) {
    asm volatile("ldmatrix.sync.aligned.m8n8.x4.shared.b16 {%0,%1,%2,%3}, [%4];"
                 : "=r"(r[0]), "=r"(r[1]), "=r"(r[2]), "=r"(r[3]) : "r"(addr));
}
__device__ __forceinline__ void ldsm_x2(uint32_t addr, uint32_t* r) {
    asm volatile("ldmatrix.sync.aligned.m8n8.x2.shared.b16 {%0,%1}, [%2];"
                 : "=r"(r[0]), "=r"(r[1]) : "r"(addr));
}

struct Acc { float v[2][4][4]; };

// ---------------- fp16 fragment compute over one staged chunk ----------------
template <int BK, int KP>
__device__ __forceinline__ void mma_chunk_l(uint32_t sA, uint32_t sB,
                                            uint32_t aoff, uint32_t boff, Acc& A) {
#pragma unroll
    for (int kk = 0; kk < BK; kk += 16) {
        uint32_t bh[4][2], af[2][4];
#pragma unroll
        for (int nf = 0; nf < 4; nf++)
            ldsm_x2(sB + boff + (nf * 8 * KP + kk) * 2, bh[nf]);
#pragma unroll
        for (int mf = 0; mf < 2; mf++)
            ldsm_x4(sA + aoff + (mf * 16 * KP + kk) * 2, af[mf]);
#pragma unroll
        for (int nf = 0; nf < 4; nf++)
#pragma unroll
            for (int mf = 0; mf < 2; mf++)
                mma_f16(A.v[mf][nf], af[mf], bh[nf]);
    }
}

template <int KP>
__device__ __forceinline__ uint32_t mk_aoff(int mbase, int lane) {
    int arow = (lane & 7) + ((lane >> 3) & 1) * 8;
    int acol = (lane >> 4) * 8;
    return (uint32_t)(((mbase + arow) * KP + acol) * 2);
}
template <int KP>
__device__ __forceinline__ uint32_t mk_boff(int nbase, int lane) {
    int brow = lane & 7;
    int bcol = ((lane >> 3) & 1) * 8;
    return (uint32_t)(((nbase + brow) * KP + bcol) * 2);
}

// ---------------- universal GEMM: cp.async 4-stage, fp16 in/out --------------
__device__ void gemm_step(const __half* __restrict__ A, int lda,
                          const __half* __restrict__ Wh, int ldw,
                          const float* __restrict__ bias,
                          __half* __restrict__ Cc, int K, int M, int m0, int n0,
                          char* dsm) {
    const int tid = threadIdx.x;
    const int w = tid >> 5, lane = tid & 31;
    const int g = lane >> 2, t4 = lane & 3;
    const int mbase = (w >> 1) * 32, nbase = (w & 1) * 32;
    const uint32_t sb0 = (uint32_t)__cvta_generic_to_shared(dsm);
    const uint32_t aoff = mk_aoff<BKP32>(mbase, lane);
    const uint32_t boff = mk_boff<BKP32>(nbase, lane);
    Acc acc;
#pragma unroll
    for (int i = 0; i < 2; i++)
#pragma unroll
        for (int j = 0; j < 4; j++)
#pragma unroll
            for (int q = 0; q < 4; q++) acc.v[i][j][q] = 0.0f;

    const int NC = K >> 5;
    auto stage = [&](int c) {
        uint32_t sb = sb0 + (c & 3) * STAGE_SZ;
        int kt = c << 5;
        for (int it = tid; it < 768; it += NT) {
            if (it < 512) {
                int row = it >> 2;
                int c8 = (it & 3) << 3;
                int mm = m0 + row; if (mm >= M) mm = M - 1;
                const void* ga = A + (size_t)mm * lda + kt + c8;
                uint32_t so = sb + (row * BKP32 + c8) * 2;
                asm volatile("cp.async.ca.shared.global [%0], [%1], 16;" :: "r"(so), "l"(ga));
            } else {
                int j = it - 512;
                int row = j >> 2;
                int c8 = (j & 3) << 3;
                const void* gb = Wh + (size_t)(n0 + row) * ldw + kt + c8;
                uint32_t so = sb + SA_SZ + (row * BKP32 + c8) * 2;
                asm volatile("cp.async.ca.shared.global [%0], [%1], 16;" :: "r"(so), "l"(gb));
            }
        }
        asm volatile("cp.async.commit_group;");
    };

    stage(0);
    if (NC > 1) stage(1);
    if (NC > 2) stage(2);
    for (int c = 0; c < NC; c++) {
        if (c + 3 < NC) {
            stage(c + 3);
            asm volatile("cp.async.wait_group 3;");
        } else if (c + 2 < NC) {
            asm volatile("cp.async.wait_group 2;");
        } else if (c + 1 < NC) {
            asm volatile("cp.async.wait_group 1;");
        } else {
            asm volatile("cp.async.wait_group 0;");
        }
        __syncthreads();
        uint32_t st = sb0 + (c & 3) * STAGE_SZ;
        mma_chunk_l<32, BKP32>(st, st + SA_SZ, aoff, boff, acc);
        __syncthreads();
    }
#pragma unroll
    for (int mf = 0; mf < 2; mf++) {
#pragma unroll
        for (int nf = 0; nf < 4; nf++) {
            int m = m0 + mbase + mf * 16 + g;
            int n = n0 + nbase + nf * 8 + 2 * t4;
            float b0 = bias[n], b1 = bias[n + 1];
            if (m < M)
                *(__half2*)(Cc + (size_t)m * G3 + n) =
                    __floats2half2_rn(acc.v[mf][nf][0] + b0, acc.v[mf][nf][1] + b1);
            if (m + 8 < M)
                *(__half2*)(Cc + (size_t)(m + 8) * G3 + n) =
                    __floats2half2_rn(acc.v[mf][nf][2] + b0, acc.v[mf][nf][3] + b1);
        }
    }
    __syncthreads();
}

// ---------------- GRU gate, half2-vectorized ---------------------------------
__device__ __forceinline__ void gate_hh(const __half* __restrict__ gi,
                                        const __half* __restrict__ gh,
                                        float* __restrict__ hf,
                                        __half* __restrict__ h16,
                                        int M, int gtid, int nthr) {
    int total = (M * HID) >> 1;
    for (int p = gtid; p < total; p += nthr) {
        int idx = p << 1;
        int m = idx >> 8;
        int j = idx & 255;
        const __half* gim = gi + (size_t)m * G3 + j;
        const __half* ghm = gh + (size_t)m * G3 + j;
        float2 gr = __half22float2(*(const __half2*)(gim));
        float2 gz = __half22float2(*(const __half2*)(gim + HID));
        float2 gn = __half22float2(*(const __half2*)(gim + 2 * HID));
        float2 hr = __half22float2(*(const __half2*)(ghm));
        float2 hz = __half22float2(*(const __half2*)(ghm + HID));
        float2 hn = __half22float2(*(const __half2*)(ghm + 2 * HID));
        float r0 = 1.0f / (1.0f + __expf(-(gr.x + hr.x)));
        float r1 = 1.0f / (1.0f + __expf(-(gr.y + hr.y)));
        float z0 = 1.0f / (1.0f + __expf(-(gz.x + hz.x)));
        float z1 = 1.0f / (1.0f + __expf(-(gz.y + hz.y)));
        float n0 = tanhf(gn.x + r0 * hn.x);
        float n1 = tanhf(gn.y + r1 * hn.y);
        float2 hv = *(const float2*)(hf + idx);
        float v0 = (1.0f - z0) * n0 + z0 * hv.x;
        float v1 = (1.0f - z1) * n1 + z1 * hv.y;
        *(float2*)(hf + idx) = make_float2(v0, v1);
        *(__half2*)(h16 + idx) = __floats2half2_rn(v0, v1);
    }
}

__device__ __forceinline__ void convW(const float* __restrict__ W, int off, int n,
                                      int gtid, int nthr) {
    for (int i = gtid; i < n; i += nthr)
        g_Whi[off + i] = __float2half_rn(W[i]);
}

// tile counts (BM=128, BN=64): stocks 63x12=756, news 13x12=156
#define ST_T 756
#define NW_T 156
#define PA_TOT (2 * ST_T + 2 * NW_T)   // 1824 = exactly 4.0 waves at grid 456
#define PE_TOT (ST_T * 2)              // 1512

// ---------------- the persistent mega-kernel ---------------------------------
__global__ __launch_bounds__(NT, 3)
void mega_kernel(const float* __restrict__ inputs, const int* __restrict__ ei,
                 const float* __restrict__ h_start, const float* __restrict__ hi_start,
                 const float* __restrict__ mc_start,
                 const float* __restrict__ Wih_c,  const float* __restrict__ Whh_c,
                 const float* __restrict__ bih_c,  const float* __restrict__ bhh_c,
                 const float* __restrict__ Wih_lh, const float* __restrict__ Whh_lh,
                 const float* __restrict__ bih_lh, const float* __restrict__ bhh_lh,
                 const float* __restrict__ Wih_li, const float* __restrict__ Whh_li,
                 const float* __restrict__ bih_li, const float* __restrict__ bhh_li,
                 float* __restrict__ m_out, float* __restrict__ h_out,
                 float* __restrict__ hi_out) {
    extern __shared__ char dsm[];

    const int gtid = blockIdx.x * NT + threadIdx.x;
    const int nthr = gridDim.x * NT;
    const int gwarp = gtid >> 5;
    const int lane = threadIdx.x & 31;
    const int nwarp = nthr >> 5;

    // ==== I0: init states, weights, x conversion, zero counters ====
    for (int i = gtid; i < NSTOCK * HID; i += nthr) {
        float hv = h_start[i & 255], pv = hi_start[i & 255];
        h_out[i] = hv; hi_out[i] = pv;
        g_h16[i] = __float2half_rn(hv);
        g_p16[i] = __float2half_rn(pv);
    }
    for (int i = gtid; i < NNEWS * HID; i += nthr) {
        float v = mc_start[i & 255];
        g_mc[i] = v;
        g_mc16[i] = __float2half_rn(v);
    }
    convW(Wih_li, OW_IH_LI, G3 * C_IN, gtid, nthr);
    convW(Whh_li, OW_HH_LI, G3 * HID,  gtid, nthr);
    convW(Wih_c,  OW_IH_C,  G3 * C_IN, gtid, nthr);
    convW(Whh_c,  OW_HH_C,  G3 * HID,  gtid, nthr);
    convW(Wih_lh, OW_IH_LH, G3 * CM,   gtid, nthr);
    convW(Whh_lh, OW_HH_LH, G3 * HID,  gtid, nthr);
    for (size_t i = gtid; i < (size_t)NSTE * C_IN; i += nthr)
        g_x16[i] = __float2half_rn(inputs[i]);
    for (int i = gtid; i < NNE; i += nthr) g_inv_news_all[i] = 0.0f;
    for (int i = gtid; i < NSTE; i += nthr) { g_deg[i] = 0; }
    for (int i = gtid; i < SEQ_L; i += nthr) g_tot[i] = 0;
    for (size_t i = gtid; i < (size_t)NNE * C_IN; i += nthr) g_acc_news_all[i] = 0.0f;
    for (size_t i = gtid; i < (size_t)NSTE * C_IN; i += nthr) g_accmc_all[i] = 0.0f;
    grid_sync();
    // ==== I0b: degree counts ====
    for (int task = gtid; task < SEQ_L * NEDGE; task += nthr) {
        int t = task / NEDGE, e = task - t * NEDGE;
        const int* news = ei + (size_t)t * 2 * NEDGE;
        atomicAdd(&g_inv_news_all[t * NNEWS + news[e]], 1.0f);
        atomicAdd(&g_deg[t * NSTOCK + news[NEDGE + e]], 1);
    }
    grid_sync();
    // ==== I1: invert counts; CSR offsets; bulk scatter x -> news ====
    for (int i = gtid; i < NNE; i += nthr)
        g_inv_news_all[i] = 1.0f / fmaxf(g_inv_news_all[i], 1.0f);
    for (int i = gtid; i < NSTE; i += nthr) {
        int d = g_deg[i];
        g_inv_stock_all[i] = 1.0f / fmaxf((float)d, 1.0f);
        int off = atomicAdd(&g_tot[i / NSTOCK], d);
        g_csr_off[i] = off;
        g_cur[i] = off;
    }
    for (int task = gwarp; task < SEQ_L * NEDGE; task += nwarp) {
        int t = task / NEDGE, e = task - t * NEDGE;
        const int* news = ei + (size_t)t * 2 * NEDGE;
        int n = news[e], s = news[NEDGE + e];
        float4 v = ((const float4*)(inputs + ((size_t)t * NSTOCK + s) * C_IN))[lane];
        float* dst = g_acc_news_all + ((size_t)t * NNEWS + n) * C_IN + lane * 4;
        atomicAdd(dst + 0, v.x); atomicAdd(dst + 1, v.y);
        atomicAdd(dst + 2, v.z); atomicAdd(dst + 3, v.w);
    }
    grid_sync();
    // ==== I2: fill CSR; normalize center in place + fp16 copy ====
    for (int task = gtid; task < SEQ_L * NEDGE; task += nthr) {
        int t = task / NEDGE, e = task - t * NEDGE;
        const int* news = ei + (size_t)t * 2 * NEDGE;
        int n = news[e], s = news[NEDGE + e];
        int slot = atomicAdd(&g_cur[t * NSTOCK + s], 1);
        g_csr_n[(size_t)t * NEDGE + slot] = n;
    }
    for (size_t i = gtid; i < (size_t)NNE * C_IN; i += nthr) {
        float v = g_acc_news_all[i] * g_inv_news_all[i >> 7];
        g_acc_news_all[i] = v;
        g_cen16[i] = __float2half_rn(v);
    }
    grid_sync();
    // ==== I4: bulk scatter center -> stocks ====
    for (int task = gwarp; task < SEQ_L * NEDGE; task += nwarp) {
        int t = task / NEDGE, e = task - t * NEDGE;
        const int* news = ei + (size_t)t * 2 * NEDGE;
        int n = news[e], s = news[NEDGE + e];
        float4 v = ((const float4*)(g_acc_news_all + ((size_t)t * NNEWS + n) * C_IN))[lane];
        float* dst = g_accmc_all + ((size_t)t * NSTOCK + s) * C_IN + lane * 4;
        atomicAdd(dst + 0, v.x); atomicAdd(dst + 1, v.y);
        atomicAdd(dst + 2, v.z); atomicAdd(dst + 3, v.w);
    }
    grid_sync();
    // ==== I5: normalize mcenter -> fp16; m_out center cols (t=63) ====
    for (size_t i = gtid; i < (size_t)NSTE * C_IN; i += nthr) {
        float v = g_accmc_all[i] * g_inv_stock_all[i >> 7];
        g_mce16[i] = __float2half_rn(v);
        if (i >= (size_t)63 * NSTOCK * C_IN) {
            size_t r = i - (size_t)63 * NSTOCK * C_IN;
            m_out[(r >> 7) * CM + (r & 127)] = v;
        }
    }
    grid_sync();

    // ==== sequential recurrence: all GEMMs in-loop, L2-resident buffers ====
    for (int t = 0; t < SEQ_L; t++) {
        const __half* xt16 = g_x16 + (size_t)t * NSTOCK * C_IN;
        const __half* cent16 = g_cen16 + (size_t)t * NNEWS * C_IN;

        // ---- A: F_prev gate + gh_li, gh_n (K256), gi_li, gi_c (K128) ----
        if (t > 0)
            gate_hh(g_gis, g_gh_lh, h_out, g_h16, NSTOCK, gtid, nthr);
        for (int tile = blockIdx.x; tile < PA_TOT; tile += gridDim.x) {
            if (tile < ST_T) {
                int mt = tile / 12, nt = tile % 12;
                gemm_step(g_p16, HID, g_Whi + OW_HH_LI, HID,
                          bhh_li, g_gh_li, HID, NSTOCK, mt * 128, nt * 64, dsm);
            } else if (tile < ST_T + NW_T) {
                int idx = tile - ST_T, mt = idx / 12, nt = idx % 12;
                gemm_step(g_mc16, HID, g_Whi + OW_HH_C, HID,
                          bhh_c, g_gh_n, HID, NNEWS, mt * 128, nt * 64, dsm);
            } else if (tile < 2 * ST_T + NW_T) {
                int idx = tile - ST_T - NW_T, mt = idx / 12, nt = idx % 12;
                gemm_step(xt16, C_IN, g_Whi + OW_IH_LI, C_IN,
                          bih_li, g_gi_s, C_IN, NSTOCK, mt * 128, nt * 64, dsm);
            } else {
                int idx = tile - 2 * ST_T - NW_T, mt = idx / 12, nt = idx % 12;
                gemm_step(cent16, C_IN, g_Whi + OW_IH_C, C_IN,
                          bih_c, g_gi_n, C_IN, NNEWS, mt * 128, nt * 64, dsm);
            }
        }
        grid_sync();

        // ---- B: gates m_c + h_input ----
        gate_hh(g_gi_n, g_gh_n, g_mc, g_mc16, NNEWS, gtid, nthr);
        gate_hh(g_gi_s, g_gh_li, hi_out, g_p16, NSTOCK, gtid, nthr);
        grid_sync();

        // ---- C': CSR gather m_c -> amc; assemble m16 = [mce | amc] ----
        for (int s = gwarp; s < NSTOCK; s += nwarp) {
            int base = t * NSTOCK + s;
            int off = g_csr_off[base], deg = g_deg[base];
            const int* en = g_csr_n + (size_t)t * NEDGE;
            float4 a0 = make_float4(0.f, 0.f, 0.f, 0.f);
            float4 a1 = make_float4(0.f, 0.f, 0.f, 0.f);
            for (int e = off; e < off + deg; e++) {
                int n = en[e];
                const float4* mp = (const float4*)(g_mc + (size_t)n * HID);
                float4 v0 = mp[lane], v1 = mp[lane + 32];
                a0.x += v0.x; a0.y += v0.y; a0.z += v0.z; a0.w += v0.w;
                a1.x += v1.x; a1.y += v1.y; a1.z += v1.z; a1.w += v1.w;
            }
            float inv = g_inv_stock_all[base];
            float vs[8] = {a0.x * inv, a0.y * inv, a0.z * inv, a0.w * inv,
                           a1.x * inv, a1.y * inv, a1.z * inv, a1.w * inv};
            // center slice copy (fp16, 8 bytes per lane)
            *(uint2*)(g_m16 + (size_t)s * CM + lane * 4) =
                *(const uint2*)(g_mce16 + (size_t)base * C_IN + lane * 4);
            __half* mp16 = g_m16 + (size_t)s * CM + C_IN + lane * 4;
#pragma unroll
            for (int q = 0; q < 4; q++) {
                mp16[q] = __float2half_rn(vs[q]);
                mp16[128 + q] = __float2half_rn(vs[4 + q]);
            }
            if (t == SEQ_L - 1) {
                float* mo = m_out + (size_t)s * CM + C_IN + lane * 4;
#pragma unroll
                for (int q = 0; q < 4; q++) { mo[q] = vs[q]; mo[128 + q] = vs[4 + q]; }
            }
        }
        grid_sync();

        // ---- E: gis = m16 @ Wih_lh^T + bias (K=384); gh_lh (K=256) ----
        for (int tile = blockIdx.x; tile < PE_TOT; tile += gridDim.x) {
            if (tile < ST_T) {
                int mt = tile / 12, nt = tile % 12;
                gemm_step(g_m16, CM, g_Whi + OW_IH_LH, CM,
                          bih_lh, g_gis, CM, NSTOCK, mt * 128, nt * 64, dsm);
            } else {
                int idx = tile - ST_T, mt = idx / 12, nt = idx % 12;
                gemm_step(g_h16, HID, g_Whi + OW_HH_LH, HID,
                          bhh_lh, g_gh_lh, HID, NSTOCK, mt * 128, nt * 64, dsm);
            }
        }
        grid_sync();
    }
    // ---- final F gate (t = SEQ_L-1) ----
    gate_hh(g_gis, g_gh_lh, h_out, g_h16, NSTOCK, gtid, nthr);
}

// ---------------- launch -----------------------------------------------------
extern "C" void kernel_launch(void* const* d_in, const int* in_sizes, int n_in,
                              void* d_out, int out_size) {
    const float* inputs   = (const float*)d_in[0];
    const int*   ei       = (const int*)d_in[1];
    const float* h_start  = (const float*)d_in[2];
    const float* hi_start = (const float*)d_in[3];
    const float* mc_start = (const float*)d_in[4];
    const float* Wih_c  = (const float*)d_in[5];
    const float* Whh_c  = (const float*)d_in[6];
    const float* bih_c  = (const float*)d_in[7];
    const float* bhh_c  = (const float*)d_in[8];
    const float* Wih_lh = (const float*)d_in[9];
    const float* Whh_lh = (const float*)d_in[10];
    const float* bih_lh = (const float*)d_in[11];
    const float* bhh_lh = (const float*)d_in[12];
    const float* Wih_li = (const float*)d_in[13];
    const float* Whh_li = (const float*)d_in[14];
    const float* bih_li = (const float*)d_in[15];
    const float* bhh_li = (const float*)d_in[16];

    float* out    = (float*)d_out;
    float* m_out  = out;
    float* h_out  = out + (size_t)NSTOCK * CM;
    float* hi_out = h_out + (size_t)NSTOCK * HID;

    cudaFuncSetAttribute(mega_kernel, cudaFuncAttributeMaxDynamicSharedMemorySize, SMEM_BYTES);

    int dev = 0, nsm = 0, occ = 0;
    cudaGetDevice(&dev);
    cudaDeviceGetAttribute(&nsm, cudaDevAttrMultiProcessorCount, dev);
    cudaOccupancyMaxActiveBlocksPerMultiprocessor(&occ, mega_kernel, NT, SMEM_BYTES);
    if (occ < 1) occ = 1;
    int nblk = nsm * occ;

    unsigned* bar = nullptr;
    cudaGetSymbolAddress((void**)&bar, g_bar_count);
    cudaMemsetAsync(bar, 0, sizeof(unsigned));

    mega_kernel<<<nblk, NT, SMEM_BYTES>>>(inputs, ei, h_start, hi_start, mc_start,
                                          Wih_c, Whh_c, bih_c, bhh_c,
                                          Wih_lh, Whh_lh, bih_lh, bhh_lh,
                                          Wih_li, Whh_li, bih_li, bhh_li,
                                          m_out, h_out, hi_out);
}